// round 1
// baseline (speedup 1.0000x reference)
#include <cuda_runtime.h>
#include <cmath>

#define BATCH 16
#define NPTS  1024
#define KNN   20
#define EPSBN 1e-5f
#define SLOPE 0.2f

// ---------------- scratch (device globals; no allocations allowed) ----------------
__device__ float g_xT[BATCH * NPTS * 3];
__device__ float g_hcat[BATCH * NPTS * 512];          // x1|x2|x3|x4 concatenated
__device__ float g_pd[(long long)BATCH * NPTS * NPTS]; // pairwise "distance" (neg sq dist)
__device__ int   g_idx[BATCH * NPTS * KNN];
__device__ float g_YZ[BATCH * NPTS * 512];            // [Y | Z] per edge block (width 2*O)
__device__ float g_h5[(long long)BATCH * NPTS * 1024];
__device__ float g_W[512 * 128];                      // prepared [wa; wb-wa] weights
__device__ float g_sq[BATCH * NPTS];
__device__ float g_pool[BATCH * 2048];
__device__ float g_fc1[BATCH * 512];
__device__ float g_fc2[BATCH * 256];

// ---------------- transpose x (B,3,N) -> (B,N,3) ----------------
__global__ void transpose_x_kernel(const float* __restrict__ x, float* __restrict__ xT)
{
    int i = blockIdx.x * blockDim.x + threadIdx.x;
    if (i >= BATCH * 3 * NPTS) return;
    int b = i / (3 * NPTS);
    int r = i % (3 * NPTS);
    int c = r / NPTS;
    int n = r % NPTS;
    xT[(b * NPTS + n) * 3 + c] = x[i];
}

// ---------------- squared norms per point ----------------
__global__ void sqnorm_kernel(const float* __restrict__ h, int lda, int C,
                              float* __restrict__ sq)
{
    int p = (blockIdx.x * blockDim.x + threadIdx.x) >> 5;
    int lane = threadIdx.x & 31;
    if (p >= BATCH * NPTS) return;
    float acc = 0.f;
    for (int c = lane; c < C; c += 32) {
        float v = h[(long long)p * lda + c];
        acc += v * v;
    }
    #pragma unroll
    for (int off = 16; off > 0; off >>= 1)
        acc += __shfl_down_sync(0xffffffffu, acc, off);
    if (lane == 0) sq[p] = acc;
}

// ---------------- generic tiled SGEMM: C = A(MxK) * B(NxK)^T ----------------
// epi: 0 = none, 1 = BN+LeakyReLU (e0 = bn params (4,N)), 2 = pd (e0 = sq, per-batch)
__global__ void sgemm_nt_kernel(const float* __restrict__ A, const float* __restrict__ Bw,
                                float* __restrict__ C,
                                int M, int Nn, int K, int lda, int ldb, int ldc,
                                long long bsA, long long bsB, long long bsC,
                                int epi, const float* __restrict__ e0)
{
    A  += (long long)blockIdx.z * bsA;
    Bw += (long long)blockIdx.z * bsB;
    C  += (long long)blockIdx.z * bsC;

    __shared__ float As[16][65];
    __shared__ float Bs[16][65];

    int tid = threadIdx.x;            // 256 threads
    int tx = tid & 15, ty = tid >> 4;
    int bx = blockIdx.x, by = blockIdx.y;

    float acc[4][4] = {};

    for (int kt = 0; kt < K; kt += 16) {
        #pragma unroll
        for (int i = 0; i < 4; ++i) {
            int idx = tid + i * 256;
            int row = idx >> 4;
            int kk  = idx & 15;
            int gk  = kt + kk;
            As[kk][row] = (gk < K) ? A[(long long)(by * 64 + row) * lda + gk] : 0.f;
            Bs[kk][row] = (gk < K) ? Bw[(long long)(bx * 64 + row) * ldb + gk] : 0.f;
        }
        __syncthreads();
        #pragma unroll
        for (int kk = 0; kk < 16; ++kk) {
            float a[4], bb[4];
            #pragma unroll
            for (int i = 0; i < 4; ++i) a[i] = As[kk][ty * 4 + i];
            #pragma unroll
            for (int j = 0; j < 4; ++j) bb[j] = Bs[kk][tx * 4 + j];
            #pragma unroll
            for (int i = 0; i < 4; ++i)
                #pragma unroll
                for (int j = 0; j < 4; ++j)
                    acc[i][j] = fmaf(a[i], bb[j], acc[i][j]);
        }
        __syncthreads();
    }

    #pragma unroll
    for (int i = 0; i < 4; ++i) {
        int gm = by * 64 + ty * 4 + i;
        #pragma unroll
        for (int j = 0; j < 4; ++j) {
            int gn = bx * 64 + tx * 4 + j;
            float v = acc[i][j];
            if (epi == 1) {
                float g  = e0[gn];
                float be = e0[Nn + gn];
                float mu = e0[2 * Nn + gn];
                float va = e0[3 * Nn + gn];
                float s = g * rsqrtf(va + EPSBN);
                v = s * v + (be - mu * s);
                v = v > 0.f ? v : SLOPE * v;
            } else if (epi == 2) {
                v = 2.f * v - e0[blockIdx.z * M + gm] - e0[blockIdx.z * M + gn];
            }
            C[(long long)gm * ldc + gn] = v;
        }
    }
}

// ---------------- iterative top-k (k=20) per row of pd ----------------
__global__ void __launch_bounds__(1024) topk_kernel(const float* __restrict__ pd,
                                                    int* __restrict__ out)
{
    int n = blockIdx.x, b = blockIdx.y;
    int tid = threadIdx.x;  // 1024
    long long rowoff = ((long long)b * NPTS + n) * NPTS;
    float v = pd[rowoff + tid];
    int lane = tid & 31, wid = tid >> 5;
    __shared__ float swv[32];
    __shared__ int   swi[32];
    __shared__ int   ssel;

    for (int it = 0; it < KNN; ++it) {
        float bv = v; int bi = tid;
        #pragma unroll
        for (int off = 16; off > 0; off >>= 1) {
            float ov = __shfl_down_sync(0xffffffffu, bv, off);
            int   oi = __shfl_down_sync(0xffffffffu, bi, off);
            if (ov > bv || (ov == bv && oi < bi)) { bv = ov; bi = oi; }
        }
        if (lane == 0) { swv[wid] = bv; swi[wid] = bi; }
        __syncthreads();
        if (wid == 0) {
            bv = swv[lane]; bi = swi[lane];
            #pragma unroll
            for (int off = 16; off > 0; off >>= 1) {
                float ov = __shfl_down_sync(0xffffffffu, bv, off);
                int   oi = __shfl_down_sync(0xffffffffu, bi, off);
                if (ov > bv || (ov == bv && oi < bi)) { bv = ov; bi = oi; }
            }
            if (lane == 0) {
                ssel = bi;
                out[((long long)b * NPTS + n) * KNN + it] = bi;
            }
        }
        __syncthreads();
        if (tid == ssel) v = -INFINITY;
    }
}

// ---------------- prepare edge weights: [wa ; wb - wa] ----------------
__global__ void prep_w_kernel(const float* __restrict__ w, float* __restrict__ Wc,
                              int O, int C)
{
    int i = blockIdx.x * blockDim.x + threadIdx.x;
    int tot = 2 * O * C;
    if (i >= tot) return;
    if (i < O * C) {
        int o = i / C, c = i % C;
        Wc[i] = w[o * 2 * C + c];
    } else {
        int j = i - O * C;
        int o = j / C, c = j % C;
        Wc[i] = w[o * 2 * C + C + c] - w[o * 2 * C + c];
    }
}

// ---------------- gather neighbors, max over k, BN + LeakyReLU ----------------
__global__ void gather_max_bn_kernel(const float* __restrict__ YZ,
                                     const int* __restrict__ idx,
                                     const float* __restrict__ bn,
                                     float* __restrict__ hcat,
                                     int O, int catoff)
{
    int n = blockIdx.x, b = blockIdx.y;
    int o = threadIdx.x;  // O threads
    __shared__ int sidx[KNN];
    if (o < KNN) sidx[o] = idx[((long long)b * NPTS + n) * KNN + o];
    __syncthreads();

    int ld = 2 * O;
    long long base = (long long)b * NPTS * ld;
    float zc = YZ[base + (long long)n * ld + O + o];
    float mx = -INFINITY, mn = INFINITY;
    #pragma unroll
    for (int k = 0; k < KNN; ++k) {
        float y = YZ[base + (long long)sidx[k] * ld + o];
        mx = fmaxf(mx, y);
        mn = fminf(mn, y);
    }
    float g  = bn[o];
    float be = bn[O + o];
    float mu = bn[2 * O + o];
    float va = bn[3 * O + o];
    float s = g * rsqrtf(va + EPSBN);
    float zsel = (s >= 0.f ? mx : mn) + zc;
    float val = s * zsel + (be - mu * s);
    val = val > 0.f ? val : SLOPE * val;
    hcat[((long long)b * NPTS + n) * 512 + catoff + o] = val;
}

// ---------------- global max + mean pool over N ----------------
__global__ void pool_kernel(const float* __restrict__ h5, float* __restrict__ pool)
{
    int b = blockIdx.y;
    int c = blockIdx.x * blockDim.x + threadIdx.x;  // 0..1023
    float mx = -INFINITY, sm = 0.f;
    long long base = (long long)b * NPTS * 1024 + c;
    for (int n = 0; n < NPTS; ++n) {
        float v = h5[base + (long long)n * 1024];
        mx = fmaxf(mx, v);
        sm += v;
    }
    pool[b * 2048 + c] = mx;
    pool[b * 2048 + 1024 + c] = sm * (1.f / (float)NPTS);
}

// ---------------- FC layer: warp per (b,o); optional BN+LReLU or bias ----------------
__global__ void fc_kernel(const float* __restrict__ in, const float* __restrict__ W,
                          const float* __restrict__ bn, const float* __restrict__ bias,
                          float* __restrict__ out, int O, int K, int Bn)
{
    int gw = (blockIdx.x * blockDim.x + threadIdx.x) >> 5;
    int lane = threadIdx.x & 31;
    if (gw >= Bn * O) return;
    int b = gw / O, o = gw % O;
    float acc = 0.f;
    const float* ip = in + (long long)b * K;
    const float* wp = W + (long long)o * K;
    for (int k = lane; k < K; k += 32) acc += ip[k] * wp[k];
    #pragma unroll
    for (int off = 16; off > 0; off >>= 1)
        acc += __shfl_down_sync(0xffffffffu, acc, off);
    if (lane == 0) {
        float v = acc;
        if (bn) {
            float g  = bn[o];
            float be = bn[O + o];
            float mu = bn[2 * O + o];
            float va = bn[3 * O + o];
            float s = g * rsqrtf(va + EPSBN);
            v = s * v + (be - mu * s);
            v = v > 0.f ? v : SLOPE * v;
        } else {
            v += bias[o];
        }
        out[(long long)b * O + o] = v;
    }
}

// ---------------- host orchestration ----------------
extern "C" void kernel_launch(void* const* d_in, const int* in_sizes, int n_in,
                              void* d_out, int out_size)
{
    (void)in_sizes; (void)n_in; (void)out_size;
    const float* x   = (const float*)d_in[0];
    const float* w1  = (const float*)d_in[1];
    const float* bn1 = (const float*)d_in[2];
    const float* w2  = (const float*)d_in[3];
    const float* bn2 = (const float*)d_in[4];
    const float* w3  = (const float*)d_in[5];
    const float* bn3 = (const float*)d_in[6];
    const float* w4  = (const float*)d_in[7];
    const float* bn4 = (const float*)d_in[8];
    const float* w5  = (const float*)d_in[9];
    const float* bn5 = (const float*)d_in[10];
    const float* wl1 = (const float*)d_in[11];
    const float* bn6 = (const float*)d_in[12];
    const float* wl2 = (const float*)d_in[13];
    const float* bn7 = (const float*)d_in[14];
    const float* wl3 = (const float*)d_in[15];
    const float* bl3 = (const float*)d_in[16];
    float* out = (float*)d_out;

    float *p_xT, *p_hcat, *p_pd, *p_YZ, *p_h5, *p_W, *p_sq, *p_pool, *p_fc1, *p_fc2;
    int* p_idx;
    cudaGetSymbolAddress((void**)&p_xT,   g_xT);
    cudaGetSymbolAddress((void**)&p_hcat, g_hcat);
    cudaGetSymbolAddress((void**)&p_pd,   g_pd);
    cudaGetSymbolAddress((void**)&p_idx,  g_idx);
    cudaGetSymbolAddress((void**)&p_YZ,   g_YZ);
    cudaGetSymbolAddress((void**)&p_h5,   g_h5);
    cudaGetSymbolAddress((void**)&p_W,    g_W);
    cudaGetSymbolAddress((void**)&p_sq,   g_sq);
    cudaGetSymbolAddress((void**)&p_pool, g_pool);
    cudaGetSymbolAddress((void**)&p_fc1,  g_fc1);
    cudaGetSymbolAddress((void**)&p_fc2,  g_fc2);

    // x -> (B,N,3)
    {
        int tot = BATCH * 3 * NPTS;
        transpose_x_kernel<<<(tot + 255) / 256, 256>>>(x, p_xT);
    }

    // edge blocks
    struct Blk { const float* h; int lda, C, O; const float* w; const float* bn; int catoff; };
    Blk blks[4] = {
        { p_xT,         3,   3,   64,  w1, bn1, 0   },
        { p_hcat + 0,   512, 64,  64,  w2, bn2, 64  },
        { p_hcat + 64,  512, 64,  128, w3, bn3, 128 },
        { p_hcat + 128, 512, 128, 256, w4, bn4, 256 },
    };

    for (int i = 0; i < 4; ++i) {
        const Blk& B = blks[i];

        // squared norms
        {
            int threads = BATCH * NPTS * 32;
            sqnorm_kernel<<<(threads + 255) / 256, 256>>>(B.h, B.lda, B.C, p_sq);
        }
        // pairwise: pd = 2*G - sq_m - sq_n (batched Gram, epilogue 2)
        {
            dim3 grid(NPTS / 64, NPTS / 64, BATCH);
            sgemm_nt_kernel<<<grid, 256>>>(B.h, B.h, p_pd,
                NPTS, NPTS, B.C, B.lda, B.lda, NPTS,
                (long long)NPTS * B.lda, (long long)NPTS * B.lda,
                (long long)NPTS * NPTS, 2, p_sq);
        }
        // top-k
        topk_kernel<<<dim3(NPTS, BATCH), 1024>>>(p_pd, p_idx);
        // prep [wa ; wb-wa]
        {
            int tot = 2 * B.O * B.C;
            prep_w_kernel<<<(tot + 255) / 256, 256>>>(B.w, p_W, B.O, B.C);
        }
        // YZ = h @ Wc^T  (M = B*N, Nn = 2*O)
        {
            dim3 grid((2 * B.O) / 64, (BATCH * NPTS) / 64, 1);
            sgemm_nt_kernel<<<grid, 256>>>(B.h, p_W, p_YZ,
                BATCH * NPTS, 2 * B.O, B.C, B.lda, B.C, 2 * B.O,
                0, 0, 0, 0, nullptr);
        }
        // gather + max_k + BN + LReLU -> hcat slice
        gather_max_bn_kernel<<<dim3(NPTS, BATCH), B.O>>>(p_YZ, p_idx, B.bn, p_hcat,
                                                         B.O, B.catoff);
    }

    // conv5: (B*N,512) @ w5^T (1024,512) with BN+LReLU epilogue
    {
        dim3 grid(1024 / 64, (BATCH * NPTS) / 64, 1);
        sgemm_nt_kernel<<<grid, 256>>>(p_hcat, w5, p_h5,
            BATCH * NPTS, 1024, 512, 512, 512, 1024,
            0, 0, 0, 1, bn5);
    }

    // pooling: max + mean over N
    pool_kernel<<<dim3(4, BATCH), 256>>>(p_h5, p_pool);

    // FC head
    {
        int warps = BATCH * 512;
        fc_kernel<<<(warps * 32 + 255) / 256, 256>>>(p_pool, wl1, bn6, nullptr,
                                                     p_fc1, 512, 2048, BATCH);
    }
    {
        int warps = BATCH * 256;
        fc_kernel<<<(warps * 32 + 255) / 256, 256>>>(p_fc1, wl2, bn7, nullptr,
                                                     p_fc2, 256, 512, BATCH);
    }
    {
        int warps = BATCH * 40;
        fc_kernel<<<(warps * 32 + 255) / 256, 256>>>(p_fc2, wl3, nullptr, bl3,
                                                     out, 40, 256, BATCH);
    }
}

// round 2
// speedup vs baseline: 2.5358x; 2.5358x over previous
#include <cuda_runtime.h>
#include <cmath>

#define BATCH 16
#define NPTS  1024
#define KNN   20
#define EPSBN 1e-5f
#define SLOPE 0.2f

// ---------------- scratch (device globals; no allocations allowed) ----------------
__device__ float g_xT[BATCH * NPTS * 3];
__device__ float g_hcat[BATCH * NPTS * 512];          // x1|x2|x3|x4 concatenated
__device__ float g_pd[(long long)BATCH * NPTS * NPTS]; // pairwise "distance" (neg sq dist)
__device__ int   g_idx[BATCH * NPTS * KNN];
__device__ float g_YZ[BATCH * NPTS * 512];            // [Y | Z] per edge block (width 2*O)
__device__ float g_h5[(long long)BATCH * NPTS * 1024];
__device__ float g_W[512 * 128];                      // prepared [wa; wb-wa] weights
__device__ float g_sq[BATCH * NPTS];
__device__ float g_pool[BATCH * 2048];
__device__ float g_fc1[BATCH * 512];
__device__ float g_fc2[BATCH * 256];

// ---------------- transpose x (B,3,N) -> (B,N,3) ----------------
__global__ void transpose_x_kernel(const float* __restrict__ x, float* __restrict__ xT)
{
    int i = blockIdx.x * blockDim.x + threadIdx.x;
    if (i >= BATCH * 3 * NPTS) return;
    int b = i / (3 * NPTS);
    int r = i % (3 * NPTS);
    int c = r / NPTS;
    int n = r % NPTS;
    xT[(b * NPTS + n) * 3 + c] = x[i];
}

// ---------------- squared norms per point ----------------
__global__ void sqnorm_kernel(const float* __restrict__ h, int lda, int C,
                              float* __restrict__ sq)
{
    int p = (blockIdx.x * blockDim.x + threadIdx.x) >> 5;
    int lane = threadIdx.x & 31;
    if (p >= BATCH * NPTS) return;
    float acc = 0.f;
    for (int c = lane; c < C; c += 32) {
        float v = h[(long long)p * lda + c];
        acc += v * v;
    }
    #pragma unroll
    for (int off = 16; off > 0; off >>= 1)
        acc += __shfl_down_sync(0xffffffffu, acc, off);
    if (lane == 0) sq[p] = acc;
}

// ---------------- generic tiled SGEMM: C = A(MxK) * B(NxK)^T ----------------
// epi: 0 = none, 1 = BN+LeakyReLU (e0 = bn params (4,N)), 2 = pd (e0 = sq, per-batch)
__global__ void sgemm_nt_kernel(const float* __restrict__ A, const float* __restrict__ Bw,
                                float* __restrict__ C,
                                int M, int Nn, int K, int lda, int ldb, int ldc,
                                long long bsA, long long bsB, long long bsC,
                                int epi, const float* __restrict__ e0)
{
    A  += (long long)blockIdx.z * bsA;
    Bw += (long long)blockIdx.z * bsB;
    C  += (long long)blockIdx.z * bsC;

    __shared__ float As[16][65];
    __shared__ float Bs[16][65];

    int tid = threadIdx.x;            // 256 threads
    int tx = tid & 15, ty = tid >> 4;
    int bx = blockIdx.x, by = blockIdx.y;

    float acc[4][4] = {};

    for (int kt = 0; kt < K; kt += 16) {
        #pragma unroll
        for (int i = 0; i < 4; ++i) {
            int idx = tid + i * 256;
            int row = idx >> 4;
            int kk  = idx & 15;
            int gk  = kt + kk;
            As[kk][row] = (gk < K) ? A[(long long)(by * 64 + row) * lda + gk] : 0.f;
            Bs[kk][row] = (gk < K) ? Bw[(long long)(bx * 64 + row) * ldb + gk] : 0.f;
        }
        __syncthreads();
        #pragma unroll
        for (int kk = 0; kk < 16; ++kk) {
            float a[4], bb[4];
            #pragma unroll
            for (int i = 0; i < 4; ++i) a[i] = As[kk][ty * 4 + i];
            #pragma unroll
            for (int j = 0; j < 4; ++j) bb[j] = Bs[kk][tx * 4 + j];
            #pragma unroll
            for (int i = 0; i < 4; ++i)
                #pragma unroll
                for (int j = 0; j < 4; ++j)
                    acc[i][j] = fmaf(a[i], bb[j], acc[i][j]);
        }
        __syncthreads();
    }

    #pragma unroll
    for (int i = 0; i < 4; ++i) {
        int gm = by * 64 + ty * 4 + i;
        #pragma unroll
        for (int j = 0; j < 4; ++j) {
            int gn = bx * 64 + tx * 4 + j;
            float v = acc[i][j];
            if (epi == 1) {
                float g  = e0[gn];
                float be = e0[Nn + gn];
                float mu = e0[2 * Nn + gn];
                float va = e0[3 * Nn + gn];
                float s = g * rsqrtf(va + EPSBN);
                v = s * v + (be - mu * s);
                v = v > 0.f ? v : SLOPE * v;
            } else if (epi == 2) {
                v = 2.f * v - e0[blockIdx.z * M + gm] - e0[blockIdx.z * M + gn];
            }
            C[(long long)gm * ldc + gn] = v;
        }
    }
}

// ---------------- warp-per-row iterative top-k (k=20) ----------------
// Each warp owns one row of 1024. Lane holds 32 values in registers at
// global column j*32+lane. 20 iterations of butterfly warp argmax; the
// winning lane invalidates its slot and rescans its 32 registers.
__global__ void __launch_bounds__(256) topk_warp_kernel(const float* __restrict__ pd,
                                                        int* __restrict__ out)
{
    int warp_in_blk = threadIdx.x >> 5;
    int lane = threadIdx.x & 31;
    int row = blockIdx.x * 8 + warp_in_blk;      // 0 .. BATCH*NPTS-1
    if (row >= BATCH * NPTS) return;

    const float* __restrict__ p = pd + (long long)row * NPTS;

    float v[32];
    #pragma unroll
    for (int j = 0; j < 32; ++j)
        v[j] = p[j * 32 + lane];                 // coalesced: lanes contiguous

    // local argmax (ascending j + strict > keeps smallest index among ties)
    float lmax = v[0];
    int   lj   = 0;
    #pragma unroll
    for (int j = 1; j < 32; ++j)
        if (v[j] > lmax) { lmax = v[j]; lj = j; }

    int* __restrict__ o = out + (long long)row * KNN;

    #pragma unroll 1
    for (int it = 0; it < KNN; ++it) {
        // warp argmax with (value desc, index asc) ordering; butterfly so all
        // lanes converge to the same winner
        float m = lmax;
        int   gi = lj * 32 + lane;
        #pragma unroll
        for (int off = 16; off > 0; off >>= 1) {
            float om = __shfl_xor_sync(0xffffffffu, m, off);
            int   oi = __shfl_xor_sync(0xffffffffu, gi, off);
            if (om > m || (om == m && oi < gi)) { m = om; gi = oi; }
        }
        if (lane == 0) o[it] = gi;

        // winner lane removes its element and rescans
        if (lane == (gi & 31)) {
            v[gi >> 5] = -INFINITY;
            float m2 = v[0];
            int   j2 = 0;
            #pragma unroll
            for (int j = 1; j < 32; ++j)
                if (v[j] > m2) { m2 = v[j]; j2 = j; }
            lmax = m2;
            lj = j2;
        }
    }
}

// ---------------- prepare edge weights: [wa ; wb - wa] ----------------
__global__ void prep_w_kernel(const float* __restrict__ w, float* __restrict__ Wc,
                              int O, int C)
{
    int i = blockIdx.x * blockDim.x + threadIdx.x;
    int tot = 2 * O * C;
    if (i >= tot) return;
    if (i < O * C) {
        int o = i / C, c = i % C;
        Wc[i] = w[o * 2 * C + c];
    } else {
        int j = i - O * C;
        int o = j / C, c = j % C;
        Wc[i] = w[o * 2 * C + C + c] - w[o * 2 * C + c];
    }
}

// ---------------- gather neighbors, max over k, BN + LeakyReLU ----------------
__global__ void gather_max_bn_kernel(const float* __restrict__ YZ,
                                     const int* __restrict__ idx,
                                     const float* __restrict__ bn,
                                     float* __restrict__ hcat,
                                     int O, int catoff)
{
    int n = blockIdx.x, b = blockIdx.y;
    int o = threadIdx.x;  // O threads
    __shared__ int sidx[KNN];
    if (o < KNN) sidx[o] = idx[((long long)b * NPTS + n) * KNN + o];
    __syncthreads();

    int ld = 2 * O;
    long long base = (long long)b * NPTS * ld;
    float zc = YZ[base + (long long)n * ld + O + o];
    float mx = -INFINITY, mn = INFINITY;
    #pragma unroll
    for (int k = 0; k < KNN; ++k) {
        float y = YZ[base + (long long)sidx[k] * ld + o];
        mx = fmaxf(mx, y);
        mn = fminf(mn, y);
    }
    float g  = bn[o];
    float be = bn[O + o];
    float mu = bn[2 * O + o];
    float va = bn[3 * O + o];
    float s = g * rsqrtf(va + EPSBN);
    float zsel = (s >= 0.f ? mx : mn) + zc;
    float val = s * zsel + (be - mu * s);
    val = val > 0.f ? val : SLOPE * val;
    hcat[((long long)b * NPTS + n) * 512 + catoff + o] = val;
}

// ---------------- global max + mean pool over N ----------------
__global__ void pool_kernel(const float* __restrict__ h5, float* __restrict__ pool)
{
    int b = blockIdx.y;
    int c = blockIdx.x * blockDim.x + threadIdx.x;  // 0..1023
    float mx = -INFINITY, sm = 0.f;
    long long base = (long long)b * NPTS * 1024 + c;
    for (int n = 0; n < NPTS; ++n) {
        float v = h5[base + (long long)n * 1024];
        mx = fmaxf(mx, v);
        sm += v;
    }
    pool[b * 2048 + c] = mx;
    pool[b * 2048 + 1024 + c] = sm * (1.f / (float)NPTS);
}

// ---------------- FC layer: warp per (b,o); optional BN+LReLU or bias ----------------
__global__ void fc_kernel(const float* __restrict__ in, const float* __restrict__ W,
                          const float* __restrict__ bn, const float* __restrict__ bias,
                          float* __restrict__ out, int O, int K, int Bn)
{
    int gw = (blockIdx.x * blockDim.x + threadIdx.x) >> 5;
    int lane = threadIdx.x & 31;
    if (gw >= Bn * O) return;
    int b = gw / O, o = gw % O;
    float acc = 0.f;
    const float* ip = in + (long long)b * K;
    const float* wp = W + (long long)o * K;
    for (int k = lane; k < K; k += 32) acc += ip[k] * wp[k];
    #pragma unroll
    for (int off = 16; off > 0; off >>= 1)
        acc += __shfl_down_sync(0xffffffffu, acc, off);
    if (lane == 0) {
        float v = acc;
        if (bn) {
            float g  = bn[o];
            float be = bn[O + o];
            float mu = bn[2 * O + o];
            float va = bn[3 * O + o];
            float s = g * rsqrtf(va + EPSBN);
            v = s * v + (be - mu * s);
            v = v > 0.f ? v : SLOPE * v;
        } else {
            v += bias[o];
        }
        out[(long long)b * O + o] = v;
    }
}

// ---------------- host orchestration ----------------
extern "C" void kernel_launch(void* const* d_in, const int* in_sizes, int n_in,
                              void* d_out, int out_size)
{
    (void)in_sizes; (void)n_in; (void)out_size;
    const float* x   = (const float*)d_in[0];
    const float* w1  = (const float*)d_in[1];
    const float* bn1 = (const float*)d_in[2];
    const float* w2  = (const float*)d_in[3];
    const float* bn2 = (const float*)d_in[4];
    const float* w3  = (const float*)d_in[5];
    const float* bn3 = (const float*)d_in[6];
    const float* w4  = (const float*)d_in[7];
    const float* bn4 = (const float*)d_in[8];
    const float* w5  = (const float*)d_in[9];
    const float* bn5 = (const float*)d_in[10];
    const float* wl1 = (const float*)d_in[11];
    const float* bn6 = (const float*)d_in[12];
    const float* wl2 = (const float*)d_in[13];
    const float* bn7 = (const float*)d_in[14];
    const float* wl3 = (const float*)d_in[15];
    const float* bl3 = (const float*)d_in[16];
    float* out = (float*)d_out;

    float *p_xT, *p_hcat, *p_pd, *p_YZ, *p_h5, *p_W, *p_sq, *p_pool, *p_fc1, *p_fc2;
    int* p_idx;
    cudaGetSymbolAddress((void**)&p_xT,   g_xT);
    cudaGetSymbolAddress((void**)&p_hcat, g_hcat);
    cudaGetSymbolAddress((void**)&p_pd,   g_pd);
    cudaGetSymbolAddress((void**)&p_idx,  g_idx);
    cudaGetSymbolAddress((void**)&p_YZ,   g_YZ);
    cudaGetSymbolAddress((void**)&p_h5,   g_h5);
    cudaGetSymbolAddress((void**)&p_W,    g_W);
    cudaGetSymbolAddress((void**)&p_sq,   g_sq);
    cudaGetSymbolAddress((void**)&p_pool, g_pool);
    cudaGetSymbolAddress((void**)&p_fc1,  g_fc1);
    cudaGetSymbolAddress((void**)&p_fc2,  g_fc2);

    // x -> (B,N,3)
    {
        int tot = BATCH * 3 * NPTS;
        transpose_x_kernel<<<(tot + 255) / 256, 256>>>(x, p_xT);
    }

    // edge blocks
    struct Blk { const float* h; int lda, C, O; const float* w; const float* bn; int catoff; };
    Blk blks[4] = {
        { p_xT,         3,   3,   64,  w1, bn1, 0   },
        { p_hcat + 0,   512, 64,  64,  w2, bn2, 64  },
        { p_hcat + 64,  512, 64,  128, w3, bn3, 128 },
        { p_hcat + 128, 512, 128, 256, w4, bn4, 256 },
    };

    for (int i = 0; i < 4; ++i) {
        const Blk& B = blks[i];

        // squared norms
        {
            int threads = BATCH * NPTS * 32;
            sqnorm_kernel<<<(threads + 255) / 256, 256>>>(B.h, B.lda, B.C, p_sq);
        }
        // pairwise: pd = 2*G - sq_m - sq_n (batched Gram, epilogue 2)
        {
            dim3 grid(NPTS / 64, NPTS / 64, BATCH);
            sgemm_nt_kernel<<<grid, 256>>>(B.h, B.h, p_pd,
                NPTS, NPTS, B.C, B.lda, B.lda, NPTS,
                (long long)NPTS * B.lda, (long long)NPTS * B.lda,
                (long long)NPTS * NPTS, 2, p_sq);
        }
        // top-k: warp per row, 8 warps/block
        topk_warp_kernel<<<(BATCH * NPTS) / 8, 256>>>(p_pd, p_idx);
        // prep [wa ; wb-wa]
        {
            int tot = 2 * B.O * B.C;
            prep_w_kernel<<<(tot + 255) / 256, 256>>>(B.w, p_W, B.O, B.C);
        }
        // YZ = h @ Wc^T  (M = B*N, Nn = 2*O)
        {
            dim3 grid((2 * B.O) / 64, (BATCH * NPTS) / 64, 1);
            sgemm_nt_kernel<<<grid, 256>>>(B.h, p_W, p_YZ,
                BATCH * NPTS, 2 * B.O, B.C, B.lda, B.C, 2 * B.O,
                0, 0, 0, 0, nullptr);
        }
        // gather + max_k + BN + LReLU -> hcat slice
        gather_max_bn_kernel<<<dim3(NPTS, BATCH), B.O>>>(p_YZ, p_idx, B.bn, p_hcat,
                                                         B.O, B.catoff);
    }

    // conv5: (B*N,512) @ w5^T (1024,512) with BN+LReLU epilogue
    {
        dim3 grid(1024 / 64, (BATCH * NPTS) / 64, 1);
        sgemm_nt_kernel<<<grid, 256>>>(p_hcat, w5, p_h5,
            BATCH * NPTS, 1024, 512, 512, 512, 1024,
            0, 0, 0, 1, bn5);
    }

    // pooling: max + mean over N
    pool_kernel<<<dim3(4, BATCH), 256>>>(p_h5, p_pool);

    // FC head
    {
        int warps = BATCH * 512;
        fc_kernel<<<(warps * 32 + 255) / 256, 256>>>(p_pool, wl1, bn6, nullptr,
                                                     p_fc1, 512, 2048, BATCH);
    }
    {
        int warps = BATCH * 256;
        fc_kernel<<<(warps * 32 + 255) / 256, 256>>>(p_fc1, wl2, bn7, nullptr,
                                                     p_fc2, 256, 512, BATCH);
    }
    {
        int warps = BATCH * 40;
        fc_kernel<<<(warps * 32 + 255) / 256, 256>>>(p_fc2, wl3, nullptr, bl3,
                                                     out, 40, 256, BATCH);
    }
}

// round 3
// speedup vs baseline: 2.7958x; 1.1026x over previous
#include <cuda_runtime.h>
#include <cmath>

#define BATCH 16
#define NPTS  1024
#define KNN   20
#define EPSBN 1e-5f
#define SLOPE 0.2f

// ---------------- scratch (device globals; no allocations allowed) ----------------
__device__ float g_xT[BATCH * NPTS * 3];
__device__ float g_hcat[BATCH * NPTS * 512];          // x1|x2|x3|x4 concatenated
__device__ float g_pd[(long long)BATCH * NPTS * NPTS];
__device__ int   g_idx[BATCH * NPTS * KNN];
__device__ float g_YZ[BATCH * NPTS * 512];            // [Y | Z] per edge block (width 2*O)
__device__ float g_h5[(long long)BATCH * NPTS * 1024];
__device__ float g_W[512 * 128];                      // prepared [wa; wb-wa] weights
__device__ float g_sq[BATCH * NPTS];
__device__ float g_pool[BATCH * 2048];
__device__ float g_fc1[BATCH * 512];
__device__ float g_fc2[BATCH * 256];

// ---------------- transpose x (B,3,N) -> (B,N,3) ----------------
__global__ void transpose_x_kernel(const float* __restrict__ x, float* __restrict__ xT)
{
    int i = blockIdx.x * blockDim.x + threadIdx.x;
    if (i >= BATCH * 3 * NPTS) return;
    int b = i / (3 * NPTS);
    int r = i % (3 * NPTS);
    int c = r / NPTS;
    int n = r % NPTS;
    xT[(b * NPTS + n) * 3 + c] = x[i];
}

// ---------------- squared norms per point ----------------
__global__ void sqnorm_kernel(const float* __restrict__ h, int lda, int C,
                              float* __restrict__ sq)
{
    int p = (blockIdx.x * blockDim.x + threadIdx.x) >> 5;
    int lane = threadIdx.x & 31;
    if (p >= BATCH * NPTS) return;
    float acc = 0.f;
    for (int c = lane; c < C; c += 32) {
        float v = h[(long long)p * lda + c];
        acc += v * v;
    }
    #pragma unroll
    for (int off = 16; off > 0; off >>= 1)
        acc += __shfl_down_sync(0xffffffffu, acc, off);
    if (lane == 0) sq[p] = acc;
}

// ---------------- 128x128 tiled SGEMM: C = A(MxK) * B(NxK)^T ----------------
// 256 threads, 8x8 per thread, k-tile 8, transposed smem, float4 LDS + STG.
// epi: 0 = none, 1 = BN+LeakyReLU (e0 = bn (4,N)), 2 = pd (e0 = sq per-batch)
__global__ void __launch_bounds__(256)
sgemm_nt_kernel(const float* __restrict__ A, const float* __restrict__ Bw,
                float* __restrict__ C,
                int M, int Nn, int K, int lda, int ldb, int ldc,
                long long bsA, long long bsB, long long bsC,
                int epi, const float* __restrict__ e0)
{
    A  += (long long)blockIdx.z * bsA;
    Bw += (long long)blockIdx.z * bsB;
    C  += (long long)blockIdx.z * bsC;

    __shared__ float As[8][128];
    __shared__ float Bs[8][128];

    int tid = threadIdx.x;
    int tx = tid & 15;        // 0..15 : column group (8 cols)
    int ty = tid >> 4;        // 0..15 : row group (8 rows)
    int bx = blockIdx.x, by = blockIdx.y;

    // load indices: each thread loads 4 consecutive k of one half-row
    int l_row = tid >> 1;            // 0..127
    int l_k0  = (tid & 1) * 4;       // 0 or 4

    float acc[8][8] = {};

    for (int kt = 0; kt < K; kt += 8) {
        #pragma unroll
        for (int i = 0; i < 4; ++i) {
            int gk = kt + l_k0 + i;
            As[l_k0 + i][l_row] = (gk < K)
                ? A[(long long)(by * 128 + l_row) * lda + gk] : 0.f;
            Bs[l_k0 + i][l_row] = (gk < K)
                ? Bw[(long long)(bx * 128 + l_row) * ldb + gk] : 0.f;
        }
        __syncthreads();

        #pragma unroll
        for (int kk = 0; kk < 8; ++kk) {
            float4 a0 = *(const float4*)&As[kk][ty * 8];
            float4 a1 = *(const float4*)&As[kk][ty * 8 + 4];
            float4 b0 = *(const float4*)&Bs[kk][tx * 8];
            float4 b1 = *(const float4*)&Bs[kk][tx * 8 + 4];
            float a[8] = {a0.x, a0.y, a0.z, a0.w, a1.x, a1.y, a1.z, a1.w};
            float b[8] = {b0.x, b0.y, b0.z, b0.w, b1.x, b1.y, b1.z, b1.w};
            #pragma unroll
            for (int i = 0; i < 8; ++i)
                #pragma unroll
                for (int j = 0; j < 8; ++j)
                    acc[i][j] = fmaf(a[i], b[j], acc[i][j]);
        }
        __syncthreads();
    }

    // epilogue
    #pragma unroll
    for (int i = 0; i < 8; ++i) {
        int gm = by * 128 + ty * 8 + i;
        float sqm = (epi == 2) ? e0[blockIdx.z * M + gm] : 0.f;
        #pragma unroll
        for (int jj = 0; jj < 2; ++jj) {
            float4 v4;
            float* vv = (float*)&v4;
            #pragma unroll
            for (int j = 0; j < 4; ++j) {
                int gn = bx * 128 + tx * 8 + jj * 4 + j;
                float v = acc[i][jj * 4 + j];
                if (epi == 1) {
                    float g  = e0[gn];
                    float be = e0[Nn + gn];
                    float mu = e0[2 * Nn + gn];
                    float va = e0[3 * Nn + gn];
                    float s = g * rsqrtf(va + EPSBN);
                    v = s * v + (be - mu * s);
                    v = v > 0.f ? v : SLOPE * v;
                } else if (epi == 2) {
                    v = 2.f * v - sqm - e0[blockIdx.z * M + gn];
                }
                vv[j] = v;
            }
            *(float4*)&C[(long long)gm * ldc + bx * 128 + tx * 8 + jj * 4] = v4;
        }
    }
}

// ---------------- warp-per-row top-k (k=20) via REDUX.SYNC.MAX ----------------
// Values converted once to order-preserving uint keys. Each iteration:
// hardware warp max + ballot + one shuffle; winner lane invalidates + rescans.
__global__ void __launch_bounds__(256) topk_warp_kernel(const float* __restrict__ pd,
                                                        int* __restrict__ out)
{
    int warp_in_blk = threadIdx.x >> 5;
    int lane = threadIdx.x & 31;
    int row = blockIdx.x * 8 + warp_in_blk;

    const float* __restrict__ p = pd + (long long)row * NPTS;

    unsigned k[32];
    #pragma unroll
    for (int j = 0; j < 32; ++j) {
        unsigned u = __float_as_uint(p[j * 32 + lane]);
        k[j] = (u & 0x80000000u) ? ~u : (u | 0x80000000u);  // monotone key
    }

    unsigned lbest = k[0];
    int lj = 0;
    #pragma unroll
    for (int j = 1; j < 32; ++j)
        if (k[j] > lbest) { lbest = k[j]; lj = j; }

    int* __restrict__ o = out + (long long)row * KNN;

    #pragma unroll 1
    for (int it = 0; it < KNN; ++it) {
        unsigned m = __reduce_max_sync(0xffffffffu, lbest);
        unsigned bal = __ballot_sync(0xffffffffu, lbest == m);
        int src = __ffs((int)bal) - 1;
        int gi = __shfl_sync(0xffffffffu, (lj << 5) | lane, src);
        if (lane == 0) o[it] = gi;
        if (lane == src) {
            unsigned b2 = 0; int j2 = 0;
            #pragma unroll
            for (int j = 0; j < 32; ++j) {
                unsigned val = (j == lj) ? 0u : k[j];
                if (j == lj) k[j] = 0u;
                if (val > b2) { b2 = val; j2 = j; }
            }
            lbest = b2; lj = j2;
        }
    }
}

// ---------------- prepare edge weights: [wa ; wb - wa] ----------------
__global__ void prep_w_kernel(const float* __restrict__ w, float* __restrict__ Wc,
                              int O, int C)
{
    int i = blockIdx.x * blockDim.x + threadIdx.x;
    int tot = 2 * O * C;
    if (i >= tot) return;
    if (i < O * C) {
        int o = i / C, c = i % C;
        Wc[i] = w[o * 2 * C + c];
    } else {
        int j = i - O * C;
        int o = j / C, c = j % C;
        Wc[i] = w[o * 2 * C + C + c] - w[o * 2 * C + c];
    }
}

// ---------------- gather + max_k + BN + LReLU, float4-vectorized ----------------
// blockDim = (O/4, 8): 8 points per block, each thread handles 4 channels.
__global__ void gather_max_bn_kernel(const float* __restrict__ YZ,
                                     const int* __restrict__ idx,
                                     const float* __restrict__ bn,
                                     float* __restrict__ hcat,
                                     int O, int catoff)
{
    int b = blockIdx.y;
    int n0 = blockIdx.x * 8;
    int o4 = threadIdx.x;             // channel group
    int py = threadIdx.y;             // point within block
    int n = n0 + py;

    __shared__ int sidx[8][KNN];
    int bw = blockDim.x * 8;
    for (int t = threadIdx.y * blockDim.x + threadIdx.x; t < 8 * KNN; t += bw)
        sidx[t / KNN][t % KNN] = idx[((long long)b * NPTS + n0 + t / KNN) * KNN + t % KNN];
    __syncthreads();

    int ld = 2 * O;
    const float* base = YZ + (long long)b * NPTS * ld;

    float4 zc = *(const float4*)&base[(long long)n * ld + O + o4 * 4];
    float4 mx = make_float4(-INFINITY, -INFINITY, -INFINITY, -INFINITY);
    float4 mn = make_float4(INFINITY, INFINITY, INFINITY, INFINITY);
    #pragma unroll
    for (int kk = 0; kk < KNN; ++kk) {
        float4 y = *(const float4*)&base[(long long)sidx[py][kk] * ld + o4 * 4];
        mx.x = fmaxf(mx.x, y.x); mn.x = fminf(mn.x, y.x);
        mx.y = fmaxf(mx.y, y.y); mn.y = fminf(mn.y, y.y);
        mx.z = fmaxf(mx.z, y.z); mn.z = fminf(mn.z, y.z);
        mx.w = fmaxf(mx.w, y.w); mn.w = fminf(mn.w, y.w);
    }

    float4 g4  = *(const float4*)&bn[o4 * 4];
    float4 be4 = *(const float4*)&bn[O + o4 * 4];
    float4 mu4 = *(const float4*)&bn[2 * O + o4 * 4];
    float4 va4 = *(const float4*)&bn[3 * O + o4 * 4];

    float4 r;
    {
        float s = g4.x * rsqrtf(va4.x + EPSBN);
        float z = (s >= 0.f ? mx.x : mn.x) + zc.x;
        float v = s * z + (be4.x - mu4.x * s);
        r.x = v > 0.f ? v : SLOPE * v;
    }
    {
        float s = g4.y * rsqrtf(va4.y + EPSBN);
        float z = (s >= 0.f ? mx.y : mn.y) + zc.y;
        float v = s * z + (be4.y - mu4.y * s);
        r.y = v > 0.f ? v : SLOPE * v;
    }
    {
        float s = g4.z * rsqrtf(va4.z + EPSBN);
        float z = (s >= 0.f ? mx.z : mn.z) + zc.z;
        float v = s * z + (be4.z - mu4.z * s);
        r.z = v > 0.f ? v : SLOPE * v;
    }
    {
        float s = g4.w * rsqrtf(va4.w + EPSBN);
        float z = (s >= 0.f ? mx.w : mn.w) + zc.w;
        float v = s * z + (be4.w - mu4.w * s);
        r.w = v > 0.f ? v : SLOPE * v;
    }
    *(float4*)&hcat[((long long)b * NPTS + n) * 512 + catoff + o4 * 4] = r;
}

// ---------------- global max + mean pool over N ----------------
__global__ void pool_kernel(const float* __restrict__ h5, float* __restrict__ pool)
{
    int b = blockIdx.y;
    int c = blockIdx.x * blockDim.x + threadIdx.x;
    float mx = -INFINITY, sm = 0.f;
    long long base = (long long)b * NPTS * 1024 + c;
    for (int n = 0; n < NPTS; ++n) {
        float v = h5[base + (long long)n * 1024];
        mx = fmaxf(mx, v);
        sm += v;
    }
    pool[b * 2048 + c] = mx;
    pool[b * 2048 + 1024 + c] = sm * (1.f / (float)NPTS);
}

// ---------------- FC layer: warp per (b,o) ----------------
__global__ void fc_kernel(const float* __restrict__ in, const float* __restrict__ W,
                          const float* __restrict__ bn, const float* __restrict__ bias,
                          float* __restrict__ out, int O, int K, int Bn)
{
    int gw = (blockIdx.x * blockDim.x + threadIdx.x) >> 5;
    int lane = threadIdx.x & 31;
    if (gw >= Bn * O) return;
    int b = gw / O, o = gw % O;
    float acc = 0.f;
    const float* ip = in + (long long)b * K;
    const float* wp = W + (long long)o * K;
    for (int k = lane; k < K; k += 32) acc += ip[k] * wp[k];
    #pragma unroll
    for (int off = 16; off > 0; off >>= 1)
        acc += __shfl_down_sync(0xffffffffu, acc, off);
    if (lane == 0) {
        float v = acc;
        if (bn) {
            float g  = bn[o];
            float be = bn[O + o];
            float mu = bn[2 * O + o];
            float va = bn[3 * O + o];
            float s = g * rsqrtf(va + EPSBN);
            v = s * v + (be - mu * s);
            v = v > 0.f ? v : SLOPE * v;
        } else {
            v += bias[o];
        }
        out[(long long)b * O + o] = v;
    }
}

// ---------------- host orchestration ----------------
extern "C" void kernel_launch(void* const* d_in, const int* in_sizes, int n_in,
                              void* d_out, int out_size)
{
    (void)in_sizes; (void)n_in; (void)out_size;
    const float* x   = (const float*)d_in[0];
    const float* w1  = (const float*)d_in[1];
    const float* bn1 = (const float*)d_in[2];
    const float* w2  = (const float*)d_in[3];
    const float* bn2 = (const float*)d_in[4];
    const float* w3  = (const float*)d_in[5];
    const float* bn3 = (const float*)d_in[6];
    const float* w4  = (const float*)d_in[7];
    const float* bn4 = (const float*)d_in[8];
    const float* w5  = (const float*)d_in[9];
    const float* bn5 = (const float*)d_in[10];
    const float* wl1 = (const float*)d_in[11];
    const float* bn6 = (const float*)d_in[12];
    const float* wl2 = (const float*)d_in[13];
    const float* bn7 = (const float*)d_in[14];
    const float* wl3 = (const float*)d_in[15];
    const float* bl3 = (const float*)d_in[16];
    float* out = (float*)d_out;

    float *p_xT, *p_hcat, *p_pd, *p_YZ, *p_h5, *p_W, *p_sq, *p_pool, *p_fc1, *p_fc2;
    int* p_idx;
    cudaGetSymbolAddress((void**)&p_xT,   g_xT);
    cudaGetSymbolAddress((void**)&p_hcat, g_hcat);
    cudaGetSymbolAddress((void**)&p_pd,   g_pd);
    cudaGetSymbolAddress((void**)&p_idx,  g_idx);
    cudaGetSymbolAddress((void**)&p_YZ,   g_YZ);
    cudaGetSymbolAddress((void**)&p_h5,   g_h5);
    cudaGetSymbolAddress((void**)&p_W,    g_W);
    cudaGetSymbolAddress((void**)&p_sq,   g_sq);
    cudaGetSymbolAddress((void**)&p_pool, g_pool);
    cudaGetSymbolAddress((void**)&p_fc1,  g_fc1);
    cudaGetSymbolAddress((void**)&p_fc2,  g_fc2);

    // x -> (B,N,3)
    {
        int tot = BATCH * 3 * NPTS;
        transpose_x_kernel<<<(tot + 255) / 256, 256>>>(x, p_xT);
    }

    struct Blk { const float* h; int lda, C, O; const float* w; const float* bn; int catoff; };
    Blk blks[4] = {
        { p_xT,         3,   3,   64,  w1, bn1, 0   },
        { p_hcat + 0,   512, 64,  64,  w2, bn2, 64  },
        { p_hcat + 64,  512, 64,  128, w3, bn3, 128 },
        { p_hcat + 128, 512, 128, 256, w4, bn4, 256 },
    };

    for (int i = 0; i < 4; ++i) {
        const Blk& B = blks[i];

        {
            int threads = BATCH * NPTS * 32;
            sqnorm_kernel<<<(threads + 255) / 256, 256>>>(B.h, B.lda, B.C, p_sq);
        }
        // pd = 2*G - sq_m - sq_n
        {
            dim3 grid(NPTS / 128, NPTS / 128, BATCH);
            sgemm_nt_kernel<<<grid, 256>>>(B.h, B.h, p_pd,
                NPTS, NPTS, B.C, B.lda, B.lda, NPTS,
                (long long)NPTS * B.lda, (long long)NPTS * B.lda,
                (long long)NPTS * NPTS, 2, p_sq);
        }
        topk_warp_kernel<<<(BATCH * NPTS) / 8, 256>>>(p_pd, p_idx);
        {
            int tot = 2 * B.O * B.C;
            prep_w_kernel<<<(tot + 255) / 256, 256>>>(B.w, p_W, B.O, B.C);
        }
        // YZ = h @ Wc^T  (M = B*N, Nn = 2*O)
        {
            dim3 grid((2 * B.O) / 128, (BATCH * NPTS) / 128, 1);
            sgemm_nt_kernel<<<grid, 256>>>(B.h, p_W, p_YZ,
                BATCH * NPTS, 2 * B.O, B.C, B.lda, B.C, 2 * B.O,
                0, 0, 0, 0, nullptr);
        }
        {
            dim3 blk(B.O / 4, 8);
            gather_max_bn_kernel<<<dim3(NPTS / 8, BATCH), blk>>>(p_YZ, p_idx, B.bn,
                                                                 p_hcat, B.O, B.catoff);
        }
    }

    // conv5: (B*N,512) @ w5^T (1024,512) + BN+LReLU
    {
        dim3 grid(1024 / 128, (BATCH * NPTS) / 128, 1);
        sgemm_nt_kernel<<<grid, 256>>>(p_hcat, w5, p_h5,
            BATCH * NPTS, 1024, 512, 512, 512, 1024,
            0, 0, 0, 1, bn5);
    }

    pool_kernel<<<dim3(4, BATCH), 256>>>(p_h5, p_pool);

    {
        int warps = BATCH * 512;
        fc_kernel<<<(warps * 32 + 255) / 256, 256>>>(p_pool, wl1, bn6, nullptr,
                                                     p_fc1, 512, 2048, BATCH);
    }
    {
        int warps = BATCH * 256;
        fc_kernel<<<(warps * 32 + 255) / 256, 256>>>(p_fc1, wl2, bn7, nullptr,
                                                     p_fc2, 256, 512, BATCH);
    }
    {
        int warps = BATCH * 40;
        fc_kernel<<<(warps * 32 + 255) / 256, 256>>>(p_fc2, wl3, nullptr, bl3,
                                                     out, 40, 256, BATCH);
    }
}

// round 4
// speedup vs baseline: 3.2060x; 1.1467x over previous
#include <cuda_runtime.h>
#include <cmath>

#define BATCH 16
#define NPTS  1024
#define KNN   20
#define EPSBN 1e-5f
#define SLOPE 0.2f

// ---------------- scratch (device globals; no allocations allowed) ----------------
__device__ float g_xT[BATCH * NPTS * 3];
__device__ float g_hcat[BATCH * NPTS * 512];
__device__ float g_pd[(long long)BATCH * NPTS * NPTS];
__device__ int   g_idx[BATCH * NPTS * KNN];
__device__ float g_YZ[BATCH * NPTS * 512];
__device__ float g_h5[(long long)BATCH * NPTS * 1024];
__device__ float g_W[512 * 128];
__device__ float g_sq[BATCH * NPTS];
__device__ float g_pool[BATCH * 2048];
__device__ float g_fc1[BATCH * 512];
__device__ float g_fc2[BATCH * 256];

// ---------------- f32x2 packed helpers (sm_103a FFMA2 path) ----------------
__device__ __forceinline__ unsigned long long pack2(float lo, float hi)
{
    unsigned long long r;
    asm("mov.b64 %0, {%1, %2};" : "=l"(r) : "f"(lo), "f"(hi));
    return r;
}
__device__ __forceinline__ void ffma2(unsigned long long& acc,
                                      unsigned long long a, unsigned long long b)
{
    asm("fma.rn.f32x2 %0, %1, %2, %0;" : "+l"(acc) : "l"(a), "l"(b));
}
__device__ __forceinline__ float2 unpack2(unsigned long long v)
{
    float lo, hi;
    asm("mov.b64 {%0, %1}, %2;" : "=f"(lo), "=f"(hi) : "l"(v));
    return make_float2(lo, hi);
}

// ---------------- transpose x (B,3,N) -> (B,N,3) ----------------
__global__ void transpose_x_kernel(const float* __restrict__ x, float* __restrict__ xT)
{
    int i = blockIdx.x * blockDim.x + threadIdx.x;
    if (i >= BATCH * 3 * NPTS) return;
    int b = i / (3 * NPTS);
    int r = i % (3 * NPTS);
    int c = r / NPTS;
    int n = r % NPTS;
    xT[(b * NPTS + n) * 3 + c] = x[i];
}

// ---------------- squared norms per point ----------------
__global__ void sqnorm_kernel(const float* __restrict__ h, int lda, int C,
                              float* __restrict__ sq)
{
    int p = (blockIdx.x * blockDim.x + threadIdx.x) >> 5;
    int lane = threadIdx.x & 31;
    if (p >= BATCH * NPTS) return;
    float acc = 0.f;
    for (int c = lane; c < C; c += 32) {
        float v = h[(long long)p * lda + c];
        acc += v * v;
    }
    #pragma unroll
    for (int off = 16; off > 0; off >>= 1)
        acc += __shfl_down_sync(0xffffffffu, acc, off);
    if (lane == 0) sq[p] = acc;
}

// ---------------- 128x128 tiled SGEMM, f32x2 core: C = A(MxK) * B(NxK)^T ----------
// 256 threads, 8x8 per thread (packed as 8x4 f32x2), k-tile 8.
// epi: 0 = none, 1 = BN+LeakyReLU (e0 = bn (4,N)), 2 = pd (e0 = sq per-batch)
__global__ void __launch_bounds__(256)
sgemm_nt_kernel(const float* __restrict__ A, const float* __restrict__ Bw,
                float* __restrict__ C,
                int M, int Nn, int K, int lda, int ldb, int ldc,
                long long bsA, long long bsB, long long bsC,
                int epi, const float* __restrict__ e0)
{
    A  += (long long)blockIdx.z * bsA;
    Bw += (long long)blockIdx.z * bsB;
    C  += (long long)blockIdx.z * bsC;

    __shared__ float As[8][128];
    __shared__ float Bs[8][128];

    int tid = threadIdx.x;
    int tx = tid & 15;
    int ty = tid >> 4;
    int bx = blockIdx.x, by = blockIdx.y;

    int l_row = tid >> 1;
    int l_k0  = (tid & 1) * 4;

    unsigned long long acc2[8][4];
    #pragma unroll
    for (int i = 0; i < 8; ++i)
        #pragma unroll
        for (int j = 0; j < 4; ++j)
            acc2[i][j] = 0ull;

    for (int kt = 0; kt < K; kt += 8) {
        #pragma unroll
        for (int i = 0; i < 4; ++i) {
            int gk = kt + l_k0 + i;
            As[l_k0 + i][l_row] = (gk < K)
                ? A[(long long)(by * 128 + l_row) * lda + gk] : 0.f;
            Bs[l_k0 + i][l_row] = (gk < K)
                ? Bw[(long long)(bx * 128 + l_row) * ldb + gk] : 0.f;
        }
        __syncthreads();

        #pragma unroll
        for (int kk = 0; kk < 8; ++kk) {
            float4 a0 = *(const float4*)&As[kk][ty * 8];
            float4 a1 = *(const float4*)&As[kk][ty * 8 + 4];
            float4 b0 = *(const float4*)&Bs[kk][tx * 8];
            float4 b1 = *(const float4*)&Bs[kk][tx * 8 + 4];

            unsigned long long bp[4];
            bp[0] = pack2(b0.x, b0.y);
            bp[1] = pack2(b0.z, b0.w);
            bp[2] = pack2(b1.x, b1.y);
            bp[3] = pack2(b1.z, b1.w);

            float a[8] = {a0.x, a0.y, a0.z, a0.w, a1.x, a1.y, a1.z, a1.w};
            #pragma unroll
            for (int i = 0; i < 8; ++i) {
                unsigned long long ap = pack2(a[i], a[i]);
                #pragma unroll
                for (int j = 0; j < 4; ++j)
                    ffma2(acc2[i][j], ap, bp[j]);
            }
        }
        __syncthreads();
    }

    // epilogue
    #pragma unroll
    for (int i = 0; i < 8; ++i) {
        int gm = by * 128 + ty * 8 + i;
        float sqm = (epi == 2) ? e0[blockIdx.z * M + gm] : 0.f;
        #pragma unroll
        for (int jj = 0; jj < 2; ++jj) {
            float4 v4;
            float* vv = (float*)&v4;
            float2 p0 = unpack2(acc2[i][jj * 2]);
            float2 p1 = unpack2(acc2[i][jj * 2 + 1]);
            float av[4] = {p0.x, p0.y, p1.x, p1.y};
            #pragma unroll
            for (int j = 0; j < 4; ++j) {
                int gn = bx * 128 + tx * 8 + jj * 4 + j;
                float v = av[j];
                if (epi == 1) {
                    float g  = e0[gn];
                    float be = e0[Nn + gn];
                    float mu = e0[2 * Nn + gn];
                    float va = e0[3 * Nn + gn];
                    float s = g * rsqrtf(va + EPSBN);
                    v = s * v + (be - mu * s);
                    v = v > 0.f ? v : SLOPE * v;
                } else if (epi == 2) {
                    v = 2.f * v - sqm - e0[blockIdx.z * M + gn];
                }
                vv[j] = v;
            }
            *(float4*)&C[(long long)gm * ldc + bx * 128 + tx * 8 + jj * 4] = v4;
        }
    }
}

// ---------------- warp-per-row top-k (k=20), REDUX + per-lane top-2 cache -------
__global__ void __launch_bounds__(256) topk_warp_kernel(const float* __restrict__ pd,
                                                        int* __restrict__ out)
{
    int warp_in_blk = threadIdx.x >> 5;
    int lane = threadIdx.x & 31;
    int row = blockIdx.x * 8 + warp_in_blk;

    const float* __restrict__ p = pd + (long long)row * NPTS;

    unsigned k[32];
    #pragma unroll
    for (int j = 0; j < 32; ++j) {
        unsigned u = __float_as_uint(p[j * 32 + lane]);
        k[j] = (u & 0x80000000u) ? ~u : (u | 0x80000000u);  // order-preserving key
    }

    // initial per-lane top-2 (value desc, smaller index preferred)
    unsigned b1 = 0, b2 = 0;
    int j1 = 0, j2 = 0;
    #pragma unroll
    for (int j = 0; j < 32; ++j) {
        unsigned v = k[j];
        if (v > b1) { b2 = b1; j2 = j1; b1 = v; j1 = j; }
        else if (v > b2) { b2 = v; j2 = j; }
    }
    bool have2 = true;

    int* __restrict__ o = out + (long long)row * KNN;

    #pragma unroll 1
    for (int it = 0; it < KNN; ++it) {
        unsigned m = __reduce_max_sync(0xffffffffu, b1);
        unsigned bal = __ballot_sync(0xffffffffu, b1 == m);
        int src = __ffs((int)bal) - 1;
        int gi = __shfl_sync(0xffffffffu, (j1 << 5) | lane, src);
        if (lane == 0) o[it] = gi;

        if (lane == src) {
            k[j1] = 0u;
            if (have2) {
                b1 = b2; j1 = j2; have2 = false;
            } else {
                unsigned n1 = 0, n2 = 0;
                int i1 = 0, i2 = 0;
                #pragma unroll
                for (int j = 0; j < 32; ++j) {
                    unsigned v = k[j];
                    if (v > n1) { n2 = n1; i2 = i1; n1 = v; i1 = j; }
                    else if (v > n2) { n2 = v; i2 = j; }
                }
                b1 = n1; j1 = i1; b2 = n2; j2 = i2; have2 = true;
            }
        }
    }
}

// ---------------- prepare edge weights: [wa ; wb - wa] ----------------
__global__ void prep_w_kernel(const float* __restrict__ w, float* __restrict__ Wc,
                              int O, int C)
{
    int i = blockIdx.x * blockDim.x + threadIdx.x;
    int tot = 2 * O * C;
    if (i >= tot) return;
    if (i < O * C) {
        int o = i / C, c = i % C;
        Wc[i] = w[o * 2 * C + c];
    } else {
        int j = i - O * C;
        int o = j / C, c = j % C;
        Wc[i] = w[o * 2 * C + C + c] - w[o * 2 * C + c];
    }
}

// ---------------- gather + max_k + BN + LReLU, float4-vectorized ----------------
__global__ void gather_max_bn_kernel(const float* __restrict__ YZ,
                                     const int* __restrict__ idx,
                                     const float* __restrict__ bn,
                                     float* __restrict__ hcat,
                                     int O, int catoff)
{
    int b = blockIdx.y;
    int n0 = blockIdx.x * 8;
    int o4 = threadIdx.x;
    int py = threadIdx.y;
    int n = n0 + py;

    __shared__ int sidx[8][KNN];
    int bw = blockDim.x * 8;
    for (int t = threadIdx.y * blockDim.x + threadIdx.x; t < 8 * KNN; t += bw)
        sidx[t / KNN][t % KNN] = idx[((long long)b * NPTS + n0 + t / KNN) * KNN + t % KNN];
    __syncthreads();

    int ld = 2 * O;
    const float* base = YZ + (long long)b * NPTS * ld;

    float4 zc = *(const float4*)&base[(long long)n * ld + O + o4 * 4];
    float4 mx = make_float4(-INFINITY, -INFINITY, -INFINITY, -INFINITY);
    float4 mn = make_float4(INFINITY, INFINITY, INFINITY, INFINITY);
    #pragma unroll
    for (int kk = 0; kk < KNN; ++kk) {
        float4 y = *(const float4*)&base[(long long)sidx[py][kk] * ld + o4 * 4];
        mx.x = fmaxf(mx.x, y.x); mn.x = fminf(mn.x, y.x);
        mx.y = fmaxf(mx.y, y.y); mn.y = fminf(mn.y, y.y);
        mx.z = fmaxf(mx.z, y.z); mn.z = fminf(mn.z, y.z);
        mx.w = fmaxf(mx.w, y.w); mn.w = fminf(mn.w, y.w);
    }

    float4 g4  = *(const float4*)&bn[o4 * 4];
    float4 be4 = *(const float4*)&bn[O + o4 * 4];
    float4 mu4 = *(const float4*)&bn[2 * O + o4 * 4];
    float4 va4 = *(const float4*)&bn[3 * O + o4 * 4];

    float4 r;
    {
        float s = g4.x * rsqrtf(va4.x + EPSBN);
        float z = (s >= 0.f ? mx.x : mn.x) + zc.x;
        float v = s * z + (be4.x - mu4.x * s);
        r.x = v > 0.f ? v : SLOPE * v;
    }
    {
        float s = g4.y * rsqrtf(va4.y + EPSBN);
        float z = (s >= 0.f ? mx.y : mn.y) + zc.y;
        float v = s * z + (be4.y - mu4.y * s);
        r.y = v > 0.f ? v : SLOPE * v;
    }
    {
        float s = g4.z * rsqrtf(va4.z + EPSBN);
        float z = (s >= 0.f ? mx.z : mn.z) + zc.z;
        float v = s * z + (be4.z - mu4.z * s);
        r.z = v > 0.f ? v : SLOPE * v;
    }
    {
        float s = g4.w * rsqrtf(va4.w + EPSBN);
        float z = (s >= 0.f ? mx.w : mn.w) + zc.w;
        float v = s * z + (be4.w - mu4.w * s);
        r.w = v > 0.f ? v : SLOPE * v;
    }
    *(float4*)&hcat[((long long)b * NPTS + n) * 512 + catoff + o4 * 4] = r;
}

// ---------------- global max + mean pool over N ----------------
__global__ void pool_kernel(const float* __restrict__ h5, float* __restrict__ pool)
{
    int b = blockIdx.y;
    int c = blockIdx.x * blockDim.x + threadIdx.x;
    float mx = -INFINITY, sm = 0.f;
    long long base = (long long)b * NPTS * 1024 + c;
    for (int n = 0; n < NPTS; ++n) {
        float v = h5[base + (long long)n * 1024];
        mx = fmaxf(mx, v);
        sm += v;
    }
    pool[b * 2048 + c] = mx;
    pool[b * 2048 + 1024 + c] = sm * (1.f / (float)NPTS);
}

// ---------------- FC layer: warp per (b,o) ----------------
__global__ void fc_kernel(const float* __restrict__ in, const float* __restrict__ W,
                          const float* __restrict__ bn, const float* __restrict__ bias,
                          float* __restrict__ out, int O, int K, int Bn)
{
    int gw = (blockIdx.x * blockDim.x + threadIdx.x) >> 5;
    int lane = threadIdx.x & 31;
    if (gw >= Bn * O) return;
    int b = gw / O, o = gw % O;
    float acc = 0.f;
    const float* ip = in + (long long)b * K;
    const float* wp = W + (long long)o * K;
    for (int k = lane; k < K; k += 32) acc += ip[k] * wp[k];
    #pragma unroll
    for (int off = 16; off > 0; off >>= 1)
        acc += __shfl_down_sync(0xffffffffu, acc, off);
    if (lane == 0) {
        float v = acc;
        if (bn) {
            float g  = bn[o];
            float be = bn[O + o];
            float mu = bn[2 * O + o];
            float va = bn[3 * O + o];
            float s = g * rsqrtf(va + EPSBN);
            v = s * v + (be - mu * s);
            v = v > 0.f ? v : SLOPE * v;
        } else {
            v += bias[o];
        }
        out[(long long)b * O + o] = v;
    }
}

// ---------------- host orchestration ----------------
extern "C" void kernel_launch(void* const* d_in, const int* in_sizes, int n_in,
                              void* d_out, int out_size)
{
    (void)in_sizes; (void)n_in; (void)out_size;
    const float* x   = (const float*)d_in[0];
    const float* w1  = (const float*)d_in[1];
    const float* bn1 = (const float*)d_in[2];
    const float* w2  = (const float*)d_in[3];
    const float* bn2 = (const float*)d_in[4];
    const float* w3  = (const float*)d_in[5];
    const float* bn3 = (const float*)d_in[6];
    const float* w4  = (const float*)d_in[7];
    const float* bn4 = (const float*)d_in[8];
    const float* w5  = (const float*)d_in[9];
    const float* bn5 = (const float*)d_in[10];
    const float* wl1 = (const float*)d_in[11];
    const float* bn6 = (const float*)d_in[12];
    const float* wl2 = (const float*)d_in[13];
    const float* bn7 = (const float*)d_in[14];
    const float* wl3 = (const float*)d_in[15];
    const float* bl3 = (const float*)d_in[16];
    float* out = (float*)d_out;

    float *p_xT, *p_hcat, *p_pd, *p_YZ, *p_h5, *p_W, *p_sq, *p_pool, *p_fc1, *p_fc2;
    int* p_idx;
    cudaGetSymbolAddress((void**)&p_xT,   g_xT);
    cudaGetSymbolAddress((void**)&p_hcat, g_hcat);
    cudaGetSymbolAddress((void**)&p_pd,   g_pd);
    cudaGetSymbolAddress((void**)&p_idx,  g_idx);
    cudaGetSymbolAddress((void**)&p_YZ,   g_YZ);
    cudaGetSymbolAddress((void**)&p_h5,   g_h5);
    cudaGetSymbolAddress((void**)&p_W,    g_W);
    cudaGetSymbolAddress((void**)&p_sq,   g_sq);
    cudaGetSymbolAddress((void**)&p_pool, g_pool);
    cudaGetSymbolAddress((void**)&p_fc1,  g_fc1);
    cudaGetSymbolAddress((void**)&p_fc2,  g_fc2);

    {
        int tot = BATCH * 3 * NPTS;
        transpose_x_kernel<<<(tot + 255) / 256, 256>>>(x, p_xT);
    }

    struct Blk { const float* h; int lda, C, O; const float* w; const float* bn; int catoff; };
    Blk blks[4] = {
        { p_xT,         3,   3,   64,  w1, bn1, 0   },
        { p_hcat + 0,   512, 64,  64,  w2, bn2, 64  },
        { p_hcat + 64,  512, 64,  128, w3, bn3, 128 },
        { p_hcat + 128, 512, 128, 256, w4, bn4, 256 },
    };

    for (int i = 0; i < 4; ++i) {
        const Blk& B = blks[i];

        {
            int threads = BATCH * NPTS * 32;
            sqnorm_kernel<<<(threads + 255) / 256, 256>>>(B.h, B.lda, B.C, p_sq);
        }
        {
            dim3 grid(NPTS / 128, NPTS / 128, BATCH);
            sgemm_nt_kernel<<<grid, 256>>>(B.h, B.h, p_pd,
                NPTS, NPTS, B.C, B.lda, B.lda, NPTS,
                (long long)NPTS * B.lda, (long long)NPTS * B.lda,
                (long long)NPTS * NPTS, 2, p_sq);
        }
        topk_warp_kernel<<<(BATCH * NPTS) / 8, 256>>>(p_pd, p_idx);
        {
            int tot = 2 * B.O * B.C;
            prep_w_kernel<<<(tot + 255) / 256, 256>>>(B.w, p_W, B.O, B.C);
        }
        {
            dim3 grid((2 * B.O) / 128, (BATCH * NPTS) / 128, 1);
            sgemm_nt_kernel<<<grid, 256>>>(B.h, p_W, p_YZ,
                BATCH * NPTS, 2 * B.O, B.C, B.lda, B.C, 2 * B.O,
                0, 0, 0, 0, nullptr);
        }
        {
            dim3 blk(B.O / 4, 8);
            gather_max_bn_kernel<<<dim3(NPTS / 8, BATCH), blk>>>(p_YZ, p_idx, B.bn,
                                                                 p_hcat, B.O, B.catoff);
        }
    }

    {
        dim3 grid(1024 / 128, (BATCH * NPTS) / 128, 1);
        sgemm_nt_kernel<<<grid, 256>>>(p_hcat, w5, p_h5,
            BATCH * NPTS, 1024, 512, 512, 512, 1024,
            0, 0, 0, 1, bn5);
    }

    pool_kernel<<<dim3(4, BATCH), 256>>>(p_h5, p_pool);

    {
        int warps = BATCH * 512;
        fc_kernel<<<(warps * 32 + 255) / 256, 256>>>(p_pool, wl1, bn6, nullptr,
                                                     p_fc1, 512, 2048, BATCH);
    }
    {
        int warps = BATCH * 256;
        fc_kernel<<<(warps * 32 + 255) / 256, 256>>>(p_fc1, wl2, bn7, nullptr,
                                                     p_fc2, 256, 512, BATCH);
    }
    {
        int warps = BATCH * 40;
        fc_kernel<<<(warps * 32 + 255) / 256, 256>>>(p_fc2, wl3, nullptr, bl3,
                                                     out, 40, 256, BATCH);
    }
}

// round 5
// speedup vs baseline: 4.1530x; 1.2954x over previous
#include <cuda_runtime.h>
#include <cmath>

#define BATCH 16
#define NPTS  1024
#define KNN   20
#define EPSBN 1e-5f
#define SLOPE 0.2f

// ---------------- scratch (device globals; no allocations allowed) ----------------
__device__ float g_xT[BATCH * NPTS * 8];               // padded C: 3 -> 8 (zeros)
__device__ float g_hcat[BATCH * NPTS * 512];
__device__ float g_pd[(long long)BATCH * NPTS * NPTS];
__device__ int   g_idx[BATCH * NPTS * KNN];
__device__ float g_YZ[BATCH * NPTS * 512];
__device__ float g_h5[(long long)BATCH * NPTS * 1024];
__device__ float g_W[512 * 128];
__device__ float g_sq[BATCH * NPTS];
__device__ float g_pool[BATCH * 2048];
__device__ float g_fc1[BATCH * 512];
__device__ float g_fc2[BATCH * 256];

// ---------------- f32x2 packed helpers (sm_103a FFMA2 path) ----------------
__device__ __forceinline__ unsigned long long pack2(float lo, float hi)
{
    unsigned long long r;
    asm("mov.b64 %0, {%1, %2};" : "=l"(r) : "f"(lo), "f"(hi));
    return r;
}
__device__ __forceinline__ void ffma2(unsigned long long& acc,
                                      unsigned long long a, unsigned long long b)
{
    asm("fma.rn.f32x2 %0, %1, %2, %0;" : "+l"(acc) : "l"(a), "l"(b));
}
__device__ __forceinline__ float2 unpack2(unsigned long long v)
{
    float lo, hi;
    asm("mov.b64 {%0, %1}, %2;" : "=f"(lo), "=f"(hi) : "l"(v));
    return make_float2(lo, hi);
}

// ---------------- transpose x (B,3,N) -> (B,N,8) zero-padded ----------------
__global__ void transpose_x_kernel(const float* __restrict__ x, float* __restrict__ xT)
{
    int p = blockIdx.x * blockDim.x + threadIdx.x;   // point index b*N+n
    if (p >= BATCH * NPTS) return;
    int b = p / NPTS;
    int n = p % NPTS;
    const float* xb = x + (long long)b * 3 * NPTS + n;
    float4 lo = make_float4(xb[0], xb[NPTS], xb[2 * NPTS], 0.f);
    float4 hi = make_float4(0.f, 0.f, 0.f, 0.f);
    *(float4*)&xT[p * 8]     = lo;
    *(float4*)&xT[p * 8 + 4] = hi;
}

// ---------------- squared norms per point ----------------
__global__ void sqnorm_kernel(const float* __restrict__ h, int lda, int C,
                              float* __restrict__ sq)
{
    int p = (blockIdx.x * blockDim.x + threadIdx.x) >> 5;
    int lane = threadIdx.x & 31;
    if (p >= BATCH * NPTS) return;
    float acc = 0.f;
    for (int c = lane; c < C; c += 32) {
        float v = h[(long long)p * lda + c];
        acc += v * v;
    }
    #pragma unroll
    for (int off = 16; off > 0; off >>= 1)
        acc += __shfl_down_sync(0xffffffffu, acc, off);
    if (lane == 0) sq[p] = acc;
}

// ---------------- 128x128 tiled SGEMM, f32x2 core + reg double buffer -----------
// Requirement: K multiple of 8 (callers pad). One LDG.128 per operand per ktile.
// epi: 0 = none, 1 = BN+LeakyReLU (e0 = bn (4,N)), 2 = pd (e0 = sq per-batch)
__global__ void __launch_bounds__(256)
sgemm_nt_kernel(const float* __restrict__ A, const float* __restrict__ Bw,
                float* __restrict__ C,
                int M, int Nn, int K, int lda, int ldb, int ldc,
                long long bsA, long long bsB, long long bsC,
                int epi, const float* __restrict__ e0)
{
    A  += (long long)blockIdx.z * bsA;
    Bw += (long long)blockIdx.z * bsB;
    C  += (long long)blockIdx.z * bsC;

    __shared__ float As[8][128];
    __shared__ float Bs[8][128];

    int tid = threadIdx.x;
    int tx = tid & 15;
    int ty = tid >> 4;
    int bx = blockIdx.x, by = blockIdx.y;

    int l_row = tid >> 1;
    int l_k0  = (tid & 1) * 4;

    const float* aptr = A + (long long)(by * 128 + l_row) * lda + l_k0;
    const float* bptr = Bw + (long long)(bx * 128 + l_row) * ldb + l_k0;

    float4 ra = *(const float4*)aptr;
    float4 rb = *(const float4*)bptr;

    unsigned long long acc2[8][4];
    #pragma unroll
    for (int i = 0; i < 8; ++i)
        #pragma unroll
        for (int j = 0; j < 4; ++j)
            acc2[i][j] = 0ull;

    for (int kt = 0; kt < K; kt += 8) {
        As[l_k0 + 0][l_row] = ra.x;
        As[l_k0 + 1][l_row] = ra.y;
        As[l_k0 + 2][l_row] = ra.z;
        As[l_k0 + 3][l_row] = ra.w;
        Bs[l_k0 + 0][l_row] = rb.x;
        Bs[l_k0 + 1][l_row] = rb.y;
        Bs[l_k0 + 2][l_row] = rb.z;
        Bs[l_k0 + 3][l_row] = rb.w;
        __syncthreads();

        if (kt + 8 < K) {
            ra = *(const float4*)(aptr + kt + 8);
            rb = *(const float4*)(bptr + kt + 8);
        }

        #pragma unroll
        for (int kk = 0; kk < 8; ++kk) {
            float4 a0 = *(const float4*)&As[kk][ty * 8];
            float4 a1 = *(const float4*)&As[kk][ty * 8 + 4];
            float4 b0 = *(const float4*)&Bs[kk][tx * 8];
            float4 b1 = *(const float4*)&Bs[kk][tx * 8 + 4];

            unsigned long long bp[4];
            bp[0] = pack2(b0.x, b0.y);
            bp[1] = pack2(b0.z, b0.w);
            bp[2] = pack2(b1.x, b1.y);
            bp[3] = pack2(b1.z, b1.w);

            float a[8] = {a0.x, a0.y, a0.z, a0.w, a1.x, a1.y, a1.z, a1.w};
            #pragma unroll
            for (int i = 0; i < 8; ++i) {
                unsigned long long ap = pack2(a[i], a[i]);
                #pragma unroll
                for (int j = 0; j < 4; ++j)
                    ffma2(acc2[i][j], ap, bp[j]);
            }
        }
        __syncthreads();
    }

    // epilogue
    #pragma unroll
    for (int i = 0; i < 8; ++i) {
        int gm = by * 128 + ty * 8 + i;
        float sqm = (epi == 2) ? e0[blockIdx.z * M + gm] : 0.f;
        #pragma unroll
        for (int jj = 0; jj < 2; ++jj) {
            float4 v4;
            float* vv = (float*)&v4;
            float2 p0 = unpack2(acc2[i][jj * 2]);
            float2 p1 = unpack2(acc2[i][jj * 2 + 1]);
            float av[4] = {p0.x, p0.y, p1.x, p1.y};
            #pragma unroll
            for (int j = 0; j < 4; ++j) {
                int gn = bx * 128 + tx * 8 + jj * 4 + j;
                float v = av[j];
                if (epi == 1) {
                    float g  = e0[gn];
                    float be = e0[Nn + gn];
                    float mu = e0[2 * Nn + gn];
                    float va = e0[3 * Nn + gn];
                    float s = g * rsqrtf(va + EPSBN);
                    v = s * v + (be - mu * s);
                    v = v > 0.f ? v : SLOPE * v;
                } else if (epi == 2) {
                    v = 2.f * v - sqm - e0[blockIdx.z * M + gn];
                }
                vv[j] = v;
            }
            *(float4*)&C[(long long)gm * ldc + bx * 128 + tx * 8 + jj * 4] = v4;
        }
    }
}

// ---------------- warp-per-row top-k (k=20), REDUX + per-lane top-2 cache -------
__global__ void __launch_bounds__(256) topk_warp_kernel(const float* __restrict__ pd,
                                                        int* __restrict__ out)
{
    int warp_in_blk = threadIdx.x >> 5;
    int lane = threadIdx.x & 31;
    int row = blockIdx.x * 8 + warp_in_blk;

    const float* __restrict__ p = pd + (long long)row * NPTS;

    unsigned k[32];
    #pragma unroll
    for (int j = 0; j < 32; ++j) {
        unsigned u = __float_as_uint(p[j * 32 + lane]);
        k[j] = (u & 0x80000000u) ? ~u : (u | 0x80000000u);  // order-preserving key
    }

    unsigned b1 = 0, b2 = 0;
    int j1 = 0, j2 = 0;
    #pragma unroll
    for (int j = 0; j < 32; ++j) {
        unsigned v = k[j];
        if (v > b1) { b2 = b1; j2 = j1; b1 = v; j1 = j; }
        else if (v > b2) { b2 = v; j2 = j; }
    }
    bool have2 = true;

    int* __restrict__ o = out + (long long)row * KNN;

    #pragma unroll 1
    for (int it = 0; it < KNN; ++it) {
        unsigned m = __reduce_max_sync(0xffffffffu, b1);
        unsigned bal = __ballot_sync(0xffffffffu, b1 == m);
        int src = __ffs((int)bal) - 1;
        int gi = __shfl_sync(0xffffffffu, (j1 << 5) | lane, src);
        if (lane == 0) o[it] = gi;

        if (lane == src) {
            k[j1] = 0u;
            if (have2) {
                b1 = b2; j1 = j2; have2 = false;
            } else {
                unsigned n1 = 0, n2 = 0;
                int i1 = 0, i2 = 0;
                #pragma unroll
                for (int j = 0; j < 32; ++j) {
                    unsigned v = k[j];
                    if (v > n1) { n2 = n1; i2 = i1; n1 = v; i1 = j; }
                    else if (v > n2) { n2 = v; i2 = j; }
                }
                b1 = n1; j1 = i1; b2 = n2; j2 = i2; have2 = true;
            }
        }
    }
}

// ---------------- prepare edge weights: [wa ; wb - wa], K-padded ----------------
__global__ void prep_w_kernel(const float* __restrict__ w, float* __restrict__ Wc,
                              int O, int C, int Cpad)
{
    int i = blockIdx.x * blockDim.x + threadIdx.x;
    int tot = 2 * O * Cpad;
    if (i >= tot) return;
    int half = i / (O * Cpad);
    int j = i % (O * Cpad);
    int o = j / Cpad, c = j % Cpad;
    float v = 0.f;
    if (c < C)
        v = half == 0 ? w[o * 2 * C + c]
                      : w[o * 2 * C + C + c] - w[o * 2 * C + c];
    Wc[half * O * Cpad + o * Cpad + c] = v;
}

// ---------------- gather + max_k + BN + LReLU, float4-vectorized ----------------
__global__ void gather_max_bn_kernel(const float* __restrict__ YZ,
                                     const int* __restrict__ idx,
                                     const float* __restrict__ bn,
                                     float* __restrict__ hcat,
                                     int O, int catoff)
{
    int b = blockIdx.y;
    int n0 = blockIdx.x * 8;
    int o4 = threadIdx.x;
    int py = threadIdx.y;
    int n = n0 + py;

    __shared__ int sidx[8][KNN];
    int bw = blockDim.x * 8;
    for (int t = threadIdx.y * blockDim.x + threadIdx.x; t < 8 * KNN; t += bw)
        sidx[t / KNN][t % KNN] = idx[((long long)b * NPTS + n0 + t / KNN) * KNN + t % KNN];
    __syncthreads();

    int ld = 2 * O;
    const float* base = YZ + (long long)b * NPTS * ld;

    float4 zc = *(const float4*)&base[(long long)n * ld + O + o4 * 4];
    float4 mx = make_float4(-INFINITY, -INFINITY, -INFINITY, -INFINITY);
    float4 mn = make_float4(INFINITY, INFINITY, INFINITY, INFINITY);
    #pragma unroll
    for (int kk = 0; kk < KNN; ++kk) {
        float4 y = *(const float4*)&base[(long long)sidx[py][kk] * ld + o4 * 4];
        mx.x = fmaxf(mx.x, y.x); mn.x = fminf(mn.x, y.x);
        mx.y = fmaxf(mx.y, y.y); mn.y = fminf(mn.y, y.y);
        mx.z = fmaxf(mx.z, y.z); mn.z = fminf(mn.z, y.z);
        mx.w = fmaxf(mx.w, y.w); mn.w = fminf(mn.w, y.w);
    }

    float4 g4  = *(const float4*)&bn[o4 * 4];
    float4 be4 = *(const float4*)&bn[O + o4 * 4];
    float4 mu4 = *(const float4*)&bn[2 * O + o4 * 4];
    float4 va4 = *(const float4*)&bn[3 * O + o4 * 4];

    float4 r;
    {
        float s = g4.x * rsqrtf(va4.x + EPSBN);
        float z = (s >= 0.f ? mx.x : mn.x) + zc.x;
        float v = s * z + (be4.x - mu4.x * s);
        r.x = v > 0.f ? v : SLOPE * v;
    }
    {
        float s = g4.y * rsqrtf(va4.y + EPSBN);
        float z = (s >= 0.f ? mx.y : mn.y) + zc.y;
        float v = s * z + (be4.y - mu4.y * s);
        r.y = v > 0.f ? v : SLOPE * v;
    }
    {
        float s = g4.z * rsqrtf(va4.z + EPSBN);
        float z = (s >= 0.f ? mx.z : mn.z) + zc.z;
        float v = s * z + (be4.z - mu4.z * s);
        r.z = v > 0.f ? v : SLOPE * v;
    }
    {
        float s = g4.w * rsqrtf(va4.w + EPSBN);
        float z = (s >= 0.f ? mx.w : mn.w) + zc.w;
        float v = s * z + (be4.w - mu4.w * s);
        r.w = v > 0.f ? v : SLOPE * v;
    }
    *(float4*)&hcat[((long long)b * NPTS + n) * 512 + catoff + o4 * 4] = r;
}

// ---------------- global max + mean pool over N ----------------
__global__ void pool_kernel(const float* __restrict__ h5, float* __restrict__ pool)
{
    int b = blockIdx.y;
    int c = blockIdx.x * blockDim.x + threadIdx.x;
    float mx = -INFINITY, sm = 0.f;
    long long base = (long long)b * NPTS * 1024 + c;
    for (int n = 0; n < NPTS; ++n) {
        float v = h5[base + (long long)n * 1024];
        mx = fmaxf(mx, v);
        sm += v;
    }
    pool[b * 2048 + c] = mx;
    pool[b * 2048 + 1024 + c] = sm * (1.f / (float)NPTS);
}

// ---------------- FC layer: warp per (b,o) ----------------
__global__ void fc_kernel(const float* __restrict__ in, const float* __restrict__ W,
                          const float* __restrict__ bn, const float* __restrict__ bias,
                          float* __restrict__ out, int O, int K, int Bn)
{
    int gw = (blockIdx.x * blockDim.x + threadIdx.x) >> 5;
    int lane = threadIdx.x & 31;
    if (gw >= Bn * O) return;
    int b = gw / O, o = gw % O;
    float acc = 0.f;
    const float* ip = in + (long long)b * K;
    const float* wp = W + (long long)o * K;
    for (int k = lane; k < K; k += 32) acc += ip[k] * wp[k];
    #pragma unroll
    for (int off = 16; off > 0; off >>= 1)
        acc += __shfl_down_sync(0xffffffffu, acc, off);
    if (lane == 0) {
        float v = acc;
        if (bn) {
            float g  = bn[o];
            float be = bn[O + o];
            float mu = bn[2 * O + o];
            float va = bn[3 * O + o];
            float s = g * rsqrtf(va + EPSBN);
            v = s * v + (be - mu * s);
            v = v > 0.f ? v : SLOPE * v;
        } else {
            v += bias[o];
        }
        out[(long long)b * O + o] = v;
    }
}

// ---------------- host orchestration ----------------
extern "C" void kernel_launch(void* const* d_in, const int* in_sizes, int n_in,
                              void* d_out, int out_size)
{
    (void)in_sizes; (void)n_in; (void)out_size;
    const float* x   = (const float*)d_in[0];
    const float* w1  = (const float*)d_in[1];
    const float* bn1 = (const float*)d_in[2];
    const float* w2  = (const float*)d_in[3];
    const float* bn2 = (const float*)d_in[4];
    const float* w3  = (const float*)d_in[5];
    const float* bn3 = (const float*)d_in[6];
    const float* w4  = (const float*)d_in[7];
    const float* bn4 = (const float*)d_in[8];
    const float* w5  = (const float*)d_in[9];
    const float* bn5 = (const float*)d_in[10];
    const float* wl1 = (const float*)d_in[11];
    const float* bn6 = (const float*)d_in[12];
    const float* wl2 = (const float*)d_in[13];
    const float* bn7 = (const float*)d_in[14];
    const float* wl3 = (const float*)d_in[15];
    const float* bl3 = (const float*)d_in[16];
    float* out = (float*)d_out;

    float *p_xT, *p_hcat, *p_pd, *p_YZ, *p_h5, *p_W, *p_sq, *p_pool, *p_fc1, *p_fc2;
    int* p_idx;
    cudaGetSymbolAddress((void**)&p_xT,   g_xT);
    cudaGetSymbolAddress((void**)&p_hcat, g_hcat);
    cudaGetSymbolAddress((void**)&p_pd,   g_pd);
    cudaGetSymbolAddress((void**)&p_idx,  g_idx);
    cudaGetSymbolAddress((void**)&p_YZ,   g_YZ);
    cudaGetSymbolAddress((void**)&p_h5,   g_h5);
    cudaGetSymbolAddress((void**)&p_W,    g_W);
    cudaGetSymbolAddress((void**)&p_sq,   g_sq);
    cudaGetSymbolAddress((void**)&p_pool, g_pool);
    cudaGetSymbolAddress((void**)&p_fc1,  g_fc1);
    cudaGetSymbolAddress((void**)&p_fc2,  g_fc2);

    {
        int tot = BATCH * NPTS;
        transpose_x_kernel<<<(tot + 255) / 256, 256>>>(x, p_xT);
    }

    struct Blk { const float* h; int lda, C, Cpad, O; const float* w; const float* bn; int catoff; };
    Blk blks[4] = {
        { p_xT,         8,   3,   8,   64,  w1, bn1, 0   },
        { p_hcat + 0,   512, 64,  64,  64,  w2, bn2, 64  },
        { p_hcat + 64,  512, 64,  64,  128, w3, bn3, 128 },
        { p_hcat + 128, 512, 128, 128, 256, w4, bn4, 256 },
    };

    for (int i = 0; i < 4; ++i) {
        const Blk& B = blks[i];

        {
            int threads = BATCH * NPTS * 32;
            sqnorm_kernel<<<(threads + 255) / 256, 256>>>(B.h, B.lda, B.C, p_sq);
        }
        // pd = 2*G - sq_m - sq_n   (K padded to Cpad; pad columns are zero)
        {
            dim3 grid(NPTS / 128, NPTS / 128, BATCH);
            sgemm_nt_kernel<<<grid, 256>>>(B.h, B.h, p_pd,
                NPTS, NPTS, B.Cpad, B.lda, B.lda, NPTS,
                (long long)NPTS * B.lda, (long long)NPTS * B.lda,
                (long long)NPTS * NPTS, 2, p_sq);
        }
        topk_warp_kernel<<<(BATCH * NPTS) / 8, 256>>>(p_pd, p_idx);
        {
            int tot = 2 * B.O * B.Cpad;
            prep_w_kernel<<<(tot + 255) / 256, 256>>>(B.w, p_W, B.O, B.C, B.Cpad);
        }
        // YZ = h @ Wc^T  (M = B*N, Nn = 2*O)
        {
            dim3 grid((2 * B.O) / 128, (BATCH * NPTS) / 128, 1);
            sgemm_nt_kernel<<<grid, 256>>>(B.h, p_W, p_YZ,
                BATCH * NPTS, 2 * B.O, B.Cpad, B.lda, B.Cpad, 2 * B.O,
                0, 0, 0, 0, nullptr);
        }
        {
            dim3 blk(B.O / 4, 8);
            gather_max_bn_kernel<<<dim3(NPTS / 8, BATCH), blk>>>(p_YZ, p_idx, B.bn,
                                                                 p_hcat, B.O, B.catoff);
        }
    }

    // conv5: (B*N,512) @ w5^T (1024,512) + BN+LReLU
    {
        dim3 grid(1024 / 128, (BATCH * NPTS) / 128, 1);
        sgemm_nt_kernel<<<grid, 256>>>(p_hcat, w5, p_h5,
            BATCH * NPTS, 1024, 512, 512, 512, 1024,
            0, 0, 0, 1, bn5);
    }

    pool_kernel<<<dim3(4, BATCH), 256>>>(p_h5, p_pool);

    {
        int warps = BATCH * 512;
        fc_kernel<<<(warps * 32 + 255) / 256, 256>>>(p_pool, wl1, bn6, nullptr,
                                                     p_fc1, 512, 2048, BATCH);
    }
    {
        int warps = BATCH * 256;
        fc_kernel<<<(warps * 32 + 255) / 256, 256>>>(p_fc1, wl2, bn7, nullptr,
                                                     p_fc2, 256, 512, BATCH);
    }
    {
        int warps = BATCH * 40;
        fc_kernel<<<(warps * 32 + 255) / 256, 256>>>(p_fc2, wl3, nullptr, bl3,
                                                     out, 40, 256, BATCH);
    }
}

// round 6
// speedup vs baseline: 4.1845x; 1.0076x over previous
#include <cuda_runtime.h>
#include <cmath>

#define BATCH 16
#define NPTS  1024
#define KNN   20
#define EPSBN 1e-5f
#define SLOPE 0.2f

// ---------------- scratch (device globals; no allocations allowed) ----------------
__device__ float g_xT[BATCH * NPTS * 8];               // padded C: 3 -> 8 (zeros)
__device__ float g_hcat[BATCH * NPTS * 512];
__device__ float g_pd[(long long)BATCH * NPTS * NPTS];
__device__ int   g_idx[BATCH * NPTS * KNN];
__device__ float g_YZ[BATCH * NPTS * 512];
__device__ float g_W[512 * 128];
__device__ float g_sq[BATCH * NPTS];
__device__ float g_pmax[8 * BATCH * 1024];
__device__ float g_psum[8 * BATCH * 1024];
__device__ float g_pool[BATCH * 2048];
__device__ float g_fc1[BATCH * 512];
__device__ float g_fc2[BATCH * 256];

// ---------------- f32x2 packed helpers (sm_103a FFMA2 path) ----------------
__device__ __forceinline__ unsigned long long pack2(float lo, float hi)
{
    unsigned long long r;
    asm("mov.b64 %0, {%1, %2};" : "=l"(r) : "f"(lo), "f"(hi));
    return r;
}
__device__ __forceinline__ void ffma2(unsigned long long& acc,
                                      unsigned long long a, unsigned long long b)
{
    asm("fma.rn.f32x2 %0, %1, %2, %0;" : "+l"(acc) : "l"(a), "l"(b));
}
__device__ __forceinline__ float2 unpack2(unsigned long long v)
{
    float lo, hi;
    asm("mov.b64 {%0, %1}, %2;" : "=f"(lo), "=f"(hi) : "l"(v));
    return make_float2(lo, hi);
}

// ---------------- transpose x (B,3,N) -> (B,N,8) zero-padded ----------------
__global__ void transpose_x_kernel(const float* __restrict__ x, float* __restrict__ xT)
{
    int p = blockIdx.x * blockDim.x + threadIdx.x;
    if (p >= BATCH * NPTS) return;
    int b = p / NPTS;
    int n = p % NPTS;
    const float* xb = x + (long long)b * 3 * NPTS + n;
    float4 lo = make_float4(xb[0], xb[NPTS], xb[2 * NPTS], 0.f);
    float4 hi = make_float4(0.f, 0.f, 0.f, 0.f);
    *(float4*)&xT[p * 8]     = lo;
    *(float4*)&xT[p * 8 + 4] = hi;
}

// ---------------- squared norms per point ----------------
__global__ void sqnorm_kernel(const float* __restrict__ h, int lda, int C,
                              float* __restrict__ sq)
{
    int p = (blockIdx.x * blockDim.x + threadIdx.x) >> 5;
    int lane = threadIdx.x & 31;
    if (p >= BATCH * NPTS) return;
    float acc = 0.f;
    for (int c = lane; c < C; c += 32) {
        float v = h[(long long)p * lda + c];
        acc += v * v;
    }
    #pragma unroll
    for (int off = 16; off > 0; off >>= 1)
        acc += __shfl_down_sync(0xffffffffu, acc, off);
    if (lane == 0) sq[p] = acc;
}

// ---------------- 128x128 tiled SGEMM, f32x2 core + reg double buffer -----------
// K multiple of 8 (callers pad).
// epi: 0 = none, 1 = BN+LeakyReLU (e0 = bn (4,N)), 2 = pd (e0 = sq per-batch)
// sym: pd symmetric mode — blockIdx.x = linear lower-triangle tile id; mirror-write.
__global__ void __launch_bounds__(256)
sgemm_nt_kernel(const float* __restrict__ A, const float* __restrict__ Bw,
                float* __restrict__ C,
                int M, int Nn, int K, int lda, int ldb, int ldc,
                long long bsA, long long bsB, long long bsC,
                int epi, const float* __restrict__ e0, int sym)
{
    A  += (long long)blockIdx.z * bsA;
    Bw += (long long)blockIdx.z * bsB;
    C  += (long long)blockIdx.z * bsC;

    __shared__ float As[8][128];
    __shared__ float Bs[8][128];

    int tid = threadIdx.x;
    int tx = tid & 15;
    int ty = tid >> 4;

    int bx, by;
    if (sym) {
        int t = blockIdx.x;
        int i = (int)floorf((sqrtf(8.f * t + 1.f) - 1.f) * 0.5f);
        while ((i + 1) * (i + 2) / 2 <= t) ++i;
        while (i * (i + 1) / 2 > t) --i;
        by = i;
        bx = t - i * (i + 1) / 2;
    } else {
        bx = blockIdx.x;
        by = blockIdx.y;
    }

    int l_row = tid >> 1;
    int l_k0  = (tid & 1) * 4;

    const float* aptr = A + (long long)(by * 128 + l_row) * lda + l_k0;
    const float* bptr = Bw + (long long)(bx * 128 + l_row) * ldb + l_k0;

    float4 ra = *(const float4*)aptr;
    float4 rb = *(const float4*)bptr;

    unsigned long long acc2[8][4];
    #pragma unroll
    for (int i = 0; i < 8; ++i)
        #pragma unroll
        for (int j = 0; j < 4; ++j)
            acc2[i][j] = 0ull;

    for (int kt = 0; kt < K; kt += 8) {
        As[l_k0 + 0][l_row] = ra.x;
        As[l_k0 + 1][l_row] = ra.y;
        As[l_k0 + 2][l_row] = ra.z;
        As[l_k0 + 3][l_row] = ra.w;
        Bs[l_k0 + 0][l_row] = rb.x;
        Bs[l_k0 + 1][l_row] = rb.y;
        Bs[l_k0 + 2][l_row] = rb.z;
        Bs[l_k0 + 3][l_row] = rb.w;
        __syncthreads();

        if (kt + 8 < K) {
            ra = *(const float4*)(aptr + kt + 8);
            rb = *(const float4*)(bptr + kt + 8);
        }

        #pragma unroll
        for (int kk = 0; kk < 8; ++kk) {
            float4 a0 = *(const float4*)&As[kk][ty * 8];
            float4 a1 = *(const float4*)&As[kk][ty * 8 + 4];
            float4 b0 = *(const float4*)&Bs[kk][tx * 8];
            float4 b1 = *(const float4*)&Bs[kk][tx * 8 + 4];

            unsigned long long bp[4];
            bp[0] = pack2(b0.x, b0.y);
            bp[1] = pack2(b0.z, b0.w);
            bp[2] = pack2(b1.x, b1.y);
            bp[3] = pack2(b1.z, b1.w);

            float a[8] = {a0.x, a0.y, a0.z, a0.w, a1.x, a1.y, a1.z, a1.w};
            #pragma unroll
            for (int i = 0; i < 8; ++i) {
                unsigned long long ap = pack2(a[i], a[i]);
                #pragma unroll
                for (int j = 0; j < 4; ++j)
                    ffma2(acc2[i][j], ap, bp[j]);
            }
        }
        __syncthreads();
    }

    if (epi == 2) {
        // pd epilogue with optional mirror write
        float vals[8][8];
        #pragma unroll
        for (int i = 0; i < 8; ++i) {
            int gm = by * 128 + ty * 8 + i;
            float sqm = e0[blockIdx.z * M + gm];
            #pragma unroll
            for (int jj = 0; jj < 4; ++jj) {
                float2 p = unpack2(acc2[i][jj]);
                int gn0 = bx * 128 + tx * 8 + jj * 2;
                vals[i][jj * 2]     = 2.f * p.x - sqm - e0[blockIdx.z * M + gn0];
                vals[i][jj * 2 + 1] = 2.f * p.y - sqm - e0[blockIdx.z * M + gn0 + 1];
            }
        }
        #pragma unroll
        for (int i = 0; i < 8; ++i) {
            int gm = by * 128 + ty * 8 + i;
            *(float4*)&C[(long long)gm * ldc + bx * 128 + tx * 8]     = *(float4*)&vals[i][0];
            *(float4*)&C[(long long)gm * ldc + bx * 128 + tx * 8 + 4] = *(float4*)&vals[i][4];
        }
        if (sym && bx != by) {
            #pragma unroll
            for (int j = 0; j < 8; ++j) {
                int gn = bx * 128 + tx * 8 + j;
                float4 w0 = make_float4(vals[0][j], vals[1][j], vals[2][j], vals[3][j]);
                float4 w1 = make_float4(vals[4][j], vals[5][j], vals[6][j], vals[7][j]);
                *(float4*)&C[(long long)gn * ldc + by * 128 + ty * 8]     = w0;
                *(float4*)&C[(long long)gn * ldc + by * 128 + ty * 8 + 4] = w1;
            }
        }
        return;
    }

    #pragma unroll
    for (int i = 0; i < 8; ++i) {
        int gm = by * 128 + ty * 8 + i;
        #pragma unroll
        for (int jj = 0; jj < 2; ++jj) {
            float4 v4;
            float* vv = (float*)&v4;
            float2 p0 = unpack2(acc2[i][jj * 2]);
            float2 p1 = unpack2(acc2[i][jj * 2 + 1]);
            float av[4] = {p0.x, p0.y, p1.x, p1.y};
            #pragma unroll
            for (int j = 0; j < 4; ++j) {
                int gn = bx * 128 + tx * 8 + jj * 4 + j;
                float v = av[j];
                if (epi == 1) {
                    float g  = e0[gn];
                    float be = e0[Nn + gn];
                    float mu = e0[2 * Nn + gn];
                    float va = e0[3 * Nn + gn];
                    float s = g * rsqrtf(va + EPSBN);
                    v = s * v + (be - mu * s);
                    v = v > 0.f ? v : SLOPE * v;
                }
                vv[j] = v;
            }
            *(float4*)&C[(long long)gm * ldc + bx * 128 + tx * 8 + jj * 4] = v4;
        }
    }
}

// ---------------- conv5 GEMM with fused BN+LReLU + max/sum pooling --------------
// A = hcat (16384 x 512), Bw = w5 (1024 x 512). Grid: (8 col tiles, 128 row tiles).
// Each block reduces its 128 rows (one batch chunk) and writes partials.
__global__ void __launch_bounds__(256)
conv5_pool_kernel(const float* __restrict__ A, const float* __restrict__ Bw,
                  const float* __restrict__ bn,
                  float* __restrict__ pmax, float* __restrict__ psum)
{
    const int K = 512, lda = 512, ldb = 512;

    __shared__ float As[8][128];
    __shared__ float Bs[8][128];
    __shared__ float redmax[16][128];
    __shared__ float redsum[16][128];

    int tid = threadIdx.x;
    int tx = tid & 15;
    int ty = tid >> 4;
    int bx = blockIdx.x, by = blockIdx.y;

    int l_row = tid >> 1;
    int l_k0  = (tid & 1) * 4;

    const float* aptr = A + (long long)(by * 128 + l_row) * lda + l_k0;
    const float* bptr = Bw + (long long)(bx * 128 + l_row) * ldb + l_k0;

    float4 ra = *(const float4*)aptr;
    float4 rb = *(const float4*)bptr;

    unsigned long long acc2[8][4];
    #pragma unroll
    for (int i = 0; i < 8; ++i)
        #pragma unroll
        for (int j = 0; j < 4; ++j)
            acc2[i][j] = 0ull;

    for (int kt = 0; kt < K; kt += 8) {
        As[l_k0 + 0][l_row] = ra.x;
        As[l_k0 + 1][l_row] = ra.y;
        As[l_k0 + 2][l_row] = ra.z;
        As[l_k0 + 3][l_row] = ra.w;
        Bs[l_k0 + 0][l_row] = rb.x;
        Bs[l_k0 + 1][l_row] = rb.y;
        Bs[l_k0 + 2][l_row] = rb.z;
        Bs[l_k0 + 3][l_row] = rb.w;
        __syncthreads();

        if (kt + 8 < K) {
            ra = *(const float4*)(aptr + kt + 8);
            rb = *(const float4*)(bptr + kt + 8);
        }

        #pragma unroll
        for (int kk = 0; kk < 8; ++kk) {
            float4 a0 = *(const float4*)&As[kk][ty * 8];
            float4 a1 = *(const float4*)&As[kk][ty * 8 + 4];
            float4 b0 = *(const float4*)&Bs[kk][tx * 8];
            float4 b1 = *(const float4*)&Bs[kk][tx * 8 + 4];

            unsigned long long bp[4];
            bp[0] = pack2(b0.x, b0.y);
            bp[1] = pack2(b0.z, b0.w);
            bp[2] = pack2(b1.x, b1.y);
            bp[3] = pack2(b1.z, b1.w);

            float a[8] = {a0.x, a0.y, a0.z, a0.w, a1.x, a1.y, a1.z, a1.w};
            #pragma unroll
            for (int i = 0; i < 8; ++i) {
                unsigned long long ap = pack2(a[i], a[i]);
                #pragma unroll
                for (int j = 0; j < 4; ++j)
                    ffma2(acc2[i][j], ap, bp[j]);
            }
        }
        __syncthreads();
    }

    // BN + LReLU per column, then reduce over this thread's 8 rows
    float s8[8], o8[8];
    #pragma unroll
    for (int jc = 0; jc < 8; ++jc) {
        int gn = bx * 128 + tx * 8 + jc;
        float g  = bn[gn];
        float be = bn[1024 + gn];
        float mu = bn[2 * 1024 + gn];
        float va = bn[3 * 1024 + gn];
        float s = g * rsqrtf(va + EPSBN);
        s8[jc] = s;
        o8[jc] = be - mu * s;
    }

    float cmax[8], csum[8];
    #pragma unroll
    for (int jc = 0; jc < 8; ++jc) { cmax[jc] = -INFINITY; csum[jc] = 0.f; }

    #pragma unroll
    for (int i = 0; i < 8; ++i) {
        #pragma unroll
        for (int jj = 0; jj < 4; ++jj) {
            float2 p = unpack2(acc2[i][jj]);
            float v0 = s8[jj * 2] * p.x + o8[jj * 2];
            v0 = v0 > 0.f ? v0 : SLOPE * v0;
            float v1 = s8[jj * 2 + 1] * p.y + o8[jj * 2 + 1];
            v1 = v1 > 0.f ? v1 : SLOPE * v1;
            cmax[jj * 2]     = fmaxf(cmax[jj * 2], v0);
            csum[jj * 2]    += v0;
            cmax[jj * 2 + 1] = fmaxf(cmax[jj * 2 + 1], v1);
            csum[jj * 2 + 1] += v1;
        }
    }

    #pragma unroll
    for (int jc = 0; jc < 8; ++jc) {
        redmax[ty][tx * 8 + jc] = cmax[jc];
        redsum[ty][tx * 8 + jc] = csum[jc];
    }
    __syncthreads();

    if (tid < 128) {
        int c = tid;
        float mx = -INFINITY, sm = 0.f;
        #pragma unroll
        for (int t = 0; t < 16; ++t) {
            mx = fmaxf(mx, redmax[t][c]);
            sm += redsum[t][c];
        }
        int b = by >> 3, chunk = by & 7;
        pmax[((long long)chunk * BATCH + b) * 1024 + bx * 128 + c] = mx;
        psum[((long long)chunk * BATCH + b) * 1024 + bx * 128 + c] = sm;
    }
}

// ---------------- final pool reduce over 8 chunks ----------------
__global__ void pool_reduce_kernel(const float* __restrict__ pmax,
                                   const float* __restrict__ psum,
                                   float* __restrict__ pool)
{
    int gi = blockIdx.x * blockDim.x + threadIdx.x;
    if (gi >= BATCH * 1024) return;
    int b = gi >> 10;
    int c = gi & 1023;
    float mx = -INFINITY, sm = 0.f;
    #pragma unroll
    for (int chunk = 0; chunk < 8; ++chunk) {
        mx = fmaxf(mx, pmax[((long long)chunk * BATCH + b) * 1024 + c]);
        sm += psum[((long long)chunk * BATCH + b) * 1024 + c];
    }
    pool[b * 2048 + c] = mx;
    pool[b * 2048 + 1024 + c] = sm * (1.f / (float)NPTS);
}

// ---------------- warp-per-row top-k (k=20), REDUX + per-lane top-2 cache -------
__global__ void __launch_bounds__(256) topk_warp_kernel(const float* __restrict__ pd,
                                                        int* __restrict__ out)
{
    int warp_in_blk = threadIdx.x >> 5;
    int lane = threadIdx.x & 31;
    int row = blockIdx.x * 8 + warp_in_blk;

    const float* __restrict__ p = pd + (long long)row * NPTS;

    unsigned k[32];
    #pragma unroll
    for (int j = 0; j < 32; ++j) {
        unsigned u = __float_as_uint(p[j * 32 + lane]);
        k[j] = (u & 0x80000000u) ? ~u : (u | 0x80000000u);
    }

    unsigned b1 = 0, b2 = 0;
    int j1 = 0, j2 = 0;
    #pragma unroll
    for (int j = 0; j < 32; ++j) {
        unsigned v = k[j];
        if (v > b1) { b2 = b1; j2 = j1; b1 = v; j1 = j; }
        else if (v > b2) { b2 = v; j2 = j; }
    }
    bool have2 = true;

    int* __restrict__ o = out + (long long)row * KNN;

    #pragma unroll 1
    for (int it = 0; it < KNN; ++it) {
        unsigned m = __reduce_max_sync(0xffffffffu, b1);
        unsigned bal = __ballot_sync(0xffffffffu, b1 == m);
        int src = __ffs((int)bal) - 1;
        int gi = __shfl_sync(0xffffffffu, (j1 << 5) | lane, src);
        if (lane == 0) o[it] = gi;

        if (lane == src) {
            k[j1] = 0u;
            if (have2) {
                b1 = b2; j1 = j2; have2 = false;
            } else {
                unsigned n1 = 0, n2 = 0;
                int i1 = 0, i2 = 0;
                #pragma unroll
                for (int j = 0; j < 32; ++j) {
                    unsigned v = k[j];
                    if (v > n1) { n2 = n1; i2 = i1; n1 = v; i1 = j; }
                    else if (v > n2) { n2 = v; i2 = j; }
                }
                b1 = n1; j1 = i1; b2 = n2; j2 = i2; have2 = true;
            }
        }
    }
}

// ---------------- prepare edge weights: [wa ; wb - wa], K-padded ----------------
__global__ void prep_w_kernel(const float* __restrict__ w, float* __restrict__ Wc,
                              int O, int C, int Cpad)
{
    int i = blockIdx.x * blockDim.x + threadIdx.x;
    int tot = 2 * O * Cpad;
    if (i >= tot) return;
    int half = i / (O * Cpad);
    int j = i % (O * Cpad);
    int o = j / Cpad, c = j % Cpad;
    float v = 0.f;
    if (c < C)
        v = half == 0 ? w[o * 2 * C + c]
                      : w[o * 2 * C + C + c] - w[o * 2 * C + c];
    Wc[half * O * Cpad + o * Cpad + c] = v;
}

// ---------------- gather + max_k + BN + LReLU, float4-vectorized ----------------
__global__ void gather_max_bn_kernel(const float* __restrict__ YZ,
                                     const int* __restrict__ idx,
                                     const float* __restrict__ bn,
                                     float* __restrict__ hcat,
                                     int O, int catoff)
{
    int b = blockIdx.y;
    int n0 = blockIdx.x * 8;
    int o4 = threadIdx.x;
    int py = threadIdx.y;
    int n = n0 + py;

    __shared__ int sidx[8][KNN];
    int bw = blockDim.x * 8;
    for (int t = threadIdx.y * blockDim.x + threadIdx.x; t < 8 * KNN; t += bw)
        sidx[t / KNN][t % KNN] = idx[((long long)b * NPTS + n0 + t / KNN) * KNN + t % KNN];
    __syncthreads();

    int ld = 2 * O;
    const float* base = YZ + (long long)b * NPTS * ld;

    float4 zc = *(const float4*)&base[(long long)n * ld + O + o4 * 4];
    float4 mx = make_float4(-INFINITY, -INFINITY, -INFINITY, -INFINITY);
    float4 mn = make_float4(INFINITY, INFINITY, INFINITY, INFINITY);
    #pragma unroll
    for (int kk = 0; kk < KNN; ++kk) {
        float4 y = *(const float4*)&base[(long long)sidx[py][kk] * ld + o4 * 4];
        mx.x = fmaxf(mx.x, y.x); mn.x = fminf(mn.x, y.x);
        mx.y = fmaxf(mx.y, y.y); mn.y = fminf(mn.y, y.y);
        mx.z = fmaxf(mx.z, y.z); mn.z = fminf(mn.z, y.z);
        mx.w = fmaxf(mx.w, y.w); mn.w = fminf(mn.w, y.w);
    }

    float4 g4  = *(const float4*)&bn[o4 * 4];
    float4 be4 = *(const float4*)&bn[O + o4 * 4];
    float4 mu4 = *(const float4*)&bn[2 * O + o4 * 4];
    float4 va4 = *(const float4*)&bn[3 * O + o4 * 4];

    float4 r;
    {
        float s = g4.x * rsqrtf(va4.x + EPSBN);
        float z = (s >= 0.f ? mx.x : mn.x) + zc.x;
        float v = s * z + (be4.x - mu4.x * s);
        r.x = v > 0.f ? v : SLOPE * v;
    }
    {
        float s = g4.y * rsqrtf(va4.y + EPSBN);
        float z = (s >= 0.f ? mx.y : mn.y) + zc.y;
        float v = s * z + (be4.y - mu4.y * s);
        r.y = v > 0.f ? v : SLOPE * v;
    }
    {
        float s = g4.z * rsqrtf(va4.z + EPSBN);
        float z = (s >= 0.f ? mx.z : mn.z) + zc.z;
        float v = s * z + (be4.z - mu4.z * s);
        r.z = v > 0.f ? v : SLOPE * v;
    }
    {
        float s = g4.w * rsqrtf(va4.w + EPSBN);
        float z = (s >= 0.f ? mx.w : mn.w) + zc.w;
        float v = s * z + (be4.w - mu4.w * s);
        r.w = v > 0.f ? v : SLOPE * v;
    }
    *(float4*)&hcat[((long long)b * NPTS + n) * 512 + catoff + o4 * 4] = r;
}

// ---------------- FC layer: warp per (b,o) ----------------
__global__ void fc_kernel(const float* __restrict__ in, const float* __restrict__ W,
                          const float* __restrict__ bn, const float* __restrict__ bias,
                          float* __restrict__ out, int O, int K, int Bn)
{
    int gw = (blockIdx.x * blockDim.x + threadIdx.x) >> 5;
    int lane = threadIdx.x & 31;
    if (gw >= Bn * O) return;
    int b = gw / O, o = gw % O;
    float acc = 0.f;
    const float* ip = in + (long long)b * K;
    const float* wp = W + (long long)o * K;
    for (int k = lane; k < K; k += 32) acc += ip[k] * wp[k];
    #pragma unroll
    for (int off = 16; off > 0; off >>= 1)
        acc += __shfl_down_sync(0xffffffffu, acc, off);
    if (lane == 0) {
        float v = acc;
        if (bn) {
            float g  = bn[o];
            float be = bn[O + o];
            float mu = bn[2 * O + o];
            float va = bn[3 * O + o];
            float s = g * rsqrtf(va + EPSBN);
            v = s * v + (be - mu * s);
            v = v > 0.f ? v : SLOPE * v;
        } else {
            v += bias[o];
        }
        out[(long long)b * O + o] = v;
    }
}

// ---------------- host orchestration ----------------
extern "C" void kernel_launch(void* const* d_in, const int* in_sizes, int n_in,
                              void* d_out, int out_size)
{
    (void)in_sizes; (void)n_in; (void)out_size;
    const float* x   = (const float*)d_in[0];
    const float* w1  = (const float*)d_in[1];
    const float* bn1 = (const float*)d_in[2];
    const float* w2  = (const float*)d_in[3];
    const float* bn2 = (const float*)d_in[4];
    const float* w3  = (const float*)d_in[5];
    const float* bn3 = (const float*)d_in[6];
    const float* w4  = (const float*)d_in[7];
    const float* bn4 = (const float*)d_in[8];
    const float* w5  = (const float*)d_in[9];
    const float* bn5 = (const float*)d_in[10];
    const float* wl1 = (const float*)d_in[11];
    const float* bn6 = (const float*)d_in[12];
    const float* wl2 = (const float*)d_in[13];
    const float* bn7 = (const float*)d_in[14];
    const float* wl3 = (const float*)d_in[15];
    const float* bl3 = (const float*)d_in[16];
    float* out = (float*)d_out;

    float *p_xT, *p_hcat, *p_pd, *p_YZ, *p_W, *p_sq, *p_pmax, *p_psum,
          *p_pool, *p_fc1, *p_fc2;
    int* p_idx;
    cudaGetSymbolAddress((void**)&p_xT,   g_xT);
    cudaGetSymbolAddress((void**)&p_hcat, g_hcat);
    cudaGetSymbolAddress((void**)&p_pd,   g_pd);
    cudaGetSymbolAddress((void**)&p_idx,  g_idx);
    cudaGetSymbolAddress((void**)&p_YZ,   g_YZ);
    cudaGetSymbolAddress((void**)&p_W,    g_W);
    cudaGetSymbolAddress((void**)&p_sq,   g_sq);
    cudaGetSymbolAddress((void**)&p_pmax, g_pmax);
    cudaGetSymbolAddress((void**)&p_psum, g_psum);
    cudaGetSymbolAddress((void**)&p_pool, g_pool);
    cudaGetSymbolAddress((void**)&p_fc1,  g_fc1);
    cudaGetSymbolAddress((void**)&p_fc2,  g_fc2);

    {
        int tot = BATCH * NPTS;
        transpose_x_kernel<<<(tot + 255) / 256, 256>>>(x, p_xT);
    }

    struct Blk { const float* h; int lda, C, Cpad, O; const float* w; const float* bn; int catoff; };
    Blk blks[4] = {
        { p_xT,         8,   3,   8,   64,  w1, bn1, 0   },
        { p_hcat + 0,   512, 64,  64,  64,  w2, bn2, 64  },
        { p_hcat + 64,  512, 64,  64,  128, w3, bn3, 128 },
        { p_hcat + 128, 512, 128, 128, 256, w4, bn4, 256 },
    };

    for (int i = 0; i < 4; ++i) {
        const Blk& B = blks[i];

        {
            int threads = BATCH * NPTS * 32;
            sqnorm_kernel<<<(threads + 255) / 256, 256>>>(B.h, B.lda, B.C, p_sq);
        }
        // pd = 2*G - sq_m - sq_n, symmetric: 36 lower-triangle tiles per batch
        {
            dim3 grid(36, 1, BATCH);
            sgemm_nt_kernel<<<grid, 256>>>(B.h, B.h, p_pd,
                NPTS, NPTS, B.Cpad, B.lda, B.lda, NPTS,
                (long long)NPTS * B.lda, (long long)NPTS * B.lda,
                (long long)NPTS * NPTS, 2, p_sq, 1);
        }
        topk_warp_kernel<<<(BATCH * NPTS) / 8, 256>>>(p_pd, p_idx);
        {
            int tot = 2 * B.O * B.Cpad;
            prep_w_kernel<<<(tot + 255) / 256, 256>>>(B.w, p_W, B.O, B.C, B.Cpad);
        }
        {
            dim3 grid((2 * B.O) / 128, (BATCH * NPTS) / 128, 1);
            sgemm_nt_kernel<<<grid, 256>>>(B.h, p_W, p_YZ,
                BATCH * NPTS, 2 * B.O, B.Cpad, B.lda, B.Cpad, 2 * B.O,
                0, 0, 0, 0, nullptr, 0);
        }
        {
            dim3 blk(B.O / 4, 8);
            gather_max_bn_kernel<<<dim3(NPTS / 8, BATCH), blk>>>(p_YZ, p_idx, B.bn,
                                                                 p_hcat, B.O, B.catoff);
        }
    }

    // conv5 + fused pooling partials
    {
        dim3 grid(8, 128);
        conv5_pool_kernel<<<grid, 256>>>(p_hcat, w5, bn5, p_pmax, p_psum);
    }
    {
        int tot = BATCH * 1024;
        pool_reduce_kernel<<<(tot + 255) / 256, 256>>>(p_pmax, p_psum, p_pool);
    }

    {
        int warps = BATCH * 512;
        fc_kernel<<<(warps * 32 + 255) / 256, 256>>>(p_pool, wl1, bn6, nullptr,
                                                     p_fc1, 512, 2048, BATCH);
    }
    {
        int warps = BATCH * 256;
        fc_kernel<<<(warps * 32 + 255) / 256, 256>>>(p_fc1, wl2, bn7, nullptr,
                                                     p_fc2, 256, 512, BATCH);
    }
    {
        int warps = BATCH * 40;
        fc_kernel<<<(warps * 32 + 255) / 256, 256>>>(p_fc2, wl3, nullptr, bl3,
                                                     out, 40, 256, BATCH);
    }
}

// round 7
// speedup vs baseline: 4.8030x; 1.1478x over previous
#include <cuda_runtime.h>
#include <cmath>

#define BATCH 16
#define NPTS  1024
#define KNN   20
#define EPSBN 1e-5f
#define SLOPE 0.2f

// ---------------- scratch (device globals; no allocations allowed) ----------------
__device__ float g_xT[BATCH * NPTS * 8];
__device__ float g_hcat[BATCH * NPTS * 512];
__device__ float g_pd[(long long)BATCH * NPTS * NPTS];
__device__ int   g_idx[BATCH * NPTS * KNN];
__device__ float g_YZ[BATCH * NPTS * 512];
__device__ float g_W[512 * 128];
__device__ float g_sq[BATCH * NPTS];
__device__ float g_pmax[8 * BATCH * 1024];
__device__ float g_psum[8 * BATCH * 1024];
__device__ float g_pool[BATCH * 2048];
__device__ float g_fc1[BATCH * 512];
__device__ float g_fc2[BATCH * 256];

// ---------------- f32x2 packed helpers ----------------
__device__ __forceinline__ unsigned long long pack2(float lo, float hi)
{
    unsigned long long r;
    asm("mov.b64 %0, {%1, %2};" : "=l"(r) : "f"(lo), "f"(hi));
    return r;
}
__device__ __forceinline__ void ffma2(unsigned long long& acc,
                                      unsigned long long a, unsigned long long b)
{
    asm("fma.rn.f32x2 %0, %1, %2, %0;" : "+l"(acc) : "l"(a), "l"(b));
}
__device__ __forceinline__ float2 unpack2(unsigned long long v)
{
    float lo, hi;
    asm("mov.b64 {%0, %1}, %2;" : "=f"(lo), "=f"(hi) : "l"(v));
    return make_float2(lo, hi);
}

// ---------------- transpose x (B,3,N) -> (B,N,8) zero-padded ----------------
__global__ void transpose_x_kernel(const float* __restrict__ x, float* __restrict__ xT)
{
    int p = blockIdx.x * blockDim.x + threadIdx.x;
    if (p >= BATCH * NPTS) return;
    int b = p / NPTS;
    int n = p % NPTS;
    const float* xb = x + (long long)b * 3 * NPTS + n;
    float4 lo = make_float4(xb[0], xb[NPTS], xb[2 * NPTS], 0.f);
    float4 hi = make_float4(0.f, 0.f, 0.f, 0.f);
    *(float4*)&xT[p * 8]     = lo;
    *(float4*)&xT[p * 8 + 4] = hi;
}

// ---------------- squared norms per point ----------------
__global__ void sqnorm_kernel(const float* __restrict__ h, int lda, int C,
                              float* __restrict__ sq)
{
    int p = (blockIdx.x * blockDim.x + threadIdx.x) >> 5;
    int lane = threadIdx.x & 31;
    if (p >= BATCH * NPTS) return;
    float acc = 0.f;
    for (int c = lane; c < C; c += 32) {
        float v = h[(long long)p * lda + c];
        acc += v * v;
    }
    #pragma unroll
    for (int off = 16; off > 0; off >>= 1)
        acc += __shfl_down_sync(0xffffffffu, acc, off);
    if (lane == 0) sq[p] = acc;
}

// ---------------- 128x128 tiled SGEMM, f32x2 core + reg double buffer -----------
__global__ void __launch_bounds__(256)
sgemm_nt_kernel(const float* __restrict__ A, const float* __restrict__ Bw,
                float* __restrict__ C,
                int M, int Nn, int K, int lda, int ldb, int ldc,
                long long bsA, long long bsB, long long bsC,
                int epi, const float* __restrict__ e0, int sym)
{
    A  += (long long)blockIdx.z * bsA;
    Bw += (long long)blockIdx.z * bsB;
    C  += (long long)blockIdx.z * bsC;

    __shared__ float As[8][128];
    __shared__ float Bs[8][128];

    int tid = threadIdx.x;
    int tx = tid & 15;
    int ty = tid >> 4;

    int bx, by;
    if (sym) {
        int t = blockIdx.x;
        int i = (int)floorf((sqrtf(8.f * t + 1.f) - 1.f) * 0.5f);
        while ((i + 1) * (i + 2) / 2 <= t) ++i;
        while (i * (i + 1) / 2 > t) --i;
        by = i;
        bx = t - i * (i + 1) / 2;
    } else {
        bx = blockIdx.x;
        by = blockIdx.y;
    }

    int l_row = tid >> 1;
    int l_k0  = (tid & 1) * 4;

    const float* aptr = A + (long long)(by * 128 + l_row) * lda + l_k0;
    const float* bptr = Bw + (long long)(bx * 128 + l_row) * ldb + l_k0;

    float4 ra = *(const float4*)aptr;
    float4 rb = *(const float4*)bptr;

    unsigned long long acc2[8][4];
    #pragma unroll
    for (int i = 0; i < 8; ++i)
        #pragma unroll
        for (int j = 0; j < 4; ++j)
            acc2[i][j] = 0ull;

    for (int kt = 0; kt < K; kt += 8) {
        As[l_k0 + 0][l_row] = ra.x;
        As[l_k0 + 1][l_row] = ra.y;
        As[l_k0 + 2][l_row] = ra.z;
        As[l_k0 + 3][l_row] = ra.w;
        Bs[l_k0 + 0][l_row] = rb.x;
        Bs[l_k0 + 1][l_row] = rb.y;
        Bs[l_k0 + 2][l_row] = rb.z;
        Bs[l_k0 + 3][l_row] = rb.w;
        __syncthreads();

        if (kt + 8 < K) {
            ra = *(const float4*)(aptr + kt + 8);
            rb = *(const float4*)(bptr + kt + 8);
        }

        #pragma unroll
        for (int kk = 0; kk < 8; ++kk) {
            float4 a0 = *(const float4*)&As[kk][ty * 8];
            float4 a1 = *(const float4*)&As[kk][ty * 8 + 4];
            float4 b0 = *(const float4*)&Bs[kk][tx * 8];
            float4 b1 = *(const float4*)&Bs[kk][tx * 8 + 4];

            unsigned long long bp[4];
            bp[0] = pack2(b0.x, b0.y);
            bp[1] = pack2(b0.z, b0.w);
            bp[2] = pack2(b1.x, b1.y);
            bp[3] = pack2(b1.z, b1.w);

            float a[8] = {a0.x, a0.y, a0.z, a0.w, a1.x, a1.y, a1.z, a1.w};
            #pragma unroll
            for (int i = 0; i < 8; ++i) {
                unsigned long long ap = pack2(a[i], a[i]);
                #pragma unroll
                for (int j = 0; j < 4; ++j)
                    ffma2(acc2[i][j], ap, bp[j]);
            }
        }
        __syncthreads();
    }

    if (epi == 2) {
        float vals[8][8];
        #pragma unroll
        for (int i = 0; i < 8; ++i) {
            int gm = by * 128 + ty * 8 + i;
            float sqm = e0[blockIdx.z * M + gm];
            #pragma unroll
            for (int jj = 0; jj < 4; ++jj) {
                float2 p = unpack2(acc2[i][jj]);
                int gn0 = bx * 128 + tx * 8 + jj * 2;
                vals[i][jj * 2]     = 2.f * p.x - sqm - e0[blockIdx.z * M + gn0];
                vals[i][jj * 2 + 1] = 2.f * p.y - sqm - e0[blockIdx.z * M + gn0 + 1];
            }
        }
        #pragma unroll
        for (int i = 0; i < 8; ++i) {
            int gm = by * 128 + ty * 8 + i;
            *(float4*)&C[(long long)gm * ldc + bx * 128 + tx * 8]     = *(float4*)&vals[i][0];
            *(float4*)&C[(long long)gm * ldc + bx * 128 + tx * 8 + 4] = *(float4*)&vals[i][4];
        }
        if (sym && bx != by) {
            #pragma unroll
            for (int j = 0; j < 8; ++j) {
                int gn = bx * 128 + tx * 8 + j;
                float4 w0 = make_float4(vals[0][j], vals[1][j], vals[2][j], vals[3][j]);
                float4 w1 = make_float4(vals[4][j], vals[5][j], vals[6][j], vals[7][j]);
                *(float4*)&C[(long long)gn * ldc + by * 128 + ty * 8]     = w0;
                *(float4*)&C[(long long)gn * ldc + by * 128 + ty * 8 + 4] = w1;
            }
        }
        return;
    }

    #pragma unroll
    for (int i = 0; i < 8; ++i) {
        int gm = by * 128 + ty * 8 + i;
        #pragma unroll
        for (int jj = 0; jj < 2; ++jj) {
            float4 v4;
            float* vv = (float*)&v4;
            float2 p0 = unpack2(acc2[i][jj * 2]);
            float2 p1 = unpack2(acc2[i][jj * 2 + 1]);
            float av[4] = {p0.x, p0.y, p1.x, p1.y};
            #pragma unroll
            for (int j = 0; j < 4; ++j) {
                int gn = bx * 128 + tx * 8 + jj * 4 + j;
                float v = av[j];
                if (epi == 1) {
                    float g  = e0[gn];
                    float be = e0[Nn + gn];
                    float mu = e0[2 * Nn + gn];
                    float va = e0[3 * Nn + gn];
                    float s = g * rsqrtf(va + EPSBN);
                    v = s * v + (be - mu * s);
                    v = v > 0.f ? v : SLOPE * v;
                }
                vv[j] = v;
            }
            *(float4*)&C[(long long)gm * ldc + bx * 128 + tx * 8 + jj * 4] = v4;
        }
    }
}

// ---------------- conv5 GEMM with fused BN+LReLU + max/sum pooling --------------
__global__ void __launch_bounds__(256)
conv5_pool_kernel(const float* __restrict__ A, const float* __restrict__ Bw,
                  const float* __restrict__ bn,
                  float* __restrict__ pmax, float* __restrict__ psum)
{
    const int K = 512, lda = 512, ldb = 512;

    __shared__ float As[8][128];
    __shared__ float Bs[8][128];
    __shared__ float redmax[16][128];
    __shared__ float redsum[16][128];

    int tid = threadIdx.x;
    int tx = tid & 15;
    int ty = tid >> 4;
    int bx = blockIdx.x, by = blockIdx.y;

    int l_row = tid >> 1;
    int l_k0  = (tid & 1) * 4;

    const float* aptr = A + (long long)(by * 128 + l_row) * lda + l_k0;
    const float* bptr = Bw + (long long)(bx * 128 + l_row) * ldb + l_k0;

    float4 ra = *(const float4*)aptr;
    float4 rb = *(const float4*)bptr;

    unsigned long long acc2[8][4];
    #pragma unroll
    for (int i = 0; i < 8; ++i)
        #pragma unroll
        for (int j = 0; j < 4; ++j)
            acc2[i][j] = 0ull;

    for (int kt = 0; kt < K; kt += 8) {
        As[l_k0 + 0][l_row] = ra.x;
        As[l_k0 + 1][l_row] = ra.y;
        As[l_k0 + 2][l_row] = ra.z;
        As[l_k0 + 3][l_row] = ra.w;
        Bs[l_k0 + 0][l_row] = rb.x;
        Bs[l_k0 + 1][l_row] = rb.y;
        Bs[l_k0 + 2][l_row] = rb.z;
        Bs[l_k0 + 3][l_row] = rb.w;
        __syncthreads();

        if (kt + 8 < K) {
            ra = *(const float4*)(aptr + kt + 8);
            rb = *(const float4*)(bptr + kt + 8);
        }

        #pragma unroll
        for (int kk = 0; kk < 8; ++kk) {
            float4 a0 = *(const float4*)&As[kk][ty * 8];
            float4 a1 = *(const float4*)&As[kk][ty * 8 + 4];
            float4 b0 = *(const float4*)&Bs[kk][tx * 8];
            float4 b1 = *(const float4*)&Bs[kk][tx * 8 + 4];

            unsigned long long bp[4];
            bp[0] = pack2(b0.x, b0.y);
            bp[1] = pack2(b0.z, b0.w);
            bp[2] = pack2(b1.x, b1.y);
            bp[3] = pack2(b1.z, b1.w);

            float a[8] = {a0.x, a0.y, a0.z, a0.w, a1.x, a1.y, a1.z, a1.w};
            #pragma unroll
            for (int i = 0; i < 8; ++i) {
                unsigned long long ap = pack2(a[i], a[i]);
                #pragma unroll
                for (int j = 0; j < 4; ++j)
                    ffma2(acc2[i][j], ap, bp[j]);
            }
        }
        __syncthreads();
    }

    float s8[8], o8[8];
    #pragma unroll
    for (int jc = 0; jc < 8; ++jc) {
        int gn = bx * 128 + tx * 8 + jc;
        float g  = bn[gn];
        float be = bn[1024 + gn];
        float mu = bn[2 * 1024 + gn];
        float va = bn[3 * 1024 + gn];
        float s = g * rsqrtf(va + EPSBN);
        s8[jc] = s;
        o8[jc] = be - mu * s;
    }

    float cmax[8], csum[8];
    #pragma unroll
    for (int jc = 0; jc < 8; ++jc) { cmax[jc] = -INFINITY; csum[jc] = 0.f; }

    #pragma unroll
    for (int i = 0; i < 8; ++i) {
        #pragma unroll
        for (int jj = 0; jj < 4; ++jj) {
            float2 p = unpack2(acc2[i][jj]);
            float v0 = s8[jj * 2] * p.x + o8[jj * 2];
            v0 = v0 > 0.f ? v0 : SLOPE * v0;
            float v1 = s8[jj * 2 + 1] * p.y + o8[jj * 2 + 1];
            v1 = v1 > 0.f ? v1 : SLOPE * v1;
            cmax[jj * 2]     = fmaxf(cmax[jj * 2], v0);
            csum[jj * 2]    += v0;
            cmax[jj * 2 + 1] = fmaxf(cmax[jj * 2 + 1], v1);
            csum[jj * 2 + 1] += v1;
        }
    }

    #pragma unroll
    for (int jc = 0; jc < 8; ++jc) {
        redmax[ty][tx * 8 + jc] = cmax[jc];
        redsum[ty][tx * 8 + jc] = csum[jc];
    }
    __syncthreads();

    if (tid < 128) {
        int c = tid;
        float mx = -INFINITY, sm = 0.f;
        #pragma unroll
        for (int t = 0; t < 16; ++t) {
            mx = fmaxf(mx, redmax[t][c]);
            sm += redsum[t][c];
        }
        int b = by >> 3, chunk = by & 7;
        pmax[((long long)chunk * BATCH + b) * 1024 + bx * 128 + c] = mx;
        psum[((long long)chunk * BATCH + b) * 1024 + bx * 128 + c] = sm;
    }
}

// ---------------- final pool reduce over 8 chunks ----------------
__global__ void pool_reduce_kernel(const float* __restrict__ pmax,
                                   const float* __restrict__ psum,
                                   float* __restrict__ pool)
{
    int gi = blockIdx.x * blockDim.x + threadIdx.x;
    if (gi >= BATCH * 1024) return;
    int b = gi >> 10;
    int c = gi & 1023;
    float mx = -INFINITY, sm = 0.f;
    #pragma unroll
    for (int chunk = 0; chunk < 8; ++chunk) {
        mx = fmaxf(mx, pmax[((long long)chunk * BATCH + b) * 1024 + c]);
        sm += psum[((long long)chunk * BATCH + b) * 1024 + c];
    }
    pool[b * 2048 + c] = mx;
    pool[b * 2048 + 1024 + c] = sm * (1.f / (float)NPTS);
}

// ---------------- warp-per-row top-k (k=20), REDUX + sorted top-4 cache ---------
__global__ void __launch_bounds__(256) topk_warp_kernel(const float* __restrict__ pd,
                                                        int* __restrict__ out)
{
    int warp_in_blk = threadIdx.x >> 5;
    int lane = threadIdx.x & 31;
    int row = blockIdx.x * 8 + warp_in_blk;

    const float* __restrict__ p = pd + (long long)row * NPTS;

    unsigned k[32];
    #pragma unroll
    for (int j = 0; j < 32; ++j) {
        unsigned u = __float_as_uint(p[j * 32 + lane]);
        k[j] = (u & 0x80000000u) ? ~u : (u | 0x80000000u);
    }

    // sorted top-4 cache: c0 >= c1 >= c2 >= c3 (ties keep lower index first)
    unsigned c0 = 0, c1 = 0, c2 = 0, c3 = 0;
    int i0 = 0, i1 = 0, i2 = 0, i3 = 0;
    #pragma unroll
    for (int j = 0; j < 32; ++j) {
        unsigned v = k[j];
        if (v > c3) {
            if (v > c2) {
                if (v > c1) {
                    if (v > c0) { c3=c2;i3=i2; c2=c1;i2=i1; c1=c0;i1=i0; c0=v;i0=j; }
                    else        { c3=c2;i3=i2; c2=c1;i2=i1; c1=v;i1=j; }
                } else          { c3=c2;i3=i2; c2=v;i2=j; }
            } else              { c3=v;i3=j; }
        }
    }

    int* __restrict__ o = out + (long long)row * KNN;

    #pragma unroll 1
    for (int it = 0; it < KNN; ++it) {
        unsigned m = __reduce_max_sync(0xffffffffu, c0);
        unsigned bal = __ballot_sync(0xffffffffu, c0 == m);
        int src = __ffs((int)bal) - 1;
        int gi = __shfl_sync(0xffffffffu, (i0 << 5) | lane, src);
        if (lane == 0) o[it] = gi;

        if (lane == src) {
            k[i0] = 0u;                          // consume
            c0 = c1; i0 = i1;                    // pop cache
            c1 = c2; i1 = i2;
            c2 = c3; i2 = i3;
            c3 = 0;  i3 = 0;
            if (c0 == 0u) {                      // cache drained (rare): rebuild
                #pragma unroll
                for (int j = 0; j < 32; ++j) {
                    unsigned v = k[j];
                    if (v > c3) {
                        if (v > c2) {
                            if (v > c1) {
                                if (v > c0) { c3=c2;i3=i2; c2=c1;i2=i1; c1=c0;i1=i0; c0=v;i0=j; }
                                else        { c3=c2;i3=i2; c2=c1;i2=i1; c1=v;i1=j; }
                            } else          { c3=c2;i3=i2; c2=v;i2=j; }
                        } else              { c3=v;i3=j; }
                    }
                }
            }
        }
    }
}

// ---------------- prepare edge weights: [wa ; wb - wa], K-padded ----------------
__global__ void prep_w_kernel(const float* __restrict__ w, float* __restrict__ Wc,
                              int O, int C, int Cpad)
{
    int i = blockIdx.x * blockDim.x + threadIdx.x;
    int tot = 2 * O * Cpad;
    if (i >= tot) return;
    int half = i / (O * Cpad);
    int j = i % (O * Cpad);
    int o = j / Cpad, c = j % Cpad;
    float v = 0.f;
    if (c < C)
        v = half == 0 ? w[o * 2 * C + c]
                      : w[o * 2 * C + C + c] - w[o * 2 * C + c];
    Wc[half * O * Cpad + o * Cpad + c] = v;
}

// ---------------- gather + max_k + BN + LReLU, float4-vectorized ----------------
__global__ void gather_max_bn_kernel(const float* __restrict__ YZ,
                                     const int* __restrict__ idx,
                                     const float* __restrict__ bn,
                                     float* __restrict__ hcat,
                                     int O, int catoff)
{
    int b = blockIdx.y;
    int n0 = blockIdx.x * 8;
    int o4 = threadIdx.x;
    int py = threadIdx.y;
    int n = n0 + py;

    __shared__ int sidx[8][KNN];
    int bw = blockDim.x * 8;
    for (int t = threadIdx.y * blockDim.x + threadIdx.x; t < 8 * KNN; t += bw)
        sidx[t / KNN][t % KNN] = idx[((long long)b * NPTS + n0 + t / KNN) * KNN + t % KNN];
    __syncthreads();

    int ld = 2 * O;
    const float* base = YZ + (long long)b * NPTS * ld;

    float4 zc = *(const float4*)&base[(long long)n * ld + O + o4 * 4];
    float4 mx = make_float4(-INFINITY, -INFINITY, -INFINITY, -INFINITY);
    float4 mn = make_float4(INFINITY, INFINITY, INFINITY, INFINITY);
    #pragma unroll
    for (int kk = 0; kk < KNN; ++kk) {
        float4 y = *(const float4*)&base[(long long)sidx[py][kk] * ld + o4 * 4];
        mx.x = fmaxf(mx.x, y.x); mn.x = fminf(mn.x, y.x);
        mx.y = fmaxf(mx.y, y.y); mn.y = fminf(mn.y, y.y);
        mx.z = fmaxf(mx.z, y.z); mn.z = fminf(mn.z, y.z);
        mx.w = fmaxf(mx.w, y.w); mn.w = fminf(mn.w, y.w);
    }

    float4 g4  = *(const float4*)&bn[o4 * 4];
    float4 be4 = *(const float4*)&bn[O + o4 * 4];
    float4 mu4 = *(const float4*)&bn[2 * O + o4 * 4];
    float4 va4 = *(const float4*)&bn[3 * O + o4 * 4];

    float4 r;
    {
        float s = g4.x * rsqrtf(va4.x + EPSBN);
        float z = (s >= 0.f ? mx.x : mn.x) + zc.x;
        float v = s * z + (be4.x - mu4.x * s);
        r.x = v > 0.f ? v : SLOPE * v;
    }
    {
        float s = g4.y * rsqrtf(va4.y + EPSBN);
        float z = (s >= 0.f ? mx.y : mn.y) + zc.y;
        float v = s * z + (be4.y - mu4.y * s);
        r.y = v > 0.f ? v : SLOPE * v;
    }
    {
        float s = g4.z * rsqrtf(va4.z + EPSBN);
        float z = (s >= 0.f ? mx.z : mn.z) + zc.z;
        float v = s * z + (be4.z - mu4.z * s);
        r.z = v > 0.f ? v : SLOPE * v;
    }
    {
        float s = g4.w * rsqrtf(va4.w + EPSBN);
        float z = (s >= 0.f ? mx.w : mn.w) + zc.w;
        float v = s * z + (be4.w - mu4.w * s);
        r.w = v > 0.f ? v : SLOPE * v;
    }
    *(float4*)&hcat[((long long)b * NPTS + n) * 512 + catoff + o4 * 4] = r;
}

// ---------------- FC layer: warp per (b,o) ----------------
__global__ void fc_kernel(const float* __restrict__ in, const float* __restrict__ W,
                          const float* __restrict__ bn, const float* __restrict__ bias,
                          float* __restrict__ out, int O, int K, int Bn)
{
    int gw = (blockIdx.x * blockDim.x + threadIdx.x) >> 5;
    int lane = threadIdx.x & 31;
    if (gw >= Bn * O) return;
    int b = gw / O, o = gw % O;
    float acc = 0.f;
    const float* ip = in + (long long)b * K;
    const float* wp = W + (long long)o * K;
    for (int k = lane; k < K; k += 32) acc += ip[k] * wp[k];
    #pragma unroll
    for (int off = 16; off > 0; off >>= 1)
        acc += __shfl_down_sync(0xffffffffu, acc, off);
    if (lane == 0) {
        float v = acc;
        if (bn) {
            float g  = bn[o];
            float be = bn[O + o];
            float mu = bn[2 * O + o];
            float va = bn[3 * O + o];
            float s = g * rsqrtf(va + EPSBN);
            v = s * v + (be - mu * s);
            v = v > 0.f ? v : SLOPE * v;
        } else {
            v += bias[o];
        }
        out[(long long)b * O + o] = v;
    }
}

// ---------------- host orchestration ----------------
extern "C" void kernel_launch(void* const* d_in, const int* in_sizes, int n_in,
                              void* d_out, int out_size)
{
    (void)in_sizes; (void)n_in; (void)out_size;
    const float* x   = (const float*)d_in[0];
    const float* w1  = (const float*)d_in[1];
    const float* bn1 = (const float*)d_in[2];
    const float* w2  = (const float*)d_in[3];
    const float* bn2 = (const float*)d_in[4];
    const float* w3  = (const float*)d_in[5];
    const float* bn3 = (const float*)d_in[6];
    const float* w4  = (const float*)d_in[7];
    const float* bn4 = (const float*)d_in[8];
    const float* w5  = (const float*)d_in[9];
    const float* bn5 = (const float*)d_in[10];
    const float* wl1 = (const float*)d_in[11];
    const float* bn6 = (const float*)d_in[12];
    const float* wl2 = (const float*)d_in[13];
    const float* bn7 = (const float*)d_in[14];
    const float* wl3 = (const float*)d_in[15];
    const float* bl3 = (const float*)d_in[16];
    float* out = (float*)d_out;

    float *p_xT, *p_hcat, *p_pd, *p_YZ, *p_W, *p_sq, *p_pmax, *p_psum,
          *p_pool, *p_fc1, *p_fc2;
    int* p_idx;
    cudaGetSymbolAddress((void**)&p_xT,   g_xT);
    cudaGetSymbolAddress((void**)&p_hcat, g_hcat);
    cudaGetSymbolAddress((void**)&p_pd,   g_pd);
    cudaGetSymbolAddress((void**)&p_idx,  g_idx);
    cudaGetSymbolAddress((void**)&p_YZ,   g_YZ);
    cudaGetSymbolAddress((void**)&p_W,    g_W);
    cudaGetSymbolAddress((void**)&p_sq,   g_sq);
    cudaGetSymbolAddress((void**)&p_pmax, g_pmax);
    cudaGetSymbolAddress((void**)&p_psum, g_psum);
    cudaGetSymbolAddress((void**)&p_pool, g_pool);
    cudaGetSymbolAddress((void**)&p_fc1,  g_fc1);
    cudaGetSymbolAddress((void**)&p_fc2,  g_fc2);

    // lazy one-time host objects for cross-stream overlap (identical GPU work
    // on every call; stream/event creation is host-side only)
    static cudaStream_t s_side = nullptr;
    static cudaEvent_t evf[4], evj[4];
    if (!s_side) {
        cudaStreamCreateWithFlags(&s_side, cudaStreamNonBlocking);
        for (int i = 0; i < 4; ++i) {
            cudaEventCreateWithFlags(&evf[i], cudaEventDisableTiming);
            cudaEventCreateWithFlags(&evj[i], cudaEventDisableTiming);
        }
    }

    {
        int tot = BATCH * NPTS;
        transpose_x_kernel<<<(tot + 255) / 256, 256>>>(x, p_xT);
    }

    struct Blk { const float* h; int lda, C, Cpad, O; const float* w; const float* bn; int catoff; };
    Blk blks[4] = {
        { p_xT,         8,   3,   8,   64,  w1, bn1, 0   },
        { p_hcat + 0,   512, 64,  64,  64,  w2, bn2, 64  },
        { p_hcat + 64,  512, 64,  64,  128, w3, bn3, 128 },
        { p_hcat + 128, 512, 128, 128, 256, w4, bn4, 256 },
    };

    for (int i = 0; i < 4; ++i) {
        const Blk& B = blks[i];

        {
            int threads = BATCH * NPTS * 32;
            sqnorm_kernel<<<(threads + 255) / 256, 256>>>(B.h, B.lda, B.C, p_sq);
        }

        // fork: side stream does prep_w + YZ GEMM while main does pd + topk
        cudaEventRecord(evf[i], 0);
        cudaStreamWaitEvent(s_side, evf[i], 0);
        {
            int tot = 2 * B.O * B.Cpad;
            prep_w_kernel<<<(tot + 255) / 256, 256, 0, s_side>>>(B.w, p_W, B.O, B.C, B.Cpad);
            dim3 grid((2 * B.O) / 128, (BATCH * NPTS) / 128, 1);
            sgemm_nt_kernel<<<grid, 256, 0, s_side>>>(B.h, p_W, p_YZ,
                BATCH * NPTS, 2 * B.O, B.Cpad, B.lda, B.Cpad, 2 * B.O,
                0, 0, 0, 0, nullptr, 0);
            cudaEventRecord(evj[i], s_side);
        }

        // main: pd (symmetric) + topk
        {
            dim3 grid(36, 1, BATCH);
            sgemm_nt_kernel<<<grid, 256>>>(B.h, B.h, p_pd,
                NPTS, NPTS, B.Cpad, B.lda, B.lda, NPTS,
                (long long)NPTS * B.lda, (long long)NPTS * B.lda,
                (long long)NPTS * NPTS, 2, p_sq, 1);
        }
        topk_warp_kernel<<<(BATCH * NPTS) / 8, 256>>>(p_pd, p_idx);

        // join, then gather
        cudaStreamWaitEvent(0, evj[i], 0);
        {
            dim3 blk(B.O / 4, 8);
            gather_max_bn_kernel<<<dim3(NPTS / 8, BATCH), blk>>>(p_YZ, p_idx, B.bn,
                                                                 p_hcat, B.O, B.catoff);
        }
    }

    // conv5 + fused pooling partials
    {
        dim3 grid(8, 128);
        conv5_pool_kernel<<<grid, 256>>>(p_hcat, w5, bn5, p_pmax, p_psum);
    }
    {
        int tot = BATCH * 1024;
        pool_reduce_kernel<<<(tot + 255) / 256, 256>>>(p_pmax, p_psum, p_pool);
    }

    {
        int warps = BATCH * 512;
        fc_kernel<<<(warps * 32 + 255) / 256, 256>>>(p_pool, wl1, bn6, nullptr,
                                                     p_fc1, 512, 2048, BATCH);
    }
    {
        int warps = BATCH * 256;
        fc_kernel<<<(warps * 32 + 255) / 256, 256>>>(p_fc1, wl2, bn7, nullptr,
                                                     p_fc2, 256, 512, BATCH);
    }
    {
        int warps = BATCH * 40;
        fc_kernel<<<(warps * 32 + 255) / 256, 256>>>(p_fc2, wl3, nullptr, bl3,
                                                     out, 40, 256, BATCH);
    }
}

// round 8
// speedup vs baseline: 5.9261x; 1.2338x over previous
#include <cuda_runtime.h>
#include <cuda_bf16.h>
#include <cmath>

#define BATCH 16
#define NPTS  1024
#define KNN   20
#define EPSBN 1e-5f
#define SLOPE 0.2f

// ---------------- scratch (device globals; no allocations allowed) ----------------
__device__ float g_xT[BATCH * NPTS * 8];
__device__ float g_hcat[BATCH * NPTS * 512];
__device__ float g_pd[(long long)BATCH * NPTS * NPTS];
__device__ int   g_idx[BATCH * NPTS * KNN];
__device__ float g_YZ[BATCH * NPTS * 512];
__device__ float g_W[512 * 128];
__device__ float g_sq[BATCH * NPTS];
__device__ float g_pmax[8 * BATCH * 1024];
__device__ float g_psum[8 * BATCH * 1024];
__device__ float g_pool[BATCH * 2048];
__device__ float g_fc1[BATCH * 512];
__device__ float g_fc2[BATCH * 256];
// split-bf16 operands for conv5
__device__ unsigned short g_Ahi[BATCH * NPTS * 512];
__device__ unsigned short g_Alo[BATCH * NPTS * 512];
__device__ unsigned short g_Bhi[1024 * 512];
__device__ unsigned short g_Blo[1024 * 512];

// ---------------- f32x2 packed helpers ----------------
__device__ __forceinline__ unsigned long long pack2(float lo, float hi)
{
    unsigned long long r;
    asm("mov.b64 %0, {%1, %2};" : "=l"(r) : "f"(lo), "f"(hi));
    return r;
}
__device__ __forceinline__ void ffma2(unsigned long long& acc,
                                      unsigned long long a, unsigned long long b)
{
    asm("fma.rn.f32x2 %0, %1, %2, %0;" : "+l"(acc) : "l"(a), "l"(b));
}
__device__ __forceinline__ float2 unpack2(unsigned long long v)
{
    float lo, hi;
    asm("mov.b64 {%0, %1}, %2;" : "=f"(lo), "=f"(hi) : "l"(v));
    return make_float2(lo, hi);
}

__device__ __forceinline__ void mma_bf16(float* d, const unsigned* a, const unsigned* b)
{
    asm volatile(
        "mma.sync.aligned.m16n8k16.row.col.f32.bf16.bf16.f32 "
        "{%0,%1,%2,%3}, {%4,%5,%6,%7}, {%8,%9}, {%0,%1,%2,%3};"
        : "+f"(d[0]), "+f"(d[1]), "+f"(d[2]), "+f"(d[3])
        : "r"(a[0]), "r"(a[1]), "r"(a[2]), "r"(a[3]), "r"(b[0]), "r"(b[1]));
}

// ---------------- transpose x (B,3,N) -> (B,N,8) zero-padded ----------------
__global__ void transpose_x_kernel(const float* __restrict__ x, float* __restrict__ xT)
{
    int p = blockIdx.x * blockDim.x + threadIdx.x;
    if (p >= BATCH * NPTS) return;
    int b = p / NPTS;
    int n = p % NPTS;
    const float* xb = x + (long long)b * 3 * NPTS + n;
    float4 lo = make_float4(xb[0], xb[NPTS], xb[2 * NPTS], 0.f);
    float4 hi = make_float4(0.f, 0.f, 0.f, 0.f);
    *(float4*)&xT[p * 8]     = lo;
    *(float4*)&xT[p * 8 + 4] = hi;
}

// ---------------- squared norms per point ----------------
__global__ void sqnorm_kernel(const float* __restrict__ h, int lda, int C,
                              float* __restrict__ sq)
{
    int p = (blockIdx.x * blockDim.x + threadIdx.x) >> 5;
    int lane = threadIdx.x & 31;
    if (p >= BATCH * NPTS) return;
    float acc = 0.f;
    for (int c = lane; c < C; c += 32) {
        float v = h[(long long)p * lda + c];
        acc += v * v;
    }
    #pragma unroll
    for (int off = 16; off > 0; off >>= 1)
        acc += __shfl_down_sync(0xffffffffu, acc, off);
    if (lane == 0) sq[p] = acc;
}

// ---------------- fp32 -> (hi, lo) bf16 split, float4-vectorized ----------------
__global__ void cvt_split4_kernel(const float* __restrict__ in,
                                  unsigned short* __restrict__ hi,
                                  unsigned short* __restrict__ lo, int n4)
{
    int i = blockIdx.x * blockDim.x + threadIdx.x;
    if (i >= n4) return;
    float4 v = ((const float4*)in)[i];
    __nv_bfloat16 h0 = __float2bfloat16_rn(v.x);
    __nv_bfloat16 h1 = __float2bfloat16_rn(v.y);
    __nv_bfloat16 h2 = __float2bfloat16_rn(v.z);
    __nv_bfloat16 h3 = __float2bfloat16_rn(v.w);
    __nv_bfloat16 l0 = __float2bfloat16_rn(v.x - __bfloat162float(h0));
    __nv_bfloat16 l1 = __float2bfloat16_rn(v.y - __bfloat162float(h1));
    __nv_bfloat16 l2 = __float2bfloat16_rn(v.z - __bfloat162float(h2));
    __nv_bfloat16 l3 = __float2bfloat16_rn(v.w - __bfloat162float(h3));
    __nv_bfloat162* hp = (__nv_bfloat162*)(hi + i * 4);
    __nv_bfloat162* lp = (__nv_bfloat162*)(lo + i * 4);
    hp[0] = __nv_bfloat162(h0, h1);
    hp[1] = __nv_bfloat162(h2, h3);
    lp[0] = __nv_bfloat162(l0, l1);
    lp[1] = __nv_bfloat162(l2, l3);
}

// ---------------- 128x128 tiled SGEMM, f32x2 core + reg double buffer -----------
__global__ void __launch_bounds__(256)
sgemm_nt_kernel(const float* __restrict__ A, const float* __restrict__ Bw,
                float* __restrict__ C,
                int M, int Nn, int K, int lda, int ldb, int ldc,
                long long bsA, long long bsB, long long bsC,
                int epi, const float* __restrict__ e0, int sym)
{
    A  += (long long)blockIdx.z * bsA;
    Bw += (long long)blockIdx.z * bsB;
    C  += (long long)blockIdx.z * bsC;

    __shared__ float As[8][128];
    __shared__ float Bs[8][128];

    int tid = threadIdx.x;
    int tx = tid & 15;
    int ty = tid >> 4;

    int bx, by;
    if (sym) {
        int t = blockIdx.x;
        int i = (int)floorf((sqrtf(8.f * t + 1.f) - 1.f) * 0.5f);
        while ((i + 1) * (i + 2) / 2 <= t) ++i;
        while (i * (i + 1) / 2 > t) --i;
        by = i;
        bx = t - i * (i + 1) / 2;
    } else {
        bx = blockIdx.x;
        by = blockIdx.y;
    }

    int l_row = tid >> 1;
    int l_k0  = (tid & 1) * 4;

    const float* aptr = A + (long long)(by * 128 + l_row) * lda + l_k0;
    const float* bptr = Bw + (long long)(bx * 128 + l_row) * ldb + l_k0;

    float4 ra = *(const float4*)aptr;
    float4 rb = *(const float4*)bptr;

    unsigned long long acc2[8][4];
    #pragma unroll
    for (int i = 0; i < 8; ++i)
        #pragma unroll
        for (int j = 0; j < 4; ++j)
            acc2[i][j] = 0ull;

    for (int kt = 0; kt < K; kt += 8) {
        As[l_k0 + 0][l_row] = ra.x;
        As[l_k0 + 1][l_row] = ra.y;
        As[l_k0 + 2][l_row] = ra.z;
        As[l_k0 + 3][l_row] = ra.w;
        Bs[l_k0 + 0][l_row] = rb.x;
        Bs[l_k0 + 1][l_row] = rb.y;
        Bs[l_k0 + 2][l_row] = rb.z;
        Bs[l_k0 + 3][l_row] = rb.w;
        __syncthreads();

        if (kt + 8 < K) {
            ra = *(const float4*)(aptr + kt + 8);
            rb = *(const float4*)(bptr + kt + 8);
        }

        #pragma unroll
        for (int kk = 0; kk < 8; ++kk) {
            float4 a0 = *(const float4*)&As[kk][ty * 8];
            float4 a1 = *(const float4*)&As[kk][ty * 8 + 4];
            float4 b0 = *(const float4*)&Bs[kk][tx * 8];
            float4 b1 = *(const float4*)&Bs[kk][tx * 8 + 4];

            unsigned long long bp[4];
            bp[0] = pack2(b0.x, b0.y);
            bp[1] = pack2(b0.z, b0.w);
            bp[2] = pack2(b1.x, b1.y);
            bp[3] = pack2(b1.z, b1.w);

            float a[8] = {a0.x, a0.y, a0.z, a0.w, a1.x, a1.y, a1.z, a1.w};
            #pragma unroll
            for (int i = 0; i < 8; ++i) {
                unsigned long long ap = pack2(a[i], a[i]);
                #pragma unroll
                for (int j = 0; j < 4; ++j)
                    ffma2(acc2[i][j], ap, bp[j]);
            }
        }
        __syncthreads();
    }

    if (epi == 2) {
        float vals[8][8];
        #pragma unroll
        for (int i = 0; i < 8; ++i) {
            int gm = by * 128 + ty * 8 + i;
            float sqm = e0[blockIdx.z * M + gm];
            #pragma unroll
            for (int jj = 0; jj < 4; ++jj) {
                float2 p = unpack2(acc2[i][jj]);
                int gn0 = bx * 128 + tx * 8 + jj * 2;
                vals[i][jj * 2]     = 2.f * p.x - sqm - e0[blockIdx.z * M + gn0];
                vals[i][jj * 2 + 1] = 2.f * p.y - sqm - e0[blockIdx.z * M + gn0 + 1];
            }
        }
        #pragma unroll
        for (int i = 0; i < 8; ++i) {
            int gm = by * 128 + ty * 8 + i;
            *(float4*)&C[(long long)gm * ldc + bx * 128 + tx * 8]     = *(float4*)&vals[i][0];
            *(float4*)&C[(long long)gm * ldc + bx * 128 + tx * 8 + 4] = *(float4*)&vals[i][4];
        }
        if (sym && bx != by) {
            #pragma unroll
            for (int j = 0; j < 8; ++j) {
                int gn = bx * 128 + tx * 8 + j;
                float4 w0 = make_float4(vals[0][j], vals[1][j], vals[2][j], vals[3][j]);
                float4 w1 = make_float4(vals[4][j], vals[5][j], vals[6][j], vals[7][j]);
                *(float4*)&C[(long long)gn * ldc + by * 128 + ty * 8]     = w0;
                *(float4*)&C[(long long)gn * ldc + by * 128 + ty * 8 + 4] = w1;
            }
        }
        return;
    }

    #pragma unroll
    for (int i = 0; i < 8; ++i) {
        int gm = by * 128 + ty * 8 + i;
        #pragma unroll
        for (int jj = 0; jj < 2; ++jj) {
            float4 v4;
            float* vv = (float*)&v4;
            float2 p0 = unpack2(acc2[i][jj * 2]);
            float2 p1 = unpack2(acc2[i][jj * 2 + 1]);
            float av[4] = {p0.x, p0.y, p1.x, p1.y};
            #pragma unroll
            for (int j = 0; j < 4; ++j) {
                int gn = bx * 128 + tx * 8 + jj * 4 + j;
                float v = av[j];
                if (epi == 1) {
                    float g  = e0[gn];
                    float be = e0[Nn + gn];
                    float mu = e0[2 * Nn + gn];
                    float va = e0[3 * Nn + gn];
                    float s = g * rsqrtf(va + EPSBN);
                    v = s * v + (be - mu * s);
                    v = v > 0.f ? v : SLOPE * v;
                }
                vv[j] = v;
            }
            *(float4*)&C[(long long)gm * ldc + bx * 128 + tx * 8 + jj * 4] = v4;
        }
    }
}

// ---------------- conv5 split-bf16 MMA + fused BN/LReLU + pooling ---------------
// A = hcat split (16384 x 512), B = w5 split (1024 x 512). Grid (8, 128).
// 8 warps: wm = w&1 (64-row half), wn = w>>1 (32-col quarter). kTile = 32.
__global__ void __launch_bounds__(256)
conv5_mma_kernel(const unsigned short* __restrict__ Ahi, const unsigned short* __restrict__ Alo,
                 const unsigned short* __restrict__ Bhi, const unsigned short* __restrict__ Blo,
                 const float* __restrict__ bn,
                 float* __restrict__ pmax, float* __restrict__ psum)
{
    __shared__ __align__(16) union SM {
        struct { unsigned ah[128 * 20], al[128 * 20], bh[128 * 20], bl[128 * 20]; } t;
        struct { float rmax[2][128]; float rsum[2][128]; } r;
    } sm;

    int tid = threadIdx.x;
    int lane = tid & 31;
    int w = tid >> 5;
    int wm = w & 1, wn = w >> 1;
    int gr = lane >> 2, tig = lane & 3;
    int bx = blockIdx.x, by = blockIdx.y;

    // global load mapping: thread -> (row, 2 quads of 8 bf16)
    int l_row = tid >> 1;
    int q0 = (tid & 1) * 2;
    long long a_base = (long long)(by * 128 + l_row) * 512;
    long long b_base = (long long)(bx * 128 + l_row) * 512;

    uint4 pa_h[2], pa_l[2], pb_h[2], pb_l[2];
    #pragma unroll
    for (int q = 0; q < 2; ++q) {
        pa_h[q] = *(const uint4*)(Ahi + a_base + (q0 + q) * 8);
        pa_l[q] = *(const uint4*)(Alo + a_base + (q0 + q) * 8);
        pb_h[q] = *(const uint4*)(Bhi + b_base + (q0 + q) * 8);
        pb_l[q] = *(const uint4*)(Blo + b_base + (q0 + q) * 8);
    }

    float acc[4][4][4];
    #pragma unroll
    for (int mt = 0; mt < 4; ++mt)
        #pragma unroll
        for (int nt = 0; nt < 4; ++nt)
            #pragma unroll
            for (int c = 0; c < 4; ++c)
                acc[mt][nt][c] = 0.f;

    for (int kt = 0; kt < 16; ++kt) {
        #pragma unroll
        for (int q = 0; q < 2; ++q) {
            *(uint4*)&sm.t.ah[l_row * 20 + (q0 + q) * 4] = pa_h[q];
            *(uint4*)&sm.t.al[l_row * 20 + (q0 + q) * 4] = pa_l[q];
            *(uint4*)&sm.t.bh[l_row * 20 + (q0 + q) * 4] = pb_h[q];
            *(uint4*)&sm.t.bl[l_row * 20 + (q0 + q) * 4] = pb_l[q];
        }
        __syncthreads();

        if (kt + 1 < 16) {
            long long koff = (long long)(kt + 1) * 32;
            #pragma unroll
            for (int q = 0; q < 2; ++q) {
                pa_h[q] = *(const uint4*)(Ahi + a_base + koff + (q0 + q) * 8);
                pa_l[q] = *(const uint4*)(Alo + a_base + koff + (q0 + q) * 8);
                pb_h[q] = *(const uint4*)(Bhi + b_base + koff + (q0 + q) * 8);
                pb_l[q] = *(const uint4*)(Blo + b_base + koff + (q0 + q) * 8);
            }
        }

        #pragma unroll
        for (int s = 0; s < 2; ++s) {
            unsigned ahf[4][4], alf[4][4];
            #pragma unroll
            for (int mt = 0; mt < 4; ++mt) {
                int r0 = wm * 64 + mt * 16 + gr;
                int p = s * 8 + tig;
                ahf[mt][0] = sm.t.ah[r0 * 20 + p];
                ahf[mt][1] = sm.t.ah[(r0 + 8) * 20 + p];
                ahf[mt][2] = sm.t.ah[r0 * 20 + p + 4];
                ahf[mt][3] = sm.t.ah[(r0 + 8) * 20 + p + 4];
                alf[mt][0] = sm.t.al[r0 * 20 + p];
                alf[mt][1] = sm.t.al[(r0 + 8) * 20 + p];
                alf[mt][2] = sm.t.al[r0 * 20 + p + 4];
                alf[mt][3] = sm.t.al[(r0 + 8) * 20 + p + 4];
            }
            unsigned bhf[4][2], blf[4][2];
            #pragma unroll
            for (int nt = 0; nt < 4; ++nt) {
                int n0 = wn * 32 + nt * 8 + gr;
                int p = s * 8 + tig;
                bhf[nt][0] = sm.t.bh[n0 * 20 + p];
                bhf[nt][1] = sm.t.bh[n0 * 20 + p + 4];
                blf[nt][0] = sm.t.bl[n0 * 20 + p];
                blf[nt][1] = sm.t.bl[n0 * 20 + p + 4];
            }
            #pragma unroll
            for (int mt = 0; mt < 4; ++mt)
                #pragma unroll
                for (int nt = 0; nt < 4; ++nt) {
                    mma_bf16(acc[mt][nt], ahf[mt], bhf[nt]);
                    mma_bf16(acc[mt][nt], ahf[mt], blf[nt]);
                    mma_bf16(acc[mt][nt], alf[mt], bhf[nt]);
                }
        }
        __syncthreads();
    }

    // epilogue: BN + LReLU, reduce max/sum over the block's 128 rows
    #pragma unroll
    for (int nt = 0; nt < 4; ++nt) {
        #pragma unroll
        for (int j = 0; j < 2; ++j) {
            int lcol = wn * 32 + nt * 8 + 2 * tig + j;
            int col = bx * 128 + lcol;
            float g  = bn[col];
            float be = bn[1024 + col];
            float mu = bn[2048 + col];
            float va = bn[3072 + col];
            float s = g * rsqrtf(va + EPSBN);
            float o = be - mu * s;
            float mx = -INFINITY, smv = 0.f;
            #pragma unroll
            for (int mt = 0; mt < 4; ++mt) {
                float v0 = s * acc[mt][nt][j] + o;
                v0 = v0 > 0.f ? v0 : SLOPE * v0;
                float v1 = s * acc[mt][nt][2 + j] + o;
                v1 = v1 > 0.f ? v1 : SLOPE * v1;
                mx = fmaxf(mx, fmaxf(v0, v1));
                smv += v0 + v1;
            }
            #pragma unroll
            for (int off = 4; off <= 16; off <<= 1) {
                mx = fmaxf(mx, __shfl_xor_sync(0xffffffffu, mx, off));
                smv += __shfl_xor_sync(0xffffffffu, smv, off);
            }
            if (gr == 0) {
                sm.r.rmax[wm][lcol] = mx;
                sm.r.rsum[wm][lcol] = smv;
            }
        }
    }
    __syncthreads();

    if (tid < 128) {
        int c = tid;
        float mx = fmaxf(sm.r.rmax[0][c], sm.r.rmax[1][c]);
        float s2 = sm.r.rsum[0][c] + sm.r.rsum[1][c];
        int b = by >> 3, chunk = by & 7;
        pmax[((long long)chunk * BATCH + b) * 1024 + bx * 128 + c] = mx;
        psum[((long long)chunk * BATCH + b) * 1024 + bx * 128 + c] = s2;
    }
}

// ---------------- final pool reduce over 8 chunks ----------------
__global__ void pool_reduce_kernel(const float* __restrict__ pmax,
                                   const float* __restrict__ psum,
                                   float* __restrict__ pool)
{
    int gi = blockIdx.x * blockDim.x + threadIdx.x;
    if (gi >= BATCH * 1024) return;
    int b = gi >> 10;
    int c = gi & 1023;
    float mx = -INFINITY, sm = 0.f;
    #pragma unroll
    for (int chunk = 0; chunk < 8; ++chunk) {
        mx = fmaxf(mx, pmax[((long long)chunk * BATCH + b) * 1024 + c]);
        sm += psum[((long long)chunk * BATCH + b) * 1024 + c];
    }
    pool[b * 2048 + c] = mx;
    pool[b * 2048 + 1024 + c] = sm * (1.f / (float)NPTS);
}

// ---------------- warp-per-row top-k (k=20), REDUX + sorted top-4 cache ---------
__global__ void __launch_bounds__(256) topk_warp_kernel(const float* __restrict__ pd,
                                                        int* __restrict__ out)
{
    int warp_in_blk = threadIdx.x >> 5;
    int lane = threadIdx.x & 31;
    int row = blockIdx.x * 8 + warp_in_blk;

    const float* __restrict__ p = pd + (long long)row * NPTS;

    unsigned k[32];
    #pragma unroll
    for (int j = 0; j < 32; ++j) {
        unsigned u = __float_as_uint(p[j * 32 + lane]);
        k[j] = (u & 0x80000000u) ? ~u : (u | 0x80000000u);
    }

    unsigned c0 = 0, c1 = 0, c2 = 0, c3 = 0;
    int i0 = 0, i1 = 0, i2 = 0, i3 = 0;
    #pragma unroll
    for (int j = 0; j < 32; ++j) {
        unsigned v = k[j];
        if (v > c3) {
            if (v > c2) {
                if (v > c1) {
                    if (v > c0) { c3=c2;i3=i2; c2=c1;i2=i1; c1=c0;i1=i0; c0=v;i0=j; }
                    else        { c3=c2;i3=i2; c2=c1;i2=i1; c1=v;i1=j; }
                } else          { c3=c2;i3=i2; c2=v;i2=j; }
            } else              { c3=v;i3=j; }
        }
    }

    int* __restrict__ o = out + (long long)row * KNN;

    #pragma unroll 1
    for (int it = 0; it < KNN; ++it) {
        unsigned m = __reduce_max_sync(0xffffffffu, c0);
        unsigned bal = __ballot_sync(0xffffffffu, c0 == m);
        int src = __ffs((int)bal) - 1;
        int gi = __shfl_sync(0xffffffffu, (i0 << 5) | lane, src);
        if (lane == 0) o[it] = gi;

        if (lane == src) {
            k[i0] = 0u;
            c0 = c1; i0 = i1;
            c1 = c2; i1 = i2;
            c2 = c3; i2 = i3;
            c3 = 0;  i3 = 0;
            if (c0 == 0u) {
                #pragma unroll
                for (int j = 0; j < 32; ++j) {
                    unsigned v = k[j];
                    if (v > c3) {
                        if (v > c2) {
                            if (v > c1) {
                                if (v > c0) { c3=c2;i3=i2; c2=c1;i2=i1; c1=c0;i1=i0; c0=v;i0=j; }
                                else        { c3=c2;i3=i2; c2=c1;i2=i1; c1=v;i1=j; }
                            } else          { c3=c2;i3=i2; c2=v;i2=j; }
                        } else              { c3=v;i3=j; }
                    }
                }
            }
        }
    }
}

// ---------------- prepare edge weights: [wa ; wb - wa], K-padded ----------------
__global__ void prep_w_kernel(const float* __restrict__ w, float* __restrict__ Wc,
                              int O, int C, int Cpad)
{
    int i = blockIdx.x * blockDim.x + threadIdx.x;
    int tot = 2 * O * Cpad;
    if (i >= tot) return;
    int half = i / (O * Cpad);
    int j = i % (O * Cpad);
    int o = j / Cpad, c = j % Cpad;
    float v = 0.f;
    if (c < C)
        v = half == 0 ? w[o * 2 * C + c]
                      : w[o * 2 * C + C + c] - w[o * 2 * C + c];
    Wc[half * O * Cpad + o * Cpad + c] = v;
}

// ---------------- gather + max_k + BN + LReLU, float4-vectorized ----------------
__global__ void gather_max_bn_kernel(const float* __restrict__ YZ,
                                     const int* __restrict__ idx,
                                     const float* __restrict__ bn,
                                     float* __restrict__ hcat,
                                     int O, int catoff)
{
    int b = blockIdx.y;
    int n0 = blockIdx.x * 8;
    int o4 = threadIdx.x;
    int py = threadIdx.y;
    int n = n0 + py;

    __shared__ int sidx[8][KNN];
    int bw = blockDim.x * 8;
    for (int t = threadIdx.y * blockDim.x + threadIdx.x; t < 8 * KNN; t += bw)
        sidx[t / KNN][t % KNN] = idx[((long long)b * NPTS + n0 + t / KNN) * KNN + t % KNN];
    __syncthreads();

    int ld = 2 * O;
    const float* base = YZ + (long long)b * NPTS * ld;

    float4 zc = *(const float4*)&base[(long long)n * ld + O + o4 * 4];
    float4 mx = make_float4(-INFINITY, -INFINITY, -INFINITY, -INFINITY);
    float4 mn = make_float4(INFINITY, INFINITY, INFINITY, INFINITY);
    #pragma unroll
    for (int kk = 0; kk < KNN; ++kk) {
        float4 y = *(const float4*)&base[(long long)sidx[py][kk] * ld + o4 * 4];
        mx.x = fmaxf(mx.x, y.x); mn.x = fminf(mn.x, y.x);
        mx.y = fmaxf(mx.y, y.y); mn.y = fminf(mn.y, y.y);
        mx.z = fmaxf(mx.z, y.z); mn.z = fminf(mn.z, y.z);
        mx.w = fmaxf(mx.w, y.w); mn.w = fminf(mn.w, y.w);
    }

    float4 g4  = *(const float4*)&bn[o4 * 4];
    float4 be4 = *(const float4*)&bn[O + o4 * 4];
    float4 mu4 = *(const float4*)&bn[2 * O + o4 * 4];
    float4 va4 = *(const float4*)&bn[3 * O + o4 * 4];

    float4 r;
    {
        float s = g4.x * rsqrtf(va4.x + EPSBN);
        float z = (s >= 0.f ? mx.x : mn.x) + zc.x;
        float v = s * z + (be4.x - mu4.x * s);
        r.x = v > 0.f ? v : SLOPE * v;
    }
    {
        float s = g4.y * rsqrtf(va4.y + EPSBN);
        float z = (s >= 0.f ? mx.y : mn.y) + zc.y;
        float v = s * z + (be4.y - mu4.y * s);
        r.y = v > 0.f ? v : SLOPE * v;
    }
    {
        float s = g4.z * rsqrtf(va4.z + EPSBN);
        float z = (s >= 0.f ? mx.z : mn.z) + zc.z;
        float v = s * z + (be4.z - mu4.z * s);
        r.z = v > 0.f ? v : SLOPE * v;
    }
    {
        float s = g4.w * rsqrtf(va4.w + EPSBN);
        float z = (s >= 0.f ? mx.w : mn.w) + zc.w;
        float v = s * z + (be4.w - mu4.w * s);
        r.w = v > 0.f ? v : SLOPE * v;
    }
    *(float4*)&hcat[((long long)b * NPTS + n) * 512 + catoff + o4 * 4] = r;
}

// ---------------- FC layer: warp per (b,o) ----------------
__global__ void fc_kernel(const float* __restrict__ in, const float* __restrict__ W,
                          const float* __restrict__ bn, const float* __restrict__ bias,
                          float* __restrict__ out, int O, int K, int Bn)
{
    int gw = (blockIdx.x * blockDim.x + threadIdx.x) >> 5;
    int lane = threadIdx.x & 31;
    if (gw >= Bn * O) return;
    int b = gw / O, o = gw % O;
    float acc = 0.f;
    const float* ip = in + (long long)b * K;
    const float* wp = W + (long long)o * K;
    for (int k = lane; k < K; k += 32) acc += ip[k] * wp[k];
    #pragma unroll
    for (int off = 16; off > 0; off >>= 1)
        acc += __shfl_down_sync(0xffffffffu, acc, off);
    if (lane == 0) {
        float v = acc;
        if (bn) {
            float g  = bn[o];
            float be = bn[O + o];
            float mu = bn[2 * O + o];
            float va = bn[3 * O + o];
            float s = g * rsqrtf(va + EPSBN);
            v = s * v + (be - mu * s);
            v = v > 0.f ? v : SLOPE * v;
        } else {
            v += bias[o];
        }
        out[(long long)b * O + o] = v;
    }
}

// ---------------- host orchestration ----------------
extern "C" void kernel_launch(void* const* d_in, const int* in_sizes, int n_in,
                              void* d_out, int out_size)
{
    (void)in_sizes; (void)n_in; (void)out_size;
    const float* x   = (const float*)d_in[0];
    const float* w1  = (const float*)d_in[1];
    const float* bn1 = (const float*)d_in[2];
    const float* w2  = (const float*)d_in[3];
    const float* bn2 = (const float*)d_in[4];
    const float* w3  = (const float*)d_in[5];
    const float* bn3 = (const float*)d_in[6];
    const float* w4  = (const float*)d_in[7];
    const float* bn4 = (const float*)d_in[8];
    const float* w5  = (const float*)d_in[9];
    const float* bn5 = (const float*)d_in[10];
    const float* wl1 = (const float*)d_in[11];
    const float* bn6 = (const float*)d_in[12];
    const float* wl2 = (const float*)d_in[13];
    const float* bn7 = (const float*)d_in[14];
    const float* wl3 = (const float*)d_in[15];
    const float* bl3 = (const float*)d_in[16];
    float* out = (float*)d_out;

    float *p_xT, *p_hcat, *p_pd, *p_YZ, *p_W, *p_sq, *p_pmax, *p_psum,
          *p_pool, *p_fc1, *p_fc2;
    int* p_idx;
    unsigned short *p_Ahi, *p_Alo, *p_Bhi, *p_Blo;
    cudaGetSymbolAddress((void**)&p_xT,   g_xT);
    cudaGetSymbolAddress((void**)&p_hcat, g_hcat);
    cudaGetSymbolAddress((void**)&p_pd,   g_pd);
    cudaGetSymbolAddress((void**)&p_idx,  g_idx);
    cudaGetSymbolAddress((void**)&p_YZ,   g_YZ);
    cudaGetSymbolAddress((void**)&p_W,    g_W);
    cudaGetSymbolAddress((void**)&p_sq,   g_sq);
    cudaGetSymbolAddress((void**)&p_pmax, g_pmax);
    cudaGetSymbolAddress((void**)&p_psum, g_psum);
    cudaGetSymbolAddress((void**)&p_pool, g_pool);
    cudaGetSymbolAddress((void**)&p_fc1,  g_fc1);
    cudaGetSymbolAddress((void**)&p_fc2,  g_fc2);
    cudaGetSymbolAddress((void**)&p_Ahi,  g_Ahi);
    cudaGetSymbolAddress((void**)&p_Alo,  g_Alo);
    cudaGetSymbolAddress((void**)&p_Bhi,  g_Bhi);
    cudaGetSymbolAddress((void**)&p_Blo,  g_Blo);

    static cudaStream_t s_side = nullptr;
    static cudaEvent_t evf[4], evj[4], evW0, evW;
    if (!s_side) {
        cudaStreamCreateWithFlags(&s_side, cudaStreamNonBlocking);
        for (int i = 0; i < 4; ++i) {
            cudaEventCreateWithFlags(&evf[i], cudaEventDisableTiming);
            cudaEventCreateWithFlags(&evj[i], cudaEventDisableTiming);
        }
        cudaEventCreateWithFlags(&evW0, cudaEventDisableTiming);
        cudaEventCreateWithFlags(&evW, cudaEventDisableTiming);
    }

    // fork side stream early: convert w5 to split bf16 there
    cudaEventRecord(evW0, 0);
    cudaStreamWaitEvent(s_side, evW0, 0);
    cvt_split4_kernel<<<(1024 * 512 / 4 + 255) / 256, 256, 0, s_side>>>(
        w5, p_Bhi, p_Blo, 1024 * 512 / 4);
    cudaEventRecord(evW, s_side);

    {
        int tot = BATCH * NPTS;
        transpose_x_kernel<<<(tot + 255) / 256, 256>>>(x, p_xT);
    }

    struct Blk { const float* h; int lda, C, Cpad, O; const float* w; const float* bn; int catoff; };
    Blk blks[4] = {
        { p_xT,         8,   3,   8,   64,  w1, bn1, 0   },
        { p_hcat + 0,   512, 64,  64,  64,  w2, bn2, 64  },
        { p_hcat + 64,  512, 64,  64,  128, w3, bn3, 128 },
        { p_hcat + 128, 512, 128, 128, 256, w4, bn4, 256 },
    };

    for (int i = 0; i < 4; ++i) {
        const Blk& B = blks[i];

        {
            int threads = BATCH * NPTS * 32;
            sqnorm_kernel<<<(threads + 255) / 256, 256>>>(B.h, B.lda, B.C, p_sq);
        }

        // fork: side stream does prep_w + YZ GEMM while main does pd + topk
        cudaEventRecord(evf[i], 0);
        cudaStreamWaitEvent(s_side, evf[i], 0);
        {
            int tot = 2 * B.O * B.Cpad;
            prep_w_kernel<<<(tot + 255) / 256, 256, 0, s_side>>>(B.w, p_W, B.O, B.C, B.Cpad);
            dim3 grid((2 * B.O) / 128, (BATCH * NPTS) / 128, 1);
            sgemm_nt_kernel<<<grid, 256, 0, s_side>>>(B.h, p_W, p_YZ,
                BATCH * NPTS, 2 * B.O, B.Cpad, B.lda, B.Cpad, 2 * B.O,
                0, 0, 0, 0, nullptr, 0);
            cudaEventRecord(evj[i], s_side);
        }

        // main: pd (symmetric) + topk
        {
            dim3 grid(36, 1, BATCH);
            sgemm_nt_kernel<<<grid, 256>>>(B.h, B.h, p_pd,
                NPTS, NPTS, B.Cpad, B.lda, B.lda, NPTS,
                (long long)NPTS * B.lda, (long long)NPTS * B.lda,
                (long long)NPTS * NPTS, 2, p_sq, 1);
        }
        topk_warp_kernel<<<(BATCH * NPTS) / 8, 256>>>(p_pd, p_idx);

        cudaStreamWaitEvent(0, evj[i], 0);
        {
            dim3 blk(B.O / 4, 8);
            gather_max_bn_kernel<<<dim3(NPTS / 8, BATCH), blk>>>(p_YZ, p_idx, B.bn,
                                                                 p_hcat, B.O, B.catoff);
        }
    }

    // split hcat to bf16 hi/lo, then conv5 tensor-core GEMM + fused pooling
    cvt_split4_kernel<<<(BATCH * NPTS * 512 / 4 + 255) / 256, 256>>>(
        p_hcat, p_Ahi, p_Alo, BATCH * NPTS * 512 / 4);
    cudaStreamWaitEvent(0, evW, 0);
    {
        dim3 grid(8, 128);
        conv5_mma_kernel<<<grid, 256>>>(p_Ahi, p_Alo, p_Bhi, p_Blo, bn5, p_pmax, p_psum);
    }
    {
        int tot = BATCH * 1024;
        pool_reduce_kernel<<<(tot + 255) / 256, 256>>>(p_pmax, p_psum, p_pool);
    }

    {
        int warps = BATCH * 512;
        fc_kernel<<<(warps * 32 + 255) / 256, 256>>>(p_pool, wl1, bn6, nullptr,
                                                     p_fc1, 512, 2048, BATCH);
    }
    {
        int warps = BATCH * 256;
        fc_kernel<<<(warps * 32 + 255) / 256, 256>>>(p_fc1, wl2, bn7, nullptr,
                                                     p_fc2, 256, 512, BATCH);
    }
    {
        int warps = BATCH * 40;
        fc_kernel<<<(warps * 32 + 255) / 256, 256>>>(p_fc2, wl3, nullptr, bl3,
                                                     out, 40, 256, BATCH);
    }
}

// round 10
// speedup vs baseline: 6.2231x; 1.0501x over previous
#include <cuda_runtime.h>
#include <cuda_bf16.h>
#include <cmath>

#define BATCH 16
#define NPTS  1024
#define KNN   20
#define EPSBN 1e-5f
#define SLOPE 0.2f

// ---------------- scratch (device globals; no allocations allowed) ----------------
__device__ float g_xT[BATCH * NPTS * 8];
__device__ float g_hcat[BATCH * NPTS * 512];
__device__ float g_pd[(long long)BATCH * NPTS * NPTS];
__device__ int   g_idx[BATCH * NPTS * KNN];
__device__ float g_YZ[BATCH * NPTS * 512];
__device__ float g_W[512 * 128];
__device__ float g_sq[BATCH * NPTS];
__device__ float g_pmax[8 * BATCH * 1024];
__device__ float g_psum[8 * BATCH * 1024];
__device__ float g_pool[BATCH * 2048];
__device__ float g_fc1[BATCH * 512];
__device__ float g_fc2[BATCH * 256];
// split-bf16 buffers
__device__ unsigned short g_Ahi[BATCH * NPTS * 512];   // hcat hi (conv5 A + pd operand)
__device__ unsigned short g_Alo[BATCH * NPTS * 512];   // hcat lo
__device__ unsigned short g_Bhi[1024 * 512];           // w5 hi
__device__ unsigned short g_Blo[1024 * 512];           // w5 lo
__device__ unsigned short g_Xhi[BATCH * NPTS * 32];    // x split, 32-padded
__device__ unsigned short g_Xlo[BATCH * NPTS * 32];

// ---------------- helpers ----------------
__device__ __forceinline__ unsigned long long pack2(float lo, float hi)
{
    unsigned long long r;
    asm("mov.b64 %0, {%1, %2};" : "=l"(r) : "f"(lo), "f"(hi));
    return r;
}
__device__ __forceinline__ void ffma2(unsigned long long& acc,
                                      unsigned long long a, unsigned long long b)
{
    asm("fma.rn.f32x2 %0, %1, %2, %0;" : "+l"(acc) : "l"(a), "l"(b));
}
__device__ __forceinline__ float2 unpack2(unsigned long long v)
{
    float lo, hi;
    asm("mov.b64 {%0, %1}, %2;" : "=f"(lo), "=f"(hi) : "l"(v));
    return make_float2(lo, hi);
}
__device__ __forceinline__ void mma_bf16(float* d, const unsigned* a, const unsigned* b)
{
    asm volatile(
        "mma.sync.aligned.m16n8k16.row.col.f32.bf16.bf16.f32 "
        "{%0,%1,%2,%3}, {%4,%5,%6,%7}, {%8,%9}, {%0,%1,%2,%3};"
        : "+f"(d[0]), "+f"(d[1]), "+f"(d[2]), "+f"(d[3])
        : "r"(a[0]), "r"(a[1]), "r"(a[2]), "r"(a[3]), "r"(b[0]), "r"(b[1]));
}
__device__ __forceinline__ unsigned short bf_bits(__nv_bfloat16 h)
{
    unsigned short s;
    memcpy(&s, &h, 2);
    return s;
}
__device__ __forceinline__ unsigned pk16(unsigned short a, unsigned short b)
{
    return (unsigned)a | ((unsigned)b << 16);
}

// ---------------- transpose x + split to bf16 (32-padded) ----------------
__global__ void transpose_x_split_kernel(const float* __restrict__ x,
                                         float* __restrict__ xT,
                                         unsigned short* __restrict__ Xhi,
                                         unsigned short* __restrict__ Xlo)
{
    int p = blockIdx.x * blockDim.x + threadIdx.x;
    if (p >= BATCH * NPTS) return;
    int b = p / NPTS;
    int n = p % NPTS;
    const float* xb = x + (long long)b * 3 * NPTS + n;
    float v0 = xb[0], v1 = xb[NPTS], v2 = xb[2 * NPTS];
    *(float4*)&xT[p * 8]     = make_float4(v0, v1, v2, 0.f);
    *(float4*)&xT[p * 8 + 4] = make_float4(0.f, 0.f, 0.f, 0.f);

    __nv_bfloat16 h0 = __float2bfloat16_rn(v0);
    __nv_bfloat16 h1 = __float2bfloat16_rn(v1);
    __nv_bfloat16 h2 = __float2bfloat16_rn(v2);
    __nv_bfloat16 l0 = __float2bfloat16_rn(v0 - __bfloat162float(h0));
    __nv_bfloat16 l1 = __float2bfloat16_rn(v1 - __bfloat162float(h1));
    __nv_bfloat16 l2 = __float2bfloat16_rn(v2 - __bfloat162float(h2));

    uint4 z = make_uint4(0, 0, 0, 0);
    uint4 vh = make_uint4(pk16(bf_bits(h0), bf_bits(h1)), pk16(bf_bits(h2), 0), 0, 0);
    uint4 vl = make_uint4(pk16(bf_bits(l0), bf_bits(l1)), pk16(bf_bits(l2), 0), 0, 0);
    uint4* ph = (uint4*)(Xhi + p * 32);
    uint4* pl = (uint4*)(Xlo + p * 32);
    ph[0] = vh; ph[1] = z; ph[2] = z; ph[3] = z;
    pl[0] = vl; pl[1] = z; pl[2] = z; pl[3] = z;
}

// ---------------- squared norms per point ----------------
__global__ void sqnorm_kernel(const float* __restrict__ h, int lda, int C,
                              float* __restrict__ sq)
{
    int p = (blockIdx.x * blockDim.x + threadIdx.x) >> 5;
    int lane = threadIdx.x & 31;
    if (p >= BATCH * NPTS) return;
    float acc = 0.f;
    for (int c = lane; c < C; c += 32) {
        float v = h[(long long)p * lda + c];
        acc += v * v;
    }
    #pragma unroll
    for (int off = 16; off > 0; off >>= 1)
        acc += __shfl_down_sync(0xffffffffu, acc, off);
    if (lane == 0) sq[p] = acc;
}

// ---------------- fp32 -> (hi, lo) bf16 split, flat float4 ----------------
__global__ void cvt_split4_kernel(const float* __restrict__ in,
                                  unsigned short* __restrict__ hi,
                                  unsigned short* __restrict__ lo, int n4)
{
    int i = blockIdx.x * blockDim.x + threadIdx.x;
    if (i >= n4) return;
    float4 v = ((const float4*)in)[i];
    __nv_bfloat16 h0 = __float2bfloat16_rn(v.x);
    __nv_bfloat16 h1 = __float2bfloat16_rn(v.y);
    __nv_bfloat16 h2 = __float2bfloat16_rn(v.z);
    __nv_bfloat16 h3 = __float2bfloat16_rn(v.w);
    __nv_bfloat16 l0 = __float2bfloat16_rn(v.x - __bfloat162float(h0));
    __nv_bfloat16 l1 = __float2bfloat16_rn(v.y - __bfloat162float(h1));
    __nv_bfloat16 l2 = __float2bfloat16_rn(v.z - __bfloat162float(h2));
    __nv_bfloat16 l3 = __float2bfloat16_rn(v.w - __bfloat162float(h3));
    uint2* hp = (uint2*)(hi + i * 4);
    uint2* lp = (uint2*)(lo + i * 4);
    *hp = make_uint2(pk16(bf_bits(h0), bf_bits(h1)), pk16(bf_bits(h2), bf_bits(h3)));
    *lp = make_uint2(pk16(bf_bits(l0), bf_bits(l1)), pk16(bf_bits(l2), bf_bits(l3)));
}

// ---------------- strided slice split: hcat cols [catoff, catoff+O) ------------
__global__ void cvt_slice_kernel(const float* __restrict__ hcat,
                                 unsigned short* __restrict__ Ahi,
                                 unsigned short* __restrict__ Alo,
                                 int catoff, int O)
{
    int per = O / 4;
    int i = blockIdx.x * blockDim.x + threadIdx.x;
    if (i >= BATCH * NPTS * per) return;
    int p = i / per;
    int j = (i % per) * 4;
    long long off = (long long)p * 512 + catoff + j;
    float4 v = *(const float4*)(hcat + off);
    __nv_bfloat16 h0 = __float2bfloat16_rn(v.x);
    __nv_bfloat16 h1 = __float2bfloat16_rn(v.y);
    __nv_bfloat16 h2 = __float2bfloat16_rn(v.z);
    __nv_bfloat16 h3 = __float2bfloat16_rn(v.w);
    __nv_bfloat16 l0 = __float2bfloat16_rn(v.x - __bfloat162float(h0));
    __nv_bfloat16 l1 = __float2bfloat16_rn(v.y - __bfloat162float(h1));
    __nv_bfloat16 l2 = __float2bfloat16_rn(v.z - __bfloat162float(h2));
    __nv_bfloat16 l3 = __float2bfloat16_rn(v.w - __bfloat162float(h3));
    *(uint2*)(Ahi + off) = make_uint2(pk16(bf_bits(h0), bf_bits(h1)),
                                      pk16(bf_bits(h2), bf_bits(h3)));
    *(uint2*)(Alo + off) = make_uint2(pk16(bf_bits(l0), bf_bits(l1)),
                                      pk16(bf_bits(l2), bf_bits(l3)));
}

// ---------------- split-bf16 MMA Gram: pd = 2*H@H^T - sq_m - sq_n --------------
// H hi/lo: row stride ld (shorts), K multiple of 32. Grid (8, 8, BATCH).
__global__ void __launch_bounds__(256)
gram_mma_kernel(const unsigned short* __restrict__ Hhi,
                const unsigned short* __restrict__ Hlo,
                int ld, int K,
                const float* __restrict__ sq, float* __restrict__ pd)
{
    __shared__ __align__(16) unsigned sah[128 * 20], sal[128 * 20],
                                      sbh[128 * 20], sbl[128 * 20];

    int b = blockIdx.z;
    long long hbase = (long long)b * NPTS * ld;
    const float* sqb = sq + b * NPTS;
    float* pdb = pd + (long long)b * NPTS * NPTS;

    int tid = threadIdx.x;
    int lane = tid & 31;
    int w = tid >> 5;
    int wm = w & 1, wn = w >> 1;
    int gr = lane >> 2, tig = lane & 3;
    int bx = blockIdx.x, by = blockIdx.y;

    int l_row = tid >> 1;
    int q0 = (tid & 1) * 2;
    long long a_base = hbase + (long long)(by * 128 + l_row) * ld;
    long long b_base = hbase + (long long)(bx * 128 + l_row) * ld;

    int nk = K >> 5;

    uint4 pa_h[2], pa_l[2], pb_h[2], pb_l[2];
    #pragma unroll
    for (int q = 0; q < 2; ++q) {
        pa_h[q] = *(const uint4*)(Hhi + a_base + (q0 + q) * 8);
        pa_l[q] = *(const uint4*)(Hlo + a_base + (q0 + q) * 8);
        pb_h[q] = *(const uint4*)(Hhi + b_base + (q0 + q) * 8);
        pb_l[q] = *(const uint4*)(Hlo + b_base + (q0 + q) * 8);
    }

    float acc[4][4][4];
    #pragma unroll
    for (int mt = 0; mt < 4; ++mt)
        #pragma unroll
        for (int nt = 0; nt < 4; ++nt)
            #pragma unroll
            for (int c = 0; c < 4; ++c)
                acc[mt][nt][c] = 0.f;

    for (int kt = 0; kt < nk; ++kt) {
        #pragma unroll
        for (int q = 0; q < 2; ++q) {
            *(uint4*)&sah[l_row * 20 + (q0 + q) * 4] = pa_h[q];
            *(uint4*)&sal[l_row * 20 + (q0 + q) * 4] = pa_l[q];
            *(uint4*)&sbh[l_row * 20 + (q0 + q) * 4] = pb_h[q];
            *(uint4*)&sbl[l_row * 20 + (q0 + q) * 4] = pb_l[q];
        }
        __syncthreads();

        if (kt + 1 < nk) {
            long long koff = (long long)(kt + 1) * 32;
            #pragma unroll
            for (int q = 0; q < 2; ++q) {
                pa_h[q] = *(const uint4*)(Hhi + a_base + koff + (q0 + q) * 8);
                pa_l[q] = *(const uint4*)(Hlo + a_base + koff + (q0 + q) * 8);
                pb_h[q] = *(const uint4*)(Hhi + b_base + koff + (q0 + q) * 8);
                pb_l[q] = *(const uint4*)(Hlo + b_base + koff + (q0 + q) * 8);
            }
        }

        #pragma unroll
        for (int s = 0; s < 2; ++s) {
            unsigned ahf[4][4], alf[4][4];
            #pragma unroll
            for (int mt = 0; mt < 4; ++mt) {
                int r0 = wm * 64 + mt * 16 + gr;
                int p = s * 8 + tig;
                ahf[mt][0] = sah[r0 * 20 + p];
                ahf[mt][1] = sah[(r0 + 8) * 20 + p];
                ahf[mt][2] = sah[r0 * 20 + p + 4];
                ahf[mt][3] = sah[(r0 + 8) * 20 + p + 4];
                alf[mt][0] = sal[r0 * 20 + p];
                alf[mt][1] = sal[(r0 + 8) * 20 + p];
                alf[mt][2] = sal[r0 * 20 + p + 4];
                alf[mt][3] = sal[(r0 + 8) * 20 + p + 4];
            }
            unsigned bhf[4][2], blf[4][2];
            #pragma unroll
            for (int nt = 0; nt < 4; ++nt) {
                int n0 = wn * 32 + nt * 8 + gr;
                int p = s * 8 + tig;
                bhf[nt][0] = sbh[n0 * 20 + p];
                bhf[nt][1] = sbh[n0 * 20 + p + 4];
                blf[nt][0] = sbl[n0 * 20 + p];
                blf[nt][1] = sbl[n0 * 20 + p + 4];
            }
            #pragma unroll
            for (int mt = 0; mt < 4; ++mt)
                #pragma unroll
                for (int nt = 0; nt < 4; ++nt) {
                    mma_bf16(acc[mt][nt], ahf[mt], bhf[nt]);
                    mma_bf16(acc[mt][nt], ahf[mt], blf[nt]);
                    mma_bf16(acc[mt][nt], alf[mt], bhf[nt]);
                }
        }
        __syncthreads();
    }

    // epilogue: pd = 2*acc - sq[r] - sq[c]
    #pragma unroll
    for (int mt = 0; mt < 4; ++mt) {
        int r0 = by * 128 + wm * 64 + mt * 16 + gr;
        float sq0 = sqb[r0];
        float sq1 = sqb[r0 + 8];
        #pragma unroll
        for (int nt = 0; nt < 4; ++nt) {
            int c = bx * 128 + wn * 32 + nt * 8 + 2 * tig;
            float sc0 = sqb[c], sc1 = sqb[c + 1];
            *(float2*)&pdb[(long long)r0 * NPTS + c] =
                make_float2(2.f * acc[mt][nt][0] - sq0 - sc0,
                            2.f * acc[mt][nt][1] - sq0 - sc1);
            *(float2*)&pdb[(long long)(r0 + 8) * NPTS + c] =
                make_float2(2.f * acc[mt][nt][2] - sq1 - sc0,
                            2.f * acc[mt][nt][3] - sq1 - sc1);
        }
    }
}

// ---------------- 128x128 tiled SGEMM, f32x2 core (YZ GEMM only now) -----------
__global__ void __launch_bounds__(256)
sgemm_nt_kernel(const float* __restrict__ A, const float* __restrict__ Bw,
                float* __restrict__ C,
                int M, int Nn, int K, int lda, int ldb, int ldc)
{
    __shared__ float As[8][128];
    __shared__ float Bs[8][128];

    int tid = threadIdx.x;
    int tx = tid & 15;
    int ty = tid >> 4;
    int bx = blockIdx.x, by = blockIdx.y;

    int l_row = tid >> 1;
    int l_k0  = (tid & 1) * 4;

    const float* aptr = A + (long long)(by * 128 + l_row) * lda + l_k0;
    const float* bptr = Bw + (long long)(bx * 128 + l_row) * ldb + l_k0;

    float4 ra = *(const float4*)aptr;
    float4 rb = *(const float4*)bptr;

    unsigned long long acc2[8][4];
    #pragma unroll
    for (int i = 0; i < 8; ++i)
        #pragma unroll
        for (int j = 0; j < 4; ++j)
            acc2[i][j] = 0ull;

    for (int kt = 0; kt < K; kt += 8) {
        As[l_k0 + 0][l_row] = ra.x;
        As[l_k0 + 1][l_row] = ra.y;
        As[l_k0 + 2][l_row] = ra.z;
        As[l_k0 + 3][l_row] = ra.w;
        Bs[l_k0 + 0][l_row] = rb.x;
        Bs[l_k0 + 1][l_row] = rb.y;
        Bs[l_k0 + 2][l_row] = rb.z;
        Bs[l_k0 + 3][l_row] = rb.w;
        __syncthreads();

        if (kt + 8 < K) {
            ra = *(const float4*)(aptr + kt + 8);
            rb = *(const float4*)(bptr + kt + 8);
        }

        #pragma unroll
        for (int kk = 0; kk < 8; ++kk) {
            float4 a0 = *(const float4*)&As[kk][ty * 8];
            float4 a1 = *(const float4*)&As[kk][ty * 8 + 4];
            float4 b0 = *(const float4*)&Bs[kk][tx * 8];
            float4 b1 = *(const float4*)&Bs[kk][tx * 8 + 4];

            unsigned long long bp[4];
            bp[0] = pack2(b0.x, b0.y);
            bp[1] = pack2(b0.z, b0.w);
            bp[2] = pack2(b1.x, b1.y);
            bp[3] = pack2(b1.z, b1.w);

            float a[8] = {a0.x, a0.y, a0.z, a0.w, a1.x, a1.y, a1.z, a1.w};
            #pragma unroll
            for (int i = 0; i < 8; ++i) {
                unsigned long long ap = pack2(a[i], a[i]);
                #pragma unroll
                for (int j = 0; j < 4; ++j)
                    ffma2(acc2[i][j], ap, bp[j]);
            }
        }
        __syncthreads();
    }

    #pragma unroll
    for (int i = 0; i < 8; ++i) {
        int gm = by * 128 + ty * 8 + i;
        #pragma unroll
        for (int jj = 0; jj < 2; ++jj) {
            float4 v4;
            float2 p0 = unpack2(acc2[i][jj * 2]);
            float2 p1 = unpack2(acc2[i][jj * 2 + 1]);
            v4.x = p0.x; v4.y = p0.y; v4.z = p1.x; v4.w = p1.y;
            *(float4*)&C[(long long)gm * ldc + bx * 128 + tx * 8 + jj * 4] = v4;
        }
    }
}

// ---------------- conv5 split-bf16 MMA + fused BN/LReLU + pooling ---------------
__global__ void __launch_bounds__(256)
conv5_mma_kernel(const unsigned short* __restrict__ Ahi, const unsigned short* __restrict__ Alo,
                 const unsigned short* __restrict__ Bhi, const unsigned short* __restrict__ Blo,
                 const float* __restrict__ bn,
                 float* __restrict__ pmax, float* __restrict__ psum)
{
    __shared__ __align__(16) union SM {
        struct { unsigned ah[128 * 20], al[128 * 20], bh[128 * 20], bl[128 * 20]; } t;
        struct { float rmax[2][128]; float rsum[2][128]; } r;
    } sm;

    int tid = threadIdx.x;
    int lane = tid & 31;
    int w = tid >> 5;
    int wm = w & 1, wn = w >> 1;
    int gr = lane >> 2, tig = lane & 3;
    int bx = blockIdx.x, by = blockIdx.y;

    int l_row = tid >> 1;
    int q0 = (tid & 1) * 2;
    long long a_base = (long long)(by * 128 + l_row) * 512;
    long long b_base = (long long)(bx * 128 + l_row) * 512;

    uint4 pa_h[2], pa_l[2], pb_h[2], pb_l[2];
    #pragma unroll
    for (int q = 0; q < 2; ++q) {
        pa_h[q] = *(const uint4*)(Ahi + a_base + (q0 + q) * 8);
        pa_l[q] = *(const uint4*)(Alo + a_base + (q0 + q) * 8);
        pb_h[q] = *(const uint4*)(Bhi + b_base + (q0 + q) * 8);
        pb_l[q] = *(const uint4*)(Blo + b_base + (q0 + q) * 8);
    }

    float acc[4][4][4];
    #pragma unroll
    for (int mt = 0; mt < 4; ++mt)
        #pragma unroll
        for (int nt = 0; nt < 4; ++nt)
            #pragma unroll
            for (int c = 0; c < 4; ++c)
                acc[mt][nt][c] = 0.f;

    for (int kt = 0; kt < 16; ++kt) {
        #pragma unroll
        for (int q = 0; q < 2; ++q) {
            *(uint4*)&sm.t.ah[l_row * 20 + (q0 + q) * 4] = pa_h[q];
            *(uint4*)&sm.t.al[l_row * 20 + (q0 + q) * 4] = pa_l[q];
            *(uint4*)&sm.t.bh[l_row * 20 + (q0 + q) * 4] = pb_h[q];
            *(uint4*)&sm.t.bl[l_row * 20 + (q0 + q) * 4] = pb_l[q];
        }
        __syncthreads();

        if (kt + 1 < 16) {
            long long koff = (long long)(kt + 1) * 32;
            #pragma unroll
            for (int q = 0; q < 2; ++q) {
                pa_h[q] = *(const uint4*)(Ahi + a_base + koff + (q0 + q) * 8);
                pa_l[q] = *(const uint4*)(Alo + a_base + koff + (q0 + q) * 8);
                pb_h[q] = *(const uint4*)(Bhi + b_base + koff + (q0 + q) * 8);
                pb_l[q] = *(const uint4*)(Blo + b_base + koff + (q0 + q) * 8);
            }
        }

        #pragma unroll
        for (int s = 0; s < 2; ++s) {
            unsigned ahf[4][4], alf[4][4];
            #pragma unroll
            for (int mt = 0; mt < 4; ++mt) {
                int r0 = wm * 64 + mt * 16 + gr;
                int p = s * 8 + tig;
                ahf[mt][0] = sm.t.ah[r0 * 20 + p];
                ahf[mt][1] = sm.t.ah[(r0 + 8) * 20 + p];
                ahf[mt][2] = sm.t.ah[r0 * 20 + p + 4];
                ahf[mt][3] = sm.t.ah[(r0 + 8) * 20 + p + 4];
                alf[mt][0] = sm.t.al[r0 * 20 + p];
                alf[mt][1] = sm.t.al[(r0 + 8) * 20 + p];
                alf[mt][2] = sm.t.al[r0 * 20 + p + 4];
                alf[mt][3] = sm.t.al[(r0 + 8) * 20 + p + 4];
            }
            unsigned bhf[4][2], blf[4][2];
            #pragma unroll
            for (int nt = 0; nt < 4; ++nt) {
                int n0 = wn * 32 + nt * 8 + gr;
                int p = s * 8 + tig;
                bhf[nt][0] = sm.t.bh[n0 * 20 + p];
                bhf[nt][1] = sm.t.bh[n0 * 20 + p + 4];
                blf[nt][0] = sm.t.bl[n0 * 20 + p];
                blf[nt][1] = sm.t.bl[n0 * 20 + p + 4];
            }
            #pragma unroll
            for (int mt = 0; mt < 4; ++mt)
                #pragma unroll
                for (int nt = 0; nt < 4; ++nt) {
                    mma_bf16(acc[mt][nt], ahf[mt], bhf[nt]);
                    mma_bf16(acc[mt][nt], ahf[mt], blf[nt]);
                    mma_bf16(acc[mt][nt], alf[mt], bhf[nt]);
                }
        }
        __syncthreads();
    }

    #pragma unroll
    for (int nt = 0; nt < 4; ++nt) {
        #pragma unroll
        for (int j = 0; j < 2; ++j) {
            int lcol = wn * 32 + nt * 8 + 2 * tig + j;
            int col = bx * 128 + lcol;
            float g  = bn[col];
            float be = bn[1024 + col];
            float mu = bn[2048 + col];
            float va = bn[3072 + col];
            float s = g * rsqrtf(va + EPSBN);
            float o = be - mu * s;
            float mx = -INFINITY, smv = 0.f;
            #pragma unroll
            for (int mt = 0; mt < 4; ++mt) {
                float v0 = s * acc[mt][nt][j] + o;
                v0 = v0 > 0.f ? v0 : SLOPE * v0;
                float v1 = s * acc[mt][nt][2 + j] + o;
                v1 = v1 > 0.f ? v1 : SLOPE * v1;
                mx = fmaxf(mx, fmaxf(v0, v1));
                smv += v0 + v1;
            }
            #pragma unroll
            for (int off = 4; off <= 16; off <<= 1) {
                mx = fmaxf(mx, __shfl_xor_sync(0xffffffffu, mx, off));
                smv += __shfl_xor_sync(0xffffffffu, smv, off);
            }
            if (gr == 0) {
                sm.r.rmax[wm][lcol] = mx;
                sm.r.rsum[wm][lcol] = smv;
            }
        }
    }
    __syncthreads();

    if (tid < 128) {
        int c = tid;
        float mx = fmaxf(sm.r.rmax[0][c], sm.r.rmax[1][c]);
        float s2 = sm.r.rsum[0][c] + sm.r.rsum[1][c];
        int b = by >> 3, chunk = by & 7;
        pmax[((long long)chunk * BATCH + b) * 1024 + bx * 128 + c] = mx;
        psum[((long long)chunk * BATCH + b) * 1024 + bx * 128 + c] = s2;
    }
}

// ---------------- final pool reduce over 8 chunks ----------------
__global__ void pool_reduce_kernel(const float* __restrict__ pmax,
                                   const float* __restrict__ psum,
                                   float* __restrict__ pool)
{
    int gi = blockIdx.x * blockDim.x + threadIdx.x;
    if (gi >= BATCH * 1024) return;
    int b = gi >> 10;
    int c = gi & 1023;
    float mx = -INFINITY, sm = 0.f;
    #pragma unroll
    for (int chunk = 0; chunk < 8; ++chunk) {
        mx = fmaxf(mx, pmax[((long long)chunk * BATCH + b) * 1024 + c]);
        sm += psum[((long long)chunk * BATCH + b) * 1024 + c];
    }
    pool[b * 2048 + c] = mx;
    pool[b * 2048 + 1024 + c] = sm * (1.f / (float)NPTS);
}

// ---------------- warp-per-row top-k (k=20), REDUX + sorted top-4 cache ---------
__global__ void __launch_bounds__(256) topk_warp_kernel(const float* __restrict__ pd,
                                                        int* __restrict__ out)
{
    int warp_in_blk = threadIdx.x >> 5;
    int lane = threadIdx.x & 31;
    int row = blockIdx.x * 8 + warp_in_blk;

    const float* __restrict__ p = pd + (long long)row * NPTS;

    unsigned k[32];
    #pragma unroll
    for (int j = 0; j < 32; ++j) {
        unsigned u = __float_as_uint(p[j * 32 + lane]);
        k[j] = (u & 0x80000000u) ? ~u : (u | 0x80000000u);
    }

    unsigned c0 = 0, c1 = 0, c2 = 0, c3 = 0;
    int i0 = 0, i1 = 0, i2 = 0, i3 = 0;
    #pragma unroll
    for (int j = 0; j < 32; ++j) {
        unsigned v = k[j];
        if (v > c3) {
            if (v > c2) {
                if (v > c1) {
                    if (v > c0) { c3=c2;i3=i2; c2=c1;i2=i1; c1=c0;i1=i0; c0=v;i0=j; }
                    else        { c3=c2;i3=i2; c2=c1;i2=i1; c1=v;i1=j; }
                } else          { c3=c2;i3=i2; c2=v;i2=j; }
            } else              { c3=v;i3=j; }
        }
    }

    int* __restrict__ o = out + (long long)row * KNN;

    #pragma unroll 1
    for (int it = 0; it < KNN; ++it) {
        unsigned m = __reduce_max_sync(0xffffffffu, c0);
        unsigned bal = __ballot_sync(0xffffffffu, c0 == m);
        int src = __ffs((int)bal) - 1;
        int gi = __shfl_sync(0xffffffffu, (i0 << 5) | lane, src);
        if (lane == 0) o[it] = gi;

        if (lane == src) {
            k[i0] = 0u;
            c0 = c1; i0 = i1;
            c1 = c2; i1 = i2;
            c2 = c3; i2 = i3;
            c3 = 0;  i3 = 0;
            if (c0 == 0u) {
                #pragma unroll
                for (int j = 0; j < 32; ++j) {
                    unsigned v = k[j];
                    if (v > c3) {
                        if (v > c2) {
                            if (v > c1) {
                                if (v > c0) { c3=c2;i3=i2; c2=c1;i2=i1; c1=c0;i1=i0; c0=v;i0=j; }
                                else        { c3=c2;i3=i2; c2=c1;i2=i1; c1=v;i1=j; }
                            } else          { c3=c2;i3=i2; c2=v;i2=j; }
                        } else              { c3=v;i3=j; }
                    }
                }
            }
        }
    }
}

// ---------------- prepare edge weights: [wa ; wb - wa], K-padded ----------------
__global__ void prep_w_kernel(const float* __restrict__ w, float* __restrict__ Wc,
                              int O, int C, int Cpad)
{
    int i = blockIdx.x * blockDim.x + threadIdx.x;
    int tot = 2 * O * Cpad;
    if (i >= tot) return;
    int half = i / (O * Cpad);
    int j = i % (O * Cpad);
    int o = j / Cpad, c = j % Cpad;
    float v = 0.f;
    if (c < C)
        v = half == 0 ? w[o * 2 * C + c]
                      : w[o * 2 * C + C + c] - w[o * 2 * C + c];
    Wc[half * O * Cpad + o * Cpad + c] = v;
}

// ---------------- gather + max_k + BN + LReLU, float4-vectorized ----------------
__global__ void gather_max_bn_kernel(const float* __restrict__ YZ,
                                     const int* __restrict__ idx,
                                     const float* __restrict__ bn,
                                     float* __restrict__ hcat,
                                     int O, int catoff)
{
    int b = blockIdx.y;
    int n0 = blockIdx.x * 8;
    int o4 = threadIdx.x;
    int py = threadIdx.y;
    int n = n0 + py;

    __shared__ int sidx[8][KNN];
    int bw = blockDim.x * 8;
    for (int t = threadIdx.y * blockDim.x + threadIdx.x; t < 8 * KNN; t += bw)
        sidx[t / KNN][t % KNN] = idx[((long long)b * NPTS + n0 + t / KNN) * KNN + t % KNN];
    __syncthreads();

    int ld = 2 * O;
    const float* base = YZ + (long long)b * NPTS * ld;

    float4 zc = *(const float4*)&base[(long long)n * ld + O + o4 * 4];
    float4 mx = make_float4(-INFINITY, -INFINITY, -INFINITY, -INFINITY);
    float4 mn = make_float4(INFINITY, INFINITY, INFINITY, INFINITY);
    #pragma unroll
    for (int kk = 0; kk < KNN; ++kk) {
        float4 y = *(const float4*)&base[(long long)sidx[py][kk] * ld + o4 * 4];
        mx.x = fmaxf(mx.x, y.x); mn.x = fminf(mn.x, y.x);
        mx.y = fmaxf(mx.y, y.y); mn.y = fminf(mn.y, y.y);
        mx.z = fmaxf(mx.z, y.z); mn.z = fminf(mn.z, y.z);
        mx.w = fmaxf(mx.w, y.w); mn.w = fminf(mn.w, y.w);
    }

    float4 g4  = *(const float4*)&bn[o4 * 4];
    float4 be4 = *(const float4*)&bn[O + o4 * 4];
    float4 mu4 = *(const float4*)&bn[2 * O + o4 * 4];
    float4 va4 = *(const float4*)&bn[3 * O + o4 * 4];

    float4 r;
    {
        float s = g4.x * rsqrtf(va4.x + EPSBN);
        float z = (s >= 0.f ? mx.x : mn.x) + zc.x;
        float v = s * z + (be4.x - mu4.x * s);
        r.x = v > 0.f ? v : SLOPE * v;
    }
    {
        float s = g4.y * rsqrtf(va4.y + EPSBN);
        float z = (s >= 0.f ? mx.y : mn.y) + zc.y;
        float v = s * z + (be4.y - mu4.y * s);
        r.y = v > 0.f ? v : SLOPE * v;
    }
    {
        float s = g4.z * rsqrtf(va4.z + EPSBN);
        float z = (s >= 0.f ? mx.z : mn.z) + zc.z;
        float v = s * z + (be4.z - mu4.z * s);
        r.z = v > 0.f ? v : SLOPE * v;
    }
    {
        float s = g4.w * rsqrtf(va4.w + EPSBN);
        float z = (s >= 0.f ? mx.w : mn.w) + zc.w;
        float v = s * z + (be4.w - mu4.w * s);
        r.w = v > 0.f ? v : SLOPE * v;
    }
    *(float4*)&hcat[((long long)b * NPTS + n) * 512 + catoff + o4 * 4] = r;
}

// ---------------- FC layer: warp per (b,o) ----------------
__global__ void fc_kernel(const float* __restrict__ in, const float* __restrict__ W,
                          const float* __restrict__ bn, const float* __restrict__ bias,
                          float* __restrict__ out, int O, int K, int Bn)
{
    int gw = (blockIdx.x * blockDim.x + threadIdx.x) >> 5;
    int lane = threadIdx.x & 31;
    if (gw >= Bn * O) return;
    int b = gw / O, o = gw % O;
    float acc = 0.f;
    const float* ip = in + (long long)b * K;
    const float* wp = W + (long long)o * K;
    for (int k = lane; k < K; k += 32) acc += ip[k] * wp[k];
    #pragma unroll
    for (int off = 16; off > 0; off >>= 1)
        acc += __shfl_down_sync(0xffffffffu, acc, off);
    if (lane == 0) {
        float v = acc;
        if (bn) {
            float g  = bn[o];
            float be = bn[O + o];
            float mu = bn[2 * O + o];
            float va = bn[3 * O + o];
            float s = g * rsqrtf(va + EPSBN);
            v = s * v + (be - mu * s);
            v = v > 0.f ? v : SLOPE * v;
        } else {
            v += bias[o];
        }
        out[(long long)b * O + o] = v;
    }
}

// ---------------- host orchestration ----------------
extern "C" void kernel_launch(void* const* d_in, const int* in_sizes, int n_in,
                              void* d_out, int out_size)
{
    (void)in_sizes; (void)n_in; (void)out_size;
    const float* x   = (const float*)d_in[0];
    const float* w1  = (const float*)d_in[1];
    const float* bn1 = (const float*)d_in[2];
    const float* w2  = (const float*)d_in[3];
    const float* bn2 = (const float*)d_in[4];
    const float* w3  = (const float*)d_in[5];
    const float* bn3 = (const float*)d_in[6];
    const float* w4  = (const float*)d_in[7];
    const float* bn4 = (const float*)d_in[8];
    const float* w5  = (const float*)d_in[9];
    const float* bn5 = (const float*)d_in[10];
    const float* wl1 = (const float*)d_in[11];
    const float* bn6 = (const float*)d_in[12];
    const float* wl2 = (const float*)d_in[13];
    const float* bn7 = (const float*)d_in[14];
    const float* wl3 = (const float*)d_in[15];
    const float* bl3 = (const float*)d_in[16];
    float* out = (float*)d_out;

    float *p_xT, *p_hcat, *p_pd, *p_YZ, *p_W, *p_sq, *p_pmax, *p_psum,
          *p_pool, *p_fc1, *p_fc2;
    int* p_idx;
    unsigned short *p_Ahi, *p_Alo, *p_Bhi, *p_Blo, *p_Xhi, *p_Xlo;
    cudaGetSymbolAddress((void**)&p_xT,   g_xT);
    cudaGetSymbolAddress((void**)&p_hcat, g_hcat);
    cudaGetSymbolAddress((void**)&p_pd,   g_pd);
    cudaGetSymbolAddress((void**)&p_idx,  g_idx);
    cudaGetSymbolAddress((void**)&p_YZ,   g_YZ);
    cudaGetSymbolAddress((void**)&p_W,    g_W);
    cudaGetSymbolAddress((void**)&p_sq,   g_sq);
    cudaGetSymbolAddress((void**)&p_pmax, g_pmax);
    cudaGetSymbolAddress((void**)&p_psum, g_psum);
    cudaGetSymbolAddress((void**)&p_pool, g_pool);
    cudaGetSymbolAddress((void**)&p_fc1,  g_fc1);
    cudaGetSymbolAddress((void**)&p_fc2,  g_fc2);
    cudaGetSymbolAddress((void**)&p_Ahi,  g_Ahi);
    cudaGetSymbolAddress((void**)&p_Alo,  g_Alo);
    cudaGetSymbolAddress((void**)&p_Bhi,  g_Bhi);
    cudaGetSymbolAddress((void**)&p_Blo,  g_Blo);
    cudaGetSymbolAddress((void**)&p_Xhi,  g_Xhi);
    cudaGetSymbolAddress((void**)&p_Xlo,  g_Xlo);

    static cudaStream_t s_side = nullptr;
    static cudaEvent_t evf[4], evj[4], evW0, evW;
    if (!s_side) {
        cudaStreamCreateWithFlags(&s_side, cudaStreamNonBlocking);
        for (int i = 0; i < 4; ++i) {
            cudaEventCreateWithFlags(&evf[i], cudaEventDisableTiming);
            cudaEventCreateWithFlags(&evj[i], cudaEventDisableTiming);
        }
        cudaEventCreateWithFlags(&evW0, cudaEventDisableTiming);
        cudaEventCreateWithFlags(&evW, cudaEventDisableTiming);
    }

    // side stream: convert w5 to split bf16
    cudaEventRecord(evW0, 0);
    cudaStreamWaitEvent(s_side, evW0, 0);
    cvt_split4_kernel<<<(1024 * 512 / 4 + 255) / 256, 256, 0, s_side>>>(
        w5, p_Bhi, p_Blo, 1024 * 512 / 4);
    cudaEventRecord(evW, s_side);

    // x -> xT (fp32, for sqnorm/YZ) + Xhi/Xlo (bf16 split, for pd Gram)
    {
        int tot = BATCH * NPTS;
        transpose_x_split_kernel<<<(tot + 255) / 256, 256>>>(x, p_xT, p_Xhi, p_Xlo);
    }

    struct Blk {
        const float* h; int lda, C, Cpad, O;
        const unsigned short *hhi, *hlo; int hld, Kmma;
        const float* w; const float* bn; int catoff;
    };
    Blk blks[4] = {
        { p_xT,         8,   3,   8,   64,  p_Xhi,       p_Xlo,       32,  32,  w1, bn1, 0   },
        { p_hcat + 0,   512, 64,  64,  64,  p_Ahi,       p_Alo,       512, 64,  w2, bn2, 64  },
        { p_hcat + 64,  512, 64,  64,  128, p_Ahi + 64,  p_Alo + 64,  512, 64,  w3, bn3, 128 },
        { p_hcat + 128, 512, 128, 128, 256, p_Ahi + 128, p_Alo + 128, 512, 128, w4, bn4, 256 },
    };

    for (int i = 0; i < 4; ++i) {
        const Blk& B = blks[i];

        {
            int threads = BATCH * NPTS * 32;
            sqnorm_kernel<<<(threads + 255) / 256, 256>>>(B.h, B.lda, B.C, p_sq);
        }

        // fork: side stream does prep_w + YZ GEMM
        cudaEventRecord(evf[i], 0);
        cudaStreamWaitEvent(s_side, evf[i], 0);
        {
            int tot = 2 * B.O * B.Cpad;
            prep_w_kernel<<<(tot + 255) / 256, 256, 0, s_side>>>(B.w, p_W, B.O, B.C, B.Cpad);
            dim3 grid((2 * B.O) / 128, (BATCH * NPTS) / 128, 1);
            sgemm_nt_kernel<<<grid, 256, 0, s_side>>>(B.h, p_W, p_YZ,
                BATCH * NPTS, 2 * B.O, B.Cpad, B.lda, B.Cpad, 2 * B.O);
            cudaEventRecord(evj[i], s_side);
        }

        // main: pd via split-bf16 MMA Gram, then topk
        {
            dim3 grid(8, 8, BATCH);
            gram_mma_kernel<<<grid, 256>>>(B.hhi, B.hlo, B.hld, B.Kmma, p_sq, p_pd);
        }
        topk_warp_kernel<<<(BATCH * NPTS) / 8, 256>>>(p_pd, p_idx);

        cudaStreamWaitEvent(0, evj[i], 0);
        {
            dim3 blk(B.O / 4, 8);
            gather_max_bn_kernel<<<dim3(NPTS / 8, BATCH), blk>>>(p_YZ, p_idx, B.bn,
                                                                 p_hcat, B.O, B.catoff);
        }
        // convert the freshly written hcat slice to bf16 split (feeds next pd + conv5)
        {
            int tot = BATCH * NPTS * (B.O / 4);
            cvt_slice_kernel<<<(tot + 255) / 256, 256>>>(p_hcat, p_Ahi, p_Alo,
                                                         B.catoff, B.O);
        }
    }

    // conv5 tensor-core GEMM + fused pooling (A operand already converted)
    cudaStreamWaitEvent(0, evW, 0);
    {
        dim3 grid(8, 128);
        conv5_mma_kernel<<<grid, 256>>>(p_Ahi, p_Alo, p_Bhi, p_Blo, bn5, p_pmax, p_psum);
    }
    {
        int tot = BATCH * 1024;
        pool_reduce_kernel<<<(tot + 255) / 256, 256>>>(p_pmax, p_psum, p_pool);
    }

    {
        int warps = BATCH * 512;
        fc_kernel<<<(warps * 32 + 255) / 256, 256>>>(p_pool, wl1, bn6, nullptr,
                                                     p_fc1, 512, 2048, BATCH);
    }
    {
        int warps = BATCH * 256;
        fc_kernel<<<(warps * 32 + 255) / 256, 256>>>(p_fc1, wl2, bn7, nullptr,
                                                     p_fc2, 256, 512, BATCH);
    }
    {
        int warps = BATCH * 40;
        fc_kernel<<<(warps * 32 + 255) / 256, 256>>>(p_fc2, wl3, nullptr, bl3,
                                                     out, 40, 256, BATCH);
    }
}

// round 11
// speedup vs baseline: 6.4020x; 1.0287x over previous
#include <cuda_runtime.h>
#include <cuda_bf16.h>
#include <cmath>

#define BATCH 16
#define NPTS  1024
#define KNN   20
#define EPSBN 1e-5f
#define SLOPE 0.2f

// ---------------- scratch (device globals; no allocations allowed) ----------------
__device__ float g_xT[BATCH * NPTS * 8];
__device__ float g_hcat[BATCH * NPTS * 512];
__device__ float g_pd[(long long)BATCH * NPTS * NPTS];
__device__ int   g_idx[BATCH * NPTS * KNN];
__device__ float g_YZ[BATCH * NPTS * 512];
__device__ float g_W[512 * 128];
__device__ float g_sq[BATCH * NPTS];
__device__ float g_pmax[8 * BATCH * 1024];
__device__ float g_psum[8 * BATCH * 1024];
__device__ float g_pool[BATCH * 2048];
__device__ float g_fc1[BATCH * 512];
__device__ float g_fc2[BATCH * 256];
// split-bf16 buffers
__device__ unsigned short g_Ahi[BATCH * NPTS * 512];
__device__ unsigned short g_Alo[BATCH * NPTS * 512];
__device__ unsigned short g_Bhi[1024 * 512];
__device__ unsigned short g_Blo[1024 * 512];
__device__ unsigned short g_Xhi[BATCH * NPTS * 32];
__device__ unsigned short g_Xlo[BATCH * NPTS * 32];

// ---------------- helpers ----------------
__device__ __forceinline__ unsigned long long pack2(float lo, float hi)
{
    unsigned long long r;
    asm("mov.b64 %0, {%1, %2};" : "=l"(r) : "f"(lo), "f"(hi));
    return r;
}
__device__ __forceinline__ void ffma2(unsigned long long& acc,
                                      unsigned long long a, unsigned long long b)
{
    asm("fma.rn.f32x2 %0, %1, %2, %0;" : "+l"(acc) : "l"(a), "l"(b));
}
__device__ __forceinline__ float2 unpack2(unsigned long long v)
{
    float lo, hi;
    asm("mov.b64 {%0, %1}, %2;" : "=f"(lo), "=f"(hi) : "l"(v));
    return make_float2(lo, hi);
}
__device__ __forceinline__ void mma_bf16(float* d, const unsigned* a, const unsigned* b)
{
    asm volatile(
        "mma.sync.aligned.m16n8k16.row.col.f32.bf16.bf16.f32 "
        "{%0,%1,%2,%3}, {%4,%5,%6,%7}, {%8,%9}, {%0,%1,%2,%3};"
        : "+f"(d[0]), "+f"(d[1]), "+f"(d[2]), "+f"(d[3])
        : "r"(a[0]), "r"(a[1]), "r"(a[2]), "r"(a[3]), "r"(b[0]), "r"(b[1]));
}
__device__ __forceinline__ unsigned short bf_bits(__nv_bfloat16 h)
{
    unsigned short s;
    memcpy(&s, &h, 2);
    return s;
}
__device__ __forceinline__ unsigned pk16(unsigned short a, unsigned short b)
{
    return (unsigned)a | ((unsigned)b << 16);
}

// ---------------- transpose x + split bf16 + sq, all fused ----------------
__global__ void transpose_x_split_kernel(const float* __restrict__ x,
                                         float* __restrict__ xT,
                                         unsigned short* __restrict__ Xhi,
                                         unsigned short* __restrict__ Xlo,
                                         float* __restrict__ sq)
{
    int p = blockIdx.x * blockDim.x + threadIdx.x;
    if (p >= BATCH * NPTS) return;
    int b = p / NPTS;
    int n = p % NPTS;
    const float* xb = x + (long long)b * 3 * NPTS + n;
    float v0 = xb[0], v1 = xb[NPTS], v2 = xb[2 * NPTS];
    *(float4*)&xT[p * 8]     = make_float4(v0, v1, v2, 0.f);
    *(float4*)&xT[p * 8 + 4] = make_float4(0.f, 0.f, 0.f, 0.f);
    sq[p] = v0 * v0 + v1 * v1 + v2 * v2;

    __nv_bfloat16 h0 = __float2bfloat16_rn(v0);
    __nv_bfloat16 h1 = __float2bfloat16_rn(v1);
    __nv_bfloat16 h2 = __float2bfloat16_rn(v2);
    __nv_bfloat16 l0 = __float2bfloat16_rn(v0 - __bfloat162float(h0));
    __nv_bfloat16 l1 = __float2bfloat16_rn(v1 - __bfloat162float(h1));
    __nv_bfloat16 l2 = __float2bfloat16_rn(v2 - __bfloat162float(h2));

    uint4 z = make_uint4(0, 0, 0, 0);
    uint4 vh = make_uint4(pk16(bf_bits(h0), bf_bits(h1)), pk16(bf_bits(h2), 0), 0, 0);
    uint4 vl = make_uint4(pk16(bf_bits(l0), bf_bits(l1)), pk16(bf_bits(l2), 0), 0, 0);
    uint4* ph = (uint4*)(Xhi + p * 32);
    uint4* pl = (uint4*)(Xlo + p * 32);
    ph[0] = vh; ph[1] = z; ph[2] = z; ph[3] = z;
    pl[0] = vl; pl[1] = z; pl[2] = z; pl[3] = z;
}

// ---------------- fp32 -> (hi, lo) bf16 split, flat float4 (w5 only) ------------
__global__ void cvt_split4_kernel(const float* __restrict__ in,
                                  unsigned short* __restrict__ hi,
                                  unsigned short* __restrict__ lo, int n4)
{
    int i = blockIdx.x * blockDim.x + threadIdx.x;
    if (i >= n4) return;
    float4 v = ((const float4*)in)[i];
    __nv_bfloat16 h0 = __float2bfloat16_rn(v.x);
    __nv_bfloat16 h1 = __float2bfloat16_rn(v.y);
    __nv_bfloat16 h2 = __float2bfloat16_rn(v.z);
    __nv_bfloat16 h3 = __float2bfloat16_rn(v.w);
    __nv_bfloat16 l0 = __float2bfloat16_rn(v.x - __bfloat162float(h0));
    __nv_bfloat16 l1 = __float2bfloat16_rn(v.y - __bfloat162float(h1));
    __nv_bfloat16 l2 = __float2bfloat16_rn(v.z - __bfloat162float(h2));
    __nv_bfloat16 l3 = __float2bfloat16_rn(v.w - __bfloat162float(h3));
    uint2* hp = (uint2*)(hi + i * 4);
    uint2* lp = (uint2*)(lo + i * 4);
    *hp = make_uint2(pk16(bf_bits(h0), bf_bits(h1)), pk16(bf_bits(h2), bf_bits(h3)));
    *lp = make_uint2(pk16(bf_bits(l0), bf_bits(l1)), pk16(bf_bits(l2), bf_bits(l3)));
}

// ---------------- split-bf16 MMA Gram: pd = 2*H@H^T - sq_m - sq_n --------------
__global__ void __launch_bounds__(256)
gram_mma_kernel(const unsigned short* __restrict__ Hhi,
                const unsigned short* __restrict__ Hlo,
                int ld, int K,
                const float* __restrict__ sq, float* __restrict__ pd)
{
    __shared__ __align__(16) unsigned sah[128 * 20], sal[128 * 20],
                                      sbh[128 * 20], sbl[128 * 20];

    int b = blockIdx.z;
    long long hbase = (long long)b * NPTS * ld;
    const float* sqb = sq + b * NPTS;
    float* pdb = pd + (long long)b * NPTS * NPTS;

    int tid = threadIdx.x;
    int lane = tid & 31;
    int w = tid >> 5;
    int wm = w & 1, wn = w >> 1;
    int gr = lane >> 2, tig = lane & 3;
    int bx = blockIdx.x, by = blockIdx.y;

    int l_row = tid >> 1;
    int q0 = (tid & 1) * 2;
    long long a_base = hbase + (long long)(by * 128 + l_row) * ld;
    long long b_base = hbase + (long long)(bx * 128 + l_row) * ld;

    int nk = K >> 5;

    uint4 pa_h[2], pa_l[2], pb_h[2], pb_l[2];
    #pragma unroll
    for (int q = 0; q < 2; ++q) {
        pa_h[q] = *(const uint4*)(Hhi + a_base + (q0 + q) * 8);
        pa_l[q] = *(const uint4*)(Hlo + a_base + (q0 + q) * 8);
        pb_h[q] = *(const uint4*)(Hhi + b_base + (q0 + q) * 8);
        pb_l[q] = *(const uint4*)(Hlo + b_base + (q0 + q) * 8);
    }

    float acc[4][4][4];
    #pragma unroll
    for (int mt = 0; mt < 4; ++mt)
        #pragma unroll
        for (int nt = 0; nt < 4; ++nt)
            #pragma unroll
            for (int c = 0; c < 4; ++c)
                acc[mt][nt][c] = 0.f;

    for (int kt = 0; kt < nk; ++kt) {
        #pragma unroll
        for (int q = 0; q < 2; ++q) {
            *(uint4*)&sah[l_row * 20 + (q0 + q) * 4] = pa_h[q];
            *(uint4*)&sal[l_row * 20 + (q0 + q) * 4] = pa_l[q];
            *(uint4*)&sbh[l_row * 20 + (q0 + q) * 4] = pb_h[q];
            *(uint4*)&sbl[l_row * 20 + (q0 + q) * 4] = pb_l[q];
        }
        __syncthreads();

        if (kt + 1 < nk) {
            long long koff = (long long)(kt + 1) * 32;
            #pragma unroll
            for (int q = 0; q < 2; ++q) {
                pa_h[q] = *(const uint4*)(Hhi + a_base + koff + (q0 + q) * 8);
                pa_l[q] = *(const uint4*)(Hlo + a_base + koff + (q0 + q) * 8);
                pb_h[q] = *(const uint4*)(Hhi + b_base + koff + (q0 + q) * 8);
                pb_l[q] = *(const uint4*)(Hlo + b_base + koff + (q0 + q) * 8);
            }
        }

        #pragma unroll
        for (int s = 0; s < 2; ++s) {
            unsigned ahf[4][4], alf[4][4];
            #pragma unroll
            for (int mt = 0; mt < 4; ++mt) {
                int r0 = wm * 64 + mt * 16 + gr;
                int p = s * 8 + tig;
                ahf[mt][0] = sah[r0 * 20 + p];
                ahf[mt][1] = sah[(r0 + 8) * 20 + p];
                ahf[mt][2] = sah[r0 * 20 + p + 4];
                ahf[mt][3] = sah[(r0 + 8) * 20 + p + 4];
                alf[mt][0] = sal[r0 * 20 + p];
                alf[mt][1] = sal[(r0 + 8) * 20 + p];
                alf[mt][2] = sal[r0 * 20 + p + 4];
                alf[mt][3] = sal[(r0 + 8) * 20 + p + 4];
            }
            unsigned bhf[4][2], blf[4][2];
            #pragma unroll
            for (int nt = 0; nt < 4; ++nt) {
                int n0 = wn * 32 + nt * 8 + gr;
                int p = s * 8 + tig;
                bhf[nt][0] = sbh[n0 * 20 + p];
                bhf[nt][1] = sbh[n0 * 20 + p + 4];
                blf[nt][0] = sbl[n0 * 20 + p];
                blf[nt][1] = sbl[n0 * 20 + p + 4];
            }
            #pragma unroll
            for (int mt = 0; mt < 4; ++mt)
                #pragma unroll
                for (int nt = 0; nt < 4; ++nt) {
                    mma_bf16(acc[mt][nt], ahf[mt], bhf[nt]);
                    mma_bf16(acc[mt][nt], ahf[mt], blf[nt]);
                    mma_bf16(acc[mt][nt], alf[mt], bhf[nt]);
                }
        }
        __syncthreads();
    }

    #pragma unroll
    for (int mt = 0; mt < 4; ++mt) {
        int r0 = by * 128 + wm * 64 + mt * 16 + gr;
        float sq0 = sqb[r0];
        float sq1 = sqb[r0 + 8];
        #pragma unroll
        for (int nt = 0; nt < 4; ++nt) {
            int c = bx * 128 + wn * 32 + nt * 8 + 2 * tig;
            float sc0 = sqb[c], sc1 = sqb[c + 1];
            *(float2*)&pdb[(long long)r0 * NPTS + c] =
                make_float2(2.f * acc[mt][nt][0] - sq0 - sc0,
                            2.f * acc[mt][nt][1] - sq0 - sc1);
            *(float2*)&pdb[(long long)(r0 + 8) * NPTS + c] =
                make_float2(2.f * acc[mt][nt][2] - sq1 - sc0,
                            2.f * acc[mt][nt][3] - sq1 - sc1);
        }
    }
}

// ---------------- 128x128 tiled SGEMM, f32x2 core (YZ GEMM) ----------------
__global__ void __launch_bounds__(256)
sgemm_nt_kernel(const float* __restrict__ A, const float* __restrict__ Bw,
                float* __restrict__ C,
                int M, int Nn, int K, int lda, int ldb, int ldc)
{
    __shared__ float As[8][128];
    __shared__ float Bs[8][128];

    int tid = threadIdx.x;
    int tx = tid & 15;
    int ty = tid >> 4;
    int bx = blockIdx.x, by = blockIdx.y;

    int l_row = tid >> 1;
    int l_k0  = (tid & 1) * 4;

    const float* aptr = A + (long long)(by * 128 + l_row) * lda + l_k0;
    const float* bptr = Bw + (long long)(bx * 128 + l_row) * ldb + l_k0;

    float4 ra = *(const float4*)aptr;
    float4 rb = *(const float4*)bptr;

    unsigned long long acc2[8][4];
    #pragma unroll
    for (int i = 0; i < 8; ++i)
        #pragma unroll
        for (int j = 0; j < 4; ++j)
            acc2[i][j] = 0ull;

    for (int kt = 0; kt < K; kt += 8) {
        As[l_k0 + 0][l_row] = ra.x;
        As[l_k0 + 1][l_row] = ra.y;
        As[l_k0 + 2][l_row] = ra.z;
        As[l_k0 + 3][l_row] = ra.w;
        Bs[l_k0 + 0][l_row] = rb.x;
        Bs[l_k0 + 1][l_row] = rb.y;
        Bs[l_k0 + 2][l_row] = rb.z;
        Bs[l_k0 + 3][l_row] = rb.w;
        __syncthreads();

        if (kt + 8 < K) {
            ra = *(const float4*)(aptr + kt + 8);
            rb = *(const float4*)(bptr + kt + 8);
        }

        #pragma unroll
        for (int kk = 0; kk < 8; ++kk) {
            float4 a0 = *(const float4*)&As[kk][ty * 8];
            float4 a1 = *(const float4*)&As[kk][ty * 8 + 4];
            float4 b0 = *(const float4*)&Bs[kk][tx * 8];
            float4 b1 = *(const float4*)&Bs[kk][tx * 8 + 4];

            unsigned long long bp[4];
            bp[0] = pack2(b0.x, b0.y);
            bp[1] = pack2(b0.z, b0.w);
            bp[2] = pack2(b1.x, b1.y);
            bp[3] = pack2(b1.z, b1.w);

            float a[8] = {a0.x, a0.y, a0.z, a0.w, a1.x, a1.y, a1.z, a1.w};
            #pragma unroll
            for (int i = 0; i < 8; ++i) {
                unsigned long long ap = pack2(a[i], a[i]);
                #pragma unroll
                for (int j = 0; j < 4; ++j)
                    ffma2(acc2[i][j], ap, bp[j]);
            }
        }
        __syncthreads();
    }

    #pragma unroll
    for (int i = 0; i < 8; ++i) {
        int gm = by * 128 + ty * 8 + i;
        #pragma unroll
        for (int jj = 0; jj < 2; ++jj) {
            float4 v4;
            float2 p0 = unpack2(acc2[i][jj * 2]);
            float2 p1 = unpack2(acc2[i][jj * 2 + 1]);
            v4.x = p0.x; v4.y = p0.y; v4.z = p1.x; v4.w = p1.y;
            *(float4*)&C[(long long)gm * ldc + bx * 128 + tx * 8 + jj * 4] = v4;
        }
    }
}

// ---------------- conv5 split-bf16 MMA + fused BN/LReLU + pooling ---------------
__global__ void __launch_bounds__(256)
conv5_mma_kernel(const unsigned short* __restrict__ Ahi, const unsigned short* __restrict__ Alo,
                 const unsigned short* __restrict__ Bhi, const unsigned short* __restrict__ Blo,
                 const float* __restrict__ bn,
                 float* __restrict__ pmax, float* __restrict__ psum)
{
    __shared__ __align__(16) union SM {
        struct { unsigned ah[128 * 20], al[128 * 20], bh[128 * 20], bl[128 * 20]; } t;
        struct { float rmax[2][128]; float rsum[2][128]; } r;
    } sm;

    int tid = threadIdx.x;
    int lane = tid & 31;
    int w = tid >> 5;
    int wm = w & 1, wn = w >> 1;
    int gr = lane >> 2, tig = lane & 3;
    int bx = blockIdx.x, by = blockIdx.y;

    int l_row = tid >> 1;
    int q0 = (tid & 1) * 2;
    long long a_base = (long long)(by * 128 + l_row) * 512;
    long long b_base = (long long)(bx * 128 + l_row) * 512;

    uint4 pa_h[2], pa_l[2], pb_h[2], pb_l[2];
    #pragma unroll
    for (int q = 0; q < 2; ++q) {
        pa_h[q] = *(const uint4*)(Ahi + a_base + (q0 + q) * 8);
        pa_l[q] = *(const uint4*)(Alo + a_base + (q0 + q) * 8);
        pb_h[q] = *(const uint4*)(Bhi + b_base + (q0 + q) * 8);
        pb_l[q] = *(const uint4*)(Blo + b_base + (q0 + q) * 8);
    }

    float acc[4][4][4];
    #pragma unroll
    for (int mt = 0; mt < 4; ++mt)
        #pragma unroll
        for (int nt = 0; nt < 4; ++nt)
            #pragma unroll
            for (int c = 0; c < 4; ++c)
                acc[mt][nt][c] = 0.f;

    for (int kt = 0; kt < 16; ++kt) {
        #pragma unroll
        for (int q = 0; q < 2; ++q) {
            *(uint4*)&sm.t.ah[l_row * 20 + (q0 + q) * 4] = pa_h[q];
            *(uint4*)&sm.t.al[l_row * 20 + (q0 + q) * 4] = pa_l[q];
            *(uint4*)&sm.t.bh[l_row * 20 + (q0 + q) * 4] = pb_h[q];
            *(uint4*)&sm.t.bl[l_row * 20 + (q0 + q) * 4] = pb_l[q];
        }
        __syncthreads();

        if (kt + 1 < 16) {
            long long koff = (long long)(kt + 1) * 32;
            #pragma unroll
            for (int q = 0; q < 2; ++q) {
                pa_h[q] = *(const uint4*)(Ahi + a_base + koff + (q0 + q) * 8);
                pa_l[q] = *(const uint4*)(Alo + a_base + koff + (q0 + q) * 8);
                pb_h[q] = *(const uint4*)(Bhi + b_base + koff + (q0 + q) * 8);
                pb_l[q] = *(const uint4*)(Blo + b_base + koff + (q0 + q) * 8);
            }
        }

        #pragma unroll
        for (int s = 0; s < 2; ++s) {
            unsigned ahf[4][4], alf[4][4];
            #pragma unroll
            for (int mt = 0; mt < 4; ++mt) {
                int r0 = wm * 64 + mt * 16 + gr;
                int p = s * 8 + tig;
                ahf[mt][0] = sm.t.ah[r0 * 20 + p];
                ahf[mt][1] = sm.t.ah[(r0 + 8) * 20 + p];
                ahf[mt][2] = sm.t.ah[r0 * 20 + p + 4];
                ahf[mt][3] = sm.t.ah[(r0 + 8) * 20 + p + 4];
                alf[mt][0] = sm.t.al[r0 * 20 + p];
                alf[mt][1] = sm.t.al[(r0 + 8) * 20 + p];
                alf[mt][2] = sm.t.al[r0 * 20 + p + 4];
                alf[mt][3] = sm.t.al[(r0 + 8) * 20 + p + 4];
            }
            unsigned bhf[4][2], blf[4][2];
            #pragma unroll
            for (int nt = 0; nt < 4; ++nt) {
                int n0 = wn * 32 + nt * 8 + gr;
                int p = s * 8 + tig;
                bhf[nt][0] = sm.t.bh[n0 * 20 + p];
                bhf[nt][1] = sm.t.bh[n0 * 20 + p + 4];
                blf[nt][0] = sm.t.bl[n0 * 20 + p];
                blf[nt][1] = sm.t.bl[n0 * 20 + p + 4];
            }
            #pragma unroll
            for (int mt = 0; mt < 4; ++mt)
                #pragma unroll
                for (int nt = 0; nt < 4; ++nt) {
                    mma_bf16(acc[mt][nt], ahf[mt], bhf[nt]);
                    mma_bf16(acc[mt][nt], ahf[mt], blf[nt]);
                    mma_bf16(acc[mt][nt], alf[mt], bhf[nt]);
                }
        }
        __syncthreads();
    }

    #pragma unroll
    for (int nt = 0; nt < 4; ++nt) {
        #pragma unroll
        for (int j = 0; j < 2; ++j) {
            int lcol = wn * 32 + nt * 8 + 2 * tig + j;
            int col = bx * 128 + lcol;
            float g  = bn[col];
            float be = bn[1024 + col];
            float mu = bn[2048 + col];
            float va = bn[3072 + col];
            float s = g * rsqrtf(va + EPSBN);
            float o = be - mu * s;
            float mx = -INFINITY, smv = 0.f;
            #pragma unroll
            for (int mt = 0; mt < 4; ++mt) {
                float v0 = s * acc[mt][nt][j] + o;
                v0 = v0 > 0.f ? v0 : SLOPE * v0;
                float v1 = s * acc[mt][nt][2 + j] + o;
                v1 = v1 > 0.f ? v1 : SLOPE * v1;
                mx = fmaxf(mx, fmaxf(v0, v1));
                smv += v0 + v1;
            }
            #pragma unroll
            for (int off = 4; off <= 16; off <<= 1) {
                mx = fmaxf(mx, __shfl_xor_sync(0xffffffffu, mx, off));
                smv += __shfl_xor_sync(0xffffffffu, smv, off);
            }
            if (gr == 0) {
                sm.r.rmax[wm][lcol] = mx;
                sm.r.rsum[wm][lcol] = smv;
            }
        }
    }
    __syncthreads();

    if (tid < 128) {
        int c = tid;
        float mx = fmaxf(sm.r.rmax[0][c], sm.r.rmax[1][c]);
        float s2 = sm.r.rsum[0][c] + sm.r.rsum[1][c];
        int b = by >> 3, chunk = by & 7;
        pmax[((long long)chunk * BATCH + b) * 1024 + bx * 128 + c] = mx;
        psum[((long long)chunk * BATCH + b) * 1024 + bx * 128 + c] = s2;
    }
}

// ---------------- final pool reduce over 8 chunks ----------------
__global__ void pool_reduce_kernel(const float* __restrict__ pmax,
                                   const float* __restrict__ psum,
                                   float* __restrict__ pool)
{
    int gi = blockIdx.x * blockDim.x + threadIdx.x;
    if (gi >= BATCH * 1024) return;
    int b = gi >> 10;
    int c = gi & 1023;
    float mx = -INFINITY, sm = 0.f;
    #pragma unroll
    for (int chunk = 0; chunk < 8; ++chunk) {
        mx = fmaxf(mx, pmax[((long long)chunk * BATCH + b) * 1024 + c]);
        sm += psum[((long long)chunk * BATCH + b) * 1024 + c];
    }
    pool[b * 2048 + c] = mx;
    pool[b * 2048 + 1024 + c] = sm * (1.f / (float)NPTS);
}

// ---------------- warp-per-row top-k (k=20), REDUX + sorted top-4 cache ---------
__global__ void __launch_bounds__(256) topk_warp_kernel(const float* __restrict__ pd,
                                                        int* __restrict__ out)
{
    int warp_in_blk = threadIdx.x >> 5;
    int lane = threadIdx.x & 31;
    int row = blockIdx.x * 8 + warp_in_blk;

    const float* __restrict__ p = pd + (long long)row * NPTS;

    unsigned k[32];
    #pragma unroll
    for (int j = 0; j < 32; ++j) {
        unsigned u = __float_as_uint(p[j * 32 + lane]);
        k[j] = (u & 0x80000000u) ? ~u : (u | 0x80000000u);
    }

    unsigned c0 = 0, c1 = 0, c2 = 0, c3 = 0;
    int i0 = 0, i1 = 0, i2 = 0, i3 = 0;
    #pragma unroll
    for (int j = 0; j < 32; ++j) {
        unsigned v = k[j];
        if (v > c3) {
            if (v > c2) {
                if (v > c1) {
                    if (v > c0) { c3=c2;i3=i2; c2=c1;i2=i1; c1=c0;i1=i0; c0=v;i0=j; }
                    else        { c3=c2;i3=i2; c2=c1;i2=i1; c1=v;i1=j; }
                } else          { c3=c2;i3=i2; c2=v;i2=j; }
            } else              { c3=v;i3=j; }
        }
    }

    int* __restrict__ o = out + (long long)row * KNN;

    #pragma unroll 1
    for (int it = 0; it < KNN; ++it) {
        unsigned m = __reduce_max_sync(0xffffffffu, c0);
        unsigned bal = __ballot_sync(0xffffffffu, c0 == m);
        int src = __ffs((int)bal) - 1;
        int gi = __shfl_sync(0xffffffffu, (i0 << 5) | lane, src);
        if (lane == 0) o[it] = gi;

        if (lane == src) {
            k[i0] = 0u;
            c0 = c1; i0 = i1;
            c1 = c2; i1 = i2;
            c2 = c3; i2 = i3;
            c3 = 0;  i3 = 0;
            if (c0 == 0u) {
                #pragma unroll
                for (int j = 0; j < 32; ++j) {
                    unsigned v = k[j];
                    if (v > c3) {
                        if (v > c2) {
                            if (v > c1) {
                                if (v > c0) { c3=c2;i3=i2; c2=c1;i2=i1; c1=c0;i1=i0; c0=v;i0=j; }
                                else        { c3=c2;i3=i2; c2=c1;i2=i1; c1=v;i1=j; }
                            } else          { c3=c2;i3=i2; c2=v;i2=j; }
                        } else              { c3=v;i3=j; }
                    }
                }
            }
        }
    }
}

// ---------------- prepare edge weights: [wa ; wb - wa], K-padded ----------------
__global__ void prep_w_kernel(const float* __restrict__ w, float* __restrict__ Wc,
                              int O, int C, int Cpad)
{
    int i = blockIdx.x * blockDim.x + threadIdx.x;
    int tot = 2 * O * Cpad;
    if (i >= tot) return;
    int half = i / (O * Cpad);
    int j = i % (O * Cpad);
    int o = j / Cpad, c = j % Cpad;
    float v = 0.f;
    if (c < C)
        v = half == 0 ? w[o * 2 * C + c]
                      : w[o * 2 * C + C + c] - w[o * 2 * C + c];
    Wc[half * O * Cpad + o * Cpad + c] = v;
}

// ---------------- FUSED gather + max_k + BN + LReLU + bf16 split + sq -----------
// blockDim (O/4, 8). Writes hcat fp32, Ahi/Alo bf16, and per-point sqnorm.
__global__ void gather_fused_kernel(const float* __restrict__ YZ,
                                    const int* __restrict__ idx,
                                    const float* __restrict__ bn,
                                    float* __restrict__ hcat,
                                    unsigned short* __restrict__ Ahi,
                                    unsigned short* __restrict__ Alo,
                                    float* __restrict__ sq,
                                    int O, int catoff, int writeSq)
{
    int b = blockIdx.y;
    int n0 = blockIdx.x * 8;
    int o4 = threadIdx.x;
    int py = threadIdx.y;
    int n = n0 + py;

    __shared__ int sidx[8][KNN];
    __shared__ float ssq[8][64];
    int bw = blockDim.x * 8;
    for (int t = threadIdx.y * blockDim.x + threadIdx.x; t < 8 * KNN; t += bw)
        sidx[t / KNN][t % KNN] = idx[((long long)b * NPTS + n0 + t / KNN) * KNN + t % KNN];
    __syncthreads();

    int ld = 2 * O;
    const float* base = YZ + (long long)b * NPTS * ld;

    float4 zc = *(const float4*)&base[(long long)n * ld + O + o4 * 4];
    float4 mx = make_float4(-INFINITY, -INFINITY, -INFINITY, -INFINITY);
    float4 mn = make_float4(INFINITY, INFINITY, INFINITY, INFINITY);
    #pragma unroll
    for (int kk = 0; kk < KNN; ++kk) {
        float4 y = *(const float4*)&base[(long long)sidx[py][kk] * ld + o4 * 4];
        mx.x = fmaxf(mx.x, y.x); mn.x = fminf(mn.x, y.x);
        mx.y = fmaxf(mx.y, y.y); mn.y = fminf(mn.y, y.y);
        mx.z = fmaxf(mx.z, y.z); mn.z = fminf(mn.z, y.z);
        mx.w = fmaxf(mx.w, y.w); mn.w = fminf(mn.w, y.w);
    }

    float4 g4  = *(const float4*)&bn[o4 * 4];
    float4 be4 = *(const float4*)&bn[O + o4 * 4];
    float4 mu4 = *(const float4*)&bn[2 * O + o4 * 4];
    float4 va4 = *(const float4*)&bn[3 * O + o4 * 4];

    float4 r;
    {
        float s = g4.x * rsqrtf(va4.x + EPSBN);
        float z = (s >= 0.f ? mx.x : mn.x) + zc.x;
        float v = s * z + (be4.x - mu4.x * s);
        r.x = v > 0.f ? v : SLOPE * v;
    }
    {
        float s = g4.y * rsqrtf(va4.y + EPSBN);
        float z = (s >= 0.f ? mx.y : mn.y) + zc.y;
        float v = s * z + (be4.y - mu4.y * s);
        r.y = v > 0.f ? v : SLOPE * v;
    }
    {
        float s = g4.z * rsqrtf(va4.z + EPSBN);
        float z = (s >= 0.f ? mx.z : mn.z) + zc.z;
        float v = s * z + (be4.z - mu4.z * s);
        r.z = v > 0.f ? v : SLOPE * v;
    }
    {
        float s = g4.w * rsqrtf(va4.w + EPSBN);
        float z = (s >= 0.f ? mx.w : mn.w) + zc.w;
        float v = s * z + (be4.w - mu4.w * s);
        r.w = v > 0.f ? v : SLOPE * v;
    }

    long long off = ((long long)b * NPTS + n) * 512 + catoff + o4 * 4;
    *(float4*)&hcat[off] = r;

    // bf16 hi/lo split (same values, feeds next gram + conv5)
    __nv_bfloat16 h0 = __float2bfloat16_rn(r.x);
    __nv_bfloat16 h1 = __float2bfloat16_rn(r.y);
    __nv_bfloat16 h2 = __float2bfloat16_rn(r.z);
    __nv_bfloat16 h3 = __float2bfloat16_rn(r.w);
    __nv_bfloat16 l0 = __float2bfloat16_rn(r.x - __bfloat162float(h0));
    __nv_bfloat16 l1 = __float2bfloat16_rn(r.y - __bfloat162float(h1));
    __nv_bfloat16 l2 = __float2bfloat16_rn(r.z - __bfloat162float(h2));
    __nv_bfloat16 l3 = __float2bfloat16_rn(r.w - __bfloat162float(h3));
    *(uint2*)(Ahi + off) = make_uint2(pk16(bf_bits(h0), bf_bits(h1)),
                                      pk16(bf_bits(h2), bf_bits(h3)));
    *(uint2*)(Alo + off) = make_uint2(pk16(bf_bits(l0), bf_bits(l1)),
                                      pk16(bf_bits(l2), bf_bits(l3)));

    // per-point squared norm (consumed by the next block's gram)
    if (writeSq) {
        ssq[py][o4] = r.x * r.x + r.y * r.y + r.z * r.z + r.w * r.w;
        __syncthreads();
        if (o4 == 0) {
            float s = 0.f;
            for (int j = 0; j < blockDim.x; ++j) s += ssq[py][j];
            sq[(long long)b * NPTS + n] = s;
        }
    }
}

// ---------------- FC layer: warp per (b,o) ----------------
__global__ void fc_kernel(const float* __restrict__ in, const float* __restrict__ W,
                          const float* __restrict__ bn, const float* __restrict__ bias,
                          float* __restrict__ out, int O, int K, int Bn)
{
    int gw = (blockIdx.x * blockDim.x + threadIdx.x) >> 5;
    int lane = threadIdx.x & 31;
    if (gw >= Bn * O) return;
    int b = gw / O, o = gw % O;
    float acc = 0.f;
    const float* ip = in + (long long)b * K;
    const float* wp = W + (long long)o * K;
    for (int k = lane; k < K; k += 32) acc += ip[k] * wp[k];
    #pragma unroll
    for (int off = 16; off > 0; off >>= 1)
        acc += __shfl_down_sync(0xffffffffu, acc, off);
    if (lane == 0) {
        float v = acc;
        if (bn) {
            float g  = bn[o];
            float be = bn[O + o];
            float mu = bn[2 * O + o];
            float va = bn[3 * O + o];
            float s = g * rsqrtf(va + EPSBN);
            v = s * v + (be - mu * s);
            v = v > 0.f ? v : SLOPE * v;
        } else {
            v += bias[o];
        }
        out[(long long)b * O + o] = v;
    }
}

// ---------------- host orchestration ----------------
extern "C" void kernel_launch(void* const* d_in, const int* in_sizes, int n_in,
                              void* d_out, int out_size)
{
    (void)in_sizes; (void)n_in; (void)out_size;
    const float* x   = (const float*)d_in[0];
    const float* w1  = (const float*)d_in[1];
    const float* bn1 = (const float*)d_in[2];
    const float* w2  = (const float*)d_in[3];
    const float* bn2 = (const float*)d_in[4];
    const float* w3  = (const float*)d_in[5];
    const float* bn3 = (const float*)d_in[6];
    const float* w4  = (const float*)d_in[7];
    const float* bn4 = (const float*)d_in[8];
    const float* w5  = (const float*)d_in[9];
    const float* bn5 = (const float*)d_in[10];
    const float* wl1 = (const float*)d_in[11];
    const float* bn6 = (const float*)d_in[12];
    const float* wl2 = (const float*)d_in[13];
    const float* bn7 = (const float*)d_in[14];
    const float* wl3 = (const float*)d_in[15];
    const float* bl3 = (const float*)d_in[16];
    float* out = (float*)d_out;

    float *p_xT, *p_hcat, *p_pd, *p_YZ, *p_W, *p_sq, *p_pmax, *p_psum,
          *p_pool, *p_fc1, *p_fc2;
    int* p_idx;
    unsigned short *p_Ahi, *p_Alo, *p_Bhi, *p_Blo, *p_Xhi, *p_Xlo;
    cudaGetSymbolAddress((void**)&p_xT,   g_xT);
    cudaGetSymbolAddress((void**)&p_hcat, g_hcat);
    cudaGetSymbolAddress((void**)&p_pd,   g_pd);
    cudaGetSymbolAddress((void**)&p_idx,  g_idx);
    cudaGetSymbolAddress((void**)&p_YZ,   g_YZ);
    cudaGetSymbolAddress((void**)&p_W,    g_W);
    cudaGetSymbolAddress((void**)&p_sq,   g_sq);
    cudaGetSymbolAddress((void**)&p_pmax, g_pmax);
    cudaGetSymbolAddress((void**)&p_psum, g_psum);
    cudaGetSymbolAddress((void**)&p_pool, g_pool);
    cudaGetSymbolAddress((void**)&p_fc1,  g_fc1);
    cudaGetSymbolAddress((void**)&p_fc2,  g_fc2);
    cudaGetSymbolAddress((void**)&p_Ahi,  g_Ahi);
    cudaGetSymbolAddress((void**)&p_Alo,  g_Alo);
    cudaGetSymbolAddress((void**)&p_Bhi,  g_Bhi);
    cudaGetSymbolAddress((void**)&p_Blo,  g_Blo);
    cudaGetSymbolAddress((void**)&p_Xhi,  g_Xhi);
    cudaGetSymbolAddress((void**)&p_Xlo,  g_Xlo);

    static cudaStream_t s_side = nullptr;
    static cudaEvent_t evf[4], evj[4], evW0, evW;
    if (!s_side) {
        cudaStreamCreateWithFlags(&s_side, cudaStreamNonBlocking);
        for (int i = 0; i < 4; ++i) {
            cudaEventCreateWithFlags(&evf[i], cudaEventDisableTiming);
            cudaEventCreateWithFlags(&evj[i], cudaEventDisableTiming);
        }
        cudaEventCreateWithFlags(&evW0, cudaEventDisableTiming);
        cudaEventCreateWithFlags(&evW, cudaEventDisableTiming);
    }

    // side stream: convert w5 to split bf16
    cudaEventRecord(evW0, 0);
    cudaStreamWaitEvent(s_side, evW0, 0);
    cvt_split4_kernel<<<(1024 * 512 / 4 + 255) / 256, 256, 0, s_side>>>(
        w5, p_Bhi, p_Blo, 1024 * 512 / 4);
    cudaEventRecord(evW, s_side);

    // x -> xT fp32 + Xhi/Xlo bf16 + sq, all fused
    {
        int tot = BATCH * NPTS;
        transpose_x_split_kernel<<<(tot + 255) / 256, 256>>>(x, p_xT, p_Xhi, p_Xlo, p_sq);
    }

    struct Blk {
        const float* h; int lda, C, Cpad, O;
        const unsigned short *hhi, *hlo; int hld, Kmma;
        const float* w; const float* bn; int catoff;
    };
    Blk blks[4] = {
        { p_xT,         8,   3,   8,   64,  p_Xhi,       p_Xlo,       32,  32,  w1, bn1, 0   },
        { p_hcat + 0,   512, 64,  64,  64,  p_Ahi,       p_Alo,       512, 64,  w2, bn2, 64  },
        { p_hcat + 64,  512, 64,  64,  128, p_Ahi + 64,  p_Alo + 64,  512, 64,  w3, bn3, 128 },
        { p_hcat + 128, 512, 128, 128, 256, p_Ahi + 128, p_Alo + 128, 512, 128, w4, bn4, 256 },
    };

    for (int i = 0; i < 4; ++i) {
        const Blk& B = blks[i];

        // fork: side stream does prep_w + YZ GEMM
        cudaEventRecord(evf[i], 0);
        cudaStreamWaitEvent(s_side, evf[i], 0);
        {
            int tot = 2 * B.O * B.Cpad;
            prep_w_kernel<<<(tot + 255) / 256, 256, 0, s_side>>>(B.w, p_W, B.O, B.C, B.Cpad);
            dim3 grid((2 * B.O) / 128, (BATCH * NPTS) / 128, 1);
            sgemm_nt_kernel<<<grid, 256, 0, s_side>>>(B.h, p_W, p_YZ,
                BATCH * NPTS, 2 * B.O, B.Cpad, B.lda, B.Cpad, 2 * B.O);
            cudaEventRecord(evj[i], s_side);
        }

        // main: pd via split-bf16 MMA Gram (sq already present), then topk
        {
            dim3 grid(8, 8, BATCH);
            gram_mma_kernel<<<grid, 256>>>(B.hhi, B.hlo, B.hld, B.Kmma, p_sq, p_pd);
        }
        topk_warp_kernel<<<(BATCH * NPTS) / 8, 256>>>(p_pd, p_idx);

        // join, then fused gather (writes hcat, bf16 split, and sq for next block)
        cudaStreamWaitEvent(0, evj[i], 0);
        {
            dim3 blk(B.O / 4, 8);
            gather_fused_kernel<<<dim3(NPTS / 8, BATCH), blk>>>(
                p_YZ, p_idx, B.bn, p_hcat, p_Ahi, p_Alo, p_sq,
                B.O, B.catoff, i < 3 ? 1 : 0);
        }
    }

    // conv5 tensor-core GEMM + fused pooling
    cudaStreamWaitEvent(0, evW, 0);
    {
        dim3 grid(8, 128);
        conv5_mma_kernel<<<grid, 256>>>(p_Ahi, p_Alo, p_Bhi, p_Blo, bn5, p_pmax, p_psum);
    }
    {
        int tot = BATCH * 1024;
        pool_reduce_kernel<<<(tot + 255) / 256, 256>>>(p_pmax, p_psum, p_pool);
    }

    {
        int warps = BATCH * 512;
        fc_kernel<<<(warps * 32 + 255) / 256, 256>>>(p_pool, wl1, bn6, nullptr,
                                                     p_fc1, 512, 2048, BATCH);
    }
    {
        int warps = BATCH * 256;
        fc_kernel<<<(warps * 32 + 255) / 256, 256>>>(p_fc1, wl2, bn7, nullptr,
                                                     p_fc2, 256, 512, BATCH);
    }
    {
        int warps = BATCH * 40;
        fc_kernel<<<(warps * 32 + 255) / 256, 256>>>(p_fc2, wl3, nullptr, bl3,
                                                     out, 40, 256, BATCH);
    }
}